// round 1
// baseline (speedup 1.0000x reference)
#include <cuda_runtime.h>
#include <math.h>

#define SEQ     2048
#define BATCH   2
#define HID     2048
#define NHEADS  16
#define HDIM    128
#define TOK     (SEQ*BATCH)     // 4096
#define QKV_N   (3*HID)         // 6144

// ---------------- scratch (device globals; no allocs allowed) ----------------
__device__ float g_q[BATCH*NHEADS*SEQ*HDIM];
__device__ float g_k[BATCH*NHEADS*SEQ*HDIM];
__device__ float g_v[BATCH*NHEADS*SEQ*HDIM];
__device__ float g_ctx[TOK*HID];
__device__ float g_cos[SEQ*64];
__device__ float g_sin[SEQ*64];

// ---------------- tiled fp32 GEMM: C[M,N] = A[M,K] * B[N,K]^T (+bias) -------
// 128x128 tile, BK=8, 256 threads, 8x8 per thread.
// MODE 1: QKV — add bias, scatter into g_q/g_k/g_v [b,h,s,d]
// MODE 2: dense — A taken from g_ctx, plain write to C
template<int MODE>
__global__ __launch_bounds__(256, 2)
void gemm_nt(const float* __restrict__ A, const float* __restrict__ Bw,
             const float* __restrict__ bias, float* __restrict__ C,
             int M, int N, int K)
{
    __shared__ float As[8][132];
    __shared__ float Bs[8][132];

    const float* Ap = (MODE == 2) ? (const float*)g_ctx : A;

    int tid = threadIdx.x;
    int tx = tid & 15;           // 0..15
    int ty = tid >> 4;           // 0..15
    int m0 = blockIdx.y * 128;
    int n0 = blockIdx.x * 128;

    int lrow = tid >> 1;         // 0..127
    int lk4  = (tid & 1) * 4;    // 0 or 4
    const float* Aptr = Ap + (size_t)(m0 + lrow) * K + lk4;
    const float* Bptr = Bw + (size_t)(n0 + lrow) * K + lk4;

    float acc[8][8];
#pragma unroll
    for (int i = 0; i < 8; i++)
#pragma unroll
        for (int j = 0; j < 8; j++) acc[i][j] = 0.0f;

    for (int k0 = 0; k0 < K; k0 += 8) {
        float4 av = *(const float4*)(Aptr + k0);
        float4 bv = *(const float4*)(Bptr + k0);
        __syncthreads();
        As[lk4+0][lrow] = av.x; As[lk4+1][lrow] = av.y;
        As[lk4+2][lrow] = av.z; As[lk4+3][lrow] = av.w;
        Bs[lk4+0][lrow] = bv.x; Bs[lk4+1][lrow] = bv.y;
        Bs[lk4+2][lrow] = bv.z; Bs[lk4+3][lrow] = bv.w;
        __syncthreads();
#pragma unroll
        for (int kk = 0; kk < 8; kk++) {
            float a[8], b[8];
            *(float4*)(a)   = *(const float4*)&As[kk][ty*8];
            *(float4*)(a+4) = *(const float4*)&As[kk][ty*8+4];
            *(float4*)(b)   = *(const float4*)&Bs[kk][tx*8];
            *(float4*)(b+4) = *(const float4*)&Bs[kk][tx*8+4];
#pragma unroll
            for (int i = 0; i < 8; i++)
#pragma unroll
                for (int j = 0; j < 8; j++)
                    acc[i][j] += a[i] * b[j];
        }
    }

#pragma unroll
    for (int i = 0; i < 8; i++) {
        int m = m0 + ty*8 + i;
#pragma unroll
        for (int j = 0; j < 8; j++) {
            int n = n0 + tx*8 + j;
            float v = acc[i][j];
            if (MODE == 1) {
                v += bias[n];
                int head = n / (3*HDIM);
                int r3   = n % (3*HDIM);
                int part = r3 / HDIM;
                int d    = r3 % HDIM;
                int s_idx = m >> 1;          // BATCH == 2
                int b_idx = m & 1;
                int off = ((b_idx*NHEADS + head)*SEQ + s_idx)*HDIM + d;
                if      (part == 0) g_q[off] = v;
                else if (part == 1) g_k[off] = v;
                else                g_v[off] = v;
            } else {
                C[(size_t)m * N + n] = v;
            }
        }
    }
}

// ---------------- RoPE tables + apply --------------------------------------
__global__ void rope_table_kernel() {
    int idx = blockIdx.x * blockDim.x + threadIdx.x;
    if (idx >= SEQ * 64) return;
    int s = idx >> 6;
    int i = idx & 63;
    // match reference rounding: inv_freq as float32, theta = f32(s)*f32(inv)
    float inv_f = (float)pow(10000.0, -((double)i) / 64.0);
    float theta = (float)s * inv_f;          // f32 rounding, like jnp einsum
    double sn, cs;
    sincos((double)theta, &sn, &cs);
    g_cos[idx] = (float)cs;
    g_sin[idx] = (float)sn;
}

__global__ void rope_apply_kernel() {
    int idx = blockIdx.x * blockDim.x + threadIdx.x;
    int total = BATCH*NHEADS*SEQ*64;
    if (idx >= total) return;
    int i = idx & 63;
    int rowid = idx >> 6;           // (b*NH+h)*SEQ + s
    int s = rowid & (SEQ - 1);
    float c  = g_cos[s*64 + i];
    float sn = g_sin[s*64 + i];
    int base = rowid * HDIM;
    float q1 = g_q[base + i], q2 = g_q[base + 64 + i];
    float k1 = g_k[base + i], k2 = g_k[base + 64 + i];
    g_q[base + i]      = q1*c - q2*sn;
    g_q[base + 64 + i] = q2*c + q1*sn;
    g_k[base + i]      = k1*c - k2*sn;
    g_k[base + 64 + i] = k2*c + k1*sn;
}

// ---------------- causal flash attention ------------------------------------
// block: (bh, qtile of 64 rows), 256 threads.
// smem: Qst[128][68] transposed, KV buffer (Kst[128][68] then Vs[64][128]),
//       Ss[64][65], m/l/scale rows.
#define Q_STRIDE 68
#define ATT_SMEM ((128*Q_STRIDE + 128*Q_STRIDE + 64*65 + 3*64) * 4)

__global__ void attn_kernel() {
    extern __shared__ float sm[];
    float* Qst  = sm;                         // [128][68]
    float* KV   = Qst + 128*Q_STRIDE;         // Kst [128][68]  OR  Vs [64][128]
    float* Ss   = KV  + 128*Q_STRIDE;         // [64][65]
    float* mrow = Ss  + 64*65;
    float* lrow = mrow + 64;
    float* srow = lrow + 64;

    int tid = threadIdx.x;
    int tx = tid & 15;
    int ty = tid >> 4;
    int qt = blockIdx.x;                      // 0..31
    int bh = blockIdx.y;                      // 0..31 (= b*NHEADS + h)
    int q0 = qt * 64;

    const float* Qg = g_q + (size_t)bh * SEQ * HDIM;
    const float* Kg = g_k + (size_t)bh * SEQ * HDIM;
    const float* Vg = g_v + (size_t)bh * SEQ * HDIM;

    // load Q tile transposed
#pragma unroll
    for (int t = 0; t < 8; t++) {
        int f4  = tid + t*256;
        int row = f4 >> 5;
        int d   = (f4 & 31) * 4;
        float4 v = *(const float4*)(Qg + (size_t)(q0 + row)*HDIM + d);
        Qst[(d+0)*Q_STRIDE + row] = v.x;
        Qst[(d+1)*Q_STRIDE + row] = v.y;
        Qst[(d+2)*Q_STRIDE + row] = v.z;
        Qst[(d+3)*Q_STRIDE + row] = v.w;
    }
    if (tid < 64) { mrow[tid] = -1e30f; lrow[tid] = 0.0f; }

    float acc[4][8];
#pragma unroll
    for (int i = 0; i < 4; i++)
#pragma unroll
        for (int c = 0; c < 8; c++) acc[i][c] = 0.0f;

    const float rnorm = 0.088388347648318447f;   // 1/sqrt(128)

    for (int kt = 0; kt <= qt; kt++) {
        int k0 = kt * 64;
        __syncthreads();   // previous PV done with KV / Ss; Q load visible
        // load K tile transposed
#pragma unroll
        for (int t = 0; t < 8; t++) {
            int f4  = tid + t*256;
            int row = f4 >> 5;
            int d   = (f4 & 31) * 4;
            float4 v = *(const float4*)(Kg + (size_t)(k0 + row)*HDIM + d);
            KV[(d+0)*Q_STRIDE + row] = v.x;
            KV[(d+1)*Q_STRIDE + row] = v.y;
            KV[(d+2)*Q_STRIDE + row] = v.z;
            KV[(d+3)*Q_STRIDE + row] = v.w;
        }
        __syncthreads();

        // S = Q K^T  (each thread 4x4)
        float sacc[4][4];
#pragma unroll
        for (int i = 0; i < 4; i++)
#pragma unroll
            for (int j = 0; j < 4; j++) sacc[i][j] = 0.0f;

        for (int d = 0; d < HDIM; d++) {
            float4 q4 = *(const float4*)&Qst[d*Q_STRIDE + ty*4];
            float4 k4 = *(const float4*)&KV [d*Q_STRIDE + tx*4];
            float qa[4] = {q4.x, q4.y, q4.z, q4.w};
            float kb[4] = {k4.x, k4.y, k4.z, k4.w};
#pragma unroll
            for (int i = 0; i < 4; i++)
#pragma unroll
                for (int j = 0; j < 4; j++)
                    sacc[i][j] += qa[i] * kb[j];
        }
#pragma unroll
        for (int i = 0; i < 4; i++) {
            int gi = q0 + ty*4 + i;
#pragma unroll
            for (int j = 0; j < 4; j++) {
                int gj = k0 + tx*4 + j;
                float v = sacc[i][j] * rnorm;
                if (gj > gi) v = -10000.0f;   // same constant as reference
                Ss[(ty*4 + i)*65 + tx*4 + j] = v;
            }
        }
        __syncthreads();

        // row-wise online softmax (64 rows, one thread each)
        if (tid < 64) {
            int r = tid;
            float m_old = mrow[r];
            float mx = m_old;
            for (int j = 0; j < 64; j++) mx = fmaxf(mx, Ss[r*65 + j]);
            float scale = expf(m_old - mx);
            float sum = 0.0f;
            for (int j = 0; j < 64; j++) {
                float p = expf(Ss[r*65 + j] - mx);
                Ss[r*65 + j] = p;
                sum += p;
            }
            mrow[r] = mx;
            lrow[r] = lrow[r] * scale + sum;
            srow[r] = scale;
        }
        __syncthreads();

        // load V tile (row-major) into KV buffer
#pragma unroll
        for (int t = 0; t < 8; t++) {
            int f4  = tid + t*256;
            int row = f4 >> 5;
            int d   = (f4 & 31) * 4;
            float4 v = *(const float4*)(Vg + (size_t)(k0 + row)*HDIM + d);
            *(float4*)&KV[row*HDIM + d] = v;
        }
        __syncthreads();

        // rescale acc, then acc += P * V  (each thread 4 rows x 8 cols)
        float sc[4];
#pragma unroll
        for (int i = 0; i < 4; i++) sc[i] = srow[ty*4 + i];
#pragma unroll
        for (int i = 0; i < 4; i++)
#pragma unroll
            for (int c = 0; c < 8; c++) acc[i][c] *= sc[i];

        for (int j = 0; j < 64; j++) {
            float p[4];
#pragma unroll
            for (int i = 0; i < 4; i++) p[i] = Ss[(ty*4 + i)*65 + j];
            float4 va = *(const float4*)&KV[j*HDIM + tx*8];
            float4 vb = *(const float4*)&KV[j*HDIM + tx*8 + 4];
            float vv[8] = {va.x, va.y, va.z, va.w, vb.x, vb.y, vb.z, vb.w};
#pragma unroll
            for (int i = 0; i < 4; i++)
#pragma unroll
                for (int c = 0; c < 8; c++)
                    acc[i][c] += p[i] * vv[c];
        }
    }

    // finalize: divide by l, write context [s,b,h]
    int b_idx = bh / NHEADS;
    int h_idx = bh % NHEADS;
#pragma unroll
    for (int i = 0; i < 4; i++) {
        float linv = 1.0f / lrow[ty*4 + i];
        int s_idx = q0 + ty*4 + i;
        float* dst = g_ctx + ((size_t)(s_idx*BATCH + b_idx))*HID + h_idx*HDIM + tx*8;
#pragma unroll
        for (int c = 0; c < 8; c++)
            dst[c] = acc[i][c] * linv;
    }
}

// ---------------- tail: append b_dense (skip_bias_add returns it) -----------
__global__ void tail_copy(const float* __restrict__ src, float* __restrict__ dst, int n) {
    int i = blockIdx.x * blockDim.x + threadIdx.x;
    if (i < n) dst[i] = src[i];
}

// ---------------- launch -----------------------------------------------------
extern "C" void kernel_launch(void* const* d_in, const int* in_sizes, int n_in,
                              void* d_out, int out_size)
{
    const float* hidden  = (const float*)d_in[0];
    // d_in[1] = attention_mask (causal; recomputed on device, unused)
    const float* w_qkv   = (const float*)d_in[2];
    const float* b_qkv   = (const float*)d_in[3];
    const float* w_dense = (const float*)d_in[4];
    const float* b_dense = (const float*)d_in[5];
    float* out = (float*)d_out;

    // 1) QKV projection + scatter
    gemm_nt<1><<<dim3(QKV_N/128, TOK/128), 256>>>(hidden, w_qkv, b_qkv, nullptr,
                                                  TOK, QKV_N, HID);
    // 2) RoPE
    rope_table_kernel<<<(SEQ*64 + 255)/256, 256>>>();
    {
        int total = BATCH*NHEADS*SEQ*64;
        rope_apply_kernel<<<(total + 255)/256, 256>>>();
    }
    // 3) causal attention
    cudaFuncSetAttribute(attn_kernel, cudaFuncAttributeMaxDynamicSharedMemorySize,
                         ATT_SMEM);
    attn_kernel<<<dim3(SEQ/64, BATCH*NHEADS), 256, ATT_SMEM>>>();
    // 4) dense projection (no bias: skip_bias_add)
    gemm_nt<2><<<dim3(HID/128, TOK/128), 256>>>(nullptr, w_dense, nullptr, out,
                                                TOK, HID, HID);
    // 5) append bias output if the harness expects the tuple flattened
    int extra = out_size - TOK*HID;
    if (extra > 0) {
        tail_copy<<<(extra + 255)/256, 256>>>(b_dense, out + (size_t)TOK*HID, extra);
    }
    (void)in_sizes; (void)n_in;
}

// round 4
// speedup vs baseline: 1.5967x; 1.5967x over previous
#include <cuda_runtime.h>
#include <cuda_bf16.h>
#include <math.h>
#include <stdint.h>

#define SEQ     2048
#define BATCH   2
#define HID     2048
#define NHEADS  16
#define HDIM    128
#define TOK     (SEQ*BATCH)     // 4096
#define QKV_N   (3*HID)         // 6144
#define K3      (3*HID)         // split-3 K' = 6144

// ---------------- scratch (device globals; no runtime allocs allowed) -------
__device__ float g_q[BATCH*NHEADS*SEQ*HDIM];
__device__ float g_k[BATCH*NHEADS*SEQ*HDIM];
__device__ float g_v[BATCH*NHEADS*SEQ*HDIM];
__device__ float g_ctx[TOK*HID];
__device__ float g_cos[SEQ*64];
__device__ float g_sin[SEQ*64];
// bf16 split-3 operand buffers
__device__ __align__(1024) __nv_bfloat16 g_Abuf[TOK*K3];      // A' [4096, 6144]
__device__ __align__(1024) __nv_bfloat16 g_Bq[QKV_N*K3];      // B' qkv [6144, 6144]
__device__ __align__(1024) __nv_bfloat16 g_Bd[HID*K3];        // B' dense [2048, 6144]

// ============================================================================
// PTX helpers (base-target-safe: mma.sync / ldmatrix / cp.async only)
// ============================================================================
__device__ __forceinline__ uint32_t smem_u32(const void* p) {
    uint32_t a;
    asm("{ .reg .u64 t; cvta.to.shared.u64 t, %1; cvt.u32.u64 %0, t; }"
        : "=r"(a) : "l"(p));
    return a;
}
__device__ __forceinline__ void cpasync16(uint32_t s, const void* g) {
    asm volatile("cp.async.cg.shared.global [%0], [%1], 16;" :: "r"(s), "l"(g));
}
#define CP_COMMIT() asm volatile("cp.async.commit_group;" ::: "memory")
#define CP_WAIT(n)  asm volatile("cp.async.wait_group %0;" :: "n"(n) : "memory")

__device__ __forceinline__ void ldsm4(uint32_t* r, uint32_t a) {
    asm volatile("ldmatrix.sync.aligned.m8n8.x4.shared.b16 {%0,%1,%2,%3}, [%4];"
        : "=r"(r[0]), "=r"(r[1]), "=r"(r[2]), "=r"(r[3]) : "r"(a));
}
__device__ __forceinline__ void ldsm2(uint32_t* r, uint32_t a) {
    asm volatile("ldmatrix.sync.aligned.m8n8.x2.shared.b16 {%0,%1}, [%2];"
        : "=r"(r[0]), "=r"(r[1]) : "r"(a));
}
__device__ __forceinline__ void mma16816(float* c, const uint32_t* a, const uint32_t* b) {
    asm volatile("mma.sync.aligned.m16n8k16.row.col.f32.bf16.bf16.f32 "
        "{%0,%1,%2,%3}, {%4,%5,%6,%7}, {%8,%9}, {%0,%1,%2,%3};"
        : "+f"(c[0]), "+f"(c[1]), "+f"(c[2]), "+f"(c[3])
        : "r"(a[0]), "r"(a[1]), "r"(a[2]), "r"(a[3]), "r"(b[0]), "r"(b[1]));
}

// ============================================================================
// HMMA split-3 bf16 GEMM: C[M,N] = A'[M,K3] * B'[N,K3]^T  (fp32 accum)
// CTA tile 128x128x32, 256 thr (8 warps 2x4, warp tile 64x32), double-buffered
// cp.async pipeline. Rows padded to 40 bf16 (80B) -> conflict-free ldmatrix.
// MODE 1: QKV — add bias + scatter to q/k/v.   MODE 2: plain C store.
// ============================================================================
#define BK 32
#define ASTR 40                        // bf16 elements per smem row (80 B)
#define TILE_B16 (128*ASTR)            // 5120 bf16 per operand tile
#define TILE_BYTES (TILE_B16*2)        // 10240
#define BUF_BYTES (2*TILE_BYTES)       // A+B per buffer

template<int MODE>
__global__ void __launch_bounds__(256, 2)
hmma_gemm(const __nv_bfloat16* __restrict__ Ag, const __nv_bfloat16* __restrict__ Bg,
          const float* __restrict__ bias, float* __restrict__ C,
          float* __restrict__ q_out, float* __restrict__ k_out, float* __restrict__ v_out,
          int N)
{
    __shared__ __align__(16) __nv_bfloat16 smbuf[2 * 2 * TILE_B16];

    const int tid  = threadIdx.x;
    const int lane = tid & 31;
    const int warp = tid >> 5;
    const int wm = warp >> 2;          // 0..1
    const int wn = warp & 3;           // 0..3
    const int m0 = blockIdx.y * 128;
    const int n0 = blockIdx.x * 128;

    const uint32_t smb = smem_u32(smbuf);

    // cp.async assignment: 2 chunks per operand per thread
    const int cr = tid >> 2;           // row 0..63 (second set +64)
    const int ccn = tid & 3;           // 16B chunk within 64B row

    const int KT = K3 / BK;            // 192

    // prefetch helper (macro-ish lambda)
    auto prefetch = [&](int kt, int buf) {
        uint32_t base = smb + buf * BUF_BYTES;
#pragma unroll
        for (int h = 0; h < 2; h++) {
            int r = cr + h * 64;
            uint32_t ad = base + (r * ASTR + ccn * 8) * 2;
            cpasync16(ad, Ag + (size_t)(m0 + r) * K3 + kt * BK + ccn * 8);
            uint32_t bd = base + TILE_BYTES + (r * ASTR + ccn * 8) * 2;
            cpasync16(bd, Bg + (size_t)(n0 + r) * K3 + kt * BK + ccn * 8);
        }
    };

    float acc[4][4][4];
#pragma unroll
    for (int i = 0; i < 4; i++)
#pragma unroll
        for (int j = 0; j < 4; j++)
#pragma unroll
            for (int e = 0; e < 4; e++) acc[i][j][e] = 0.0f;

    // ldmatrix per-lane address pieces
    const int l16 = lane & 15;
    const uint32_t a_off = (((wm * 64 + l16) * ASTR) + ((lane >> 4) * 8)) * 2;
    const uint32_t b_off = (((wn * 32 + (l16 & 7)) * ASTR) + ((l16 >> 3) * 8)) * 2;

    prefetch(0, 0);
    CP_COMMIT();

    for (int kt = 0; kt < KT; kt++) {
        if (kt + 1 < KT) {
            prefetch(kt + 1, (kt + 1) & 1);
            CP_COMMIT();
            CP_WAIT(1);
        } else {
            CP_WAIT(0);
        }
        __syncthreads();

        uint32_t abase = smb + (kt & 1) * BUF_BYTES + a_off;
        uint32_t bbase = smb + (kt & 1) * BUF_BYTES + TILE_BYTES + b_off;

#pragma unroll
        for (int k16 = 0; k16 < BK; k16 += 16) {
            uint32_t bfr[4][2];
#pragma unroll
            for (int nt = 0; nt < 4; nt++)
                ldsm2(bfr[nt], bbase + (nt * 8 * ASTR + k16) * 2);
#pragma unroll
            for (int mt = 0; mt < 4; mt++) {
                uint32_t afr[4];
                ldsm4(afr, abase + (mt * 16 * ASTR + k16) * 2);
#pragma unroll
                for (int nt = 0; nt < 4; nt++)
                    mma16816(acc[mt][nt], afr, bfr[nt]);
            }
        }
        __syncthreads();
    }

    // ---------------- epilogue ----------------
    const int g  = lane >> 2;
    const int c2 = (lane & 3) * 2;
#pragma unroll
    for (int mt = 0; mt < 4; mt++) {
#pragma unroll
        for (int nt = 0; nt < 4; nt++) {
#pragma unroll
            for (int i = 0; i < 2; i++) {
#pragma unroll
                for (int j = 0; j < 2; j++) {
                    int m = m0 + wm * 64 + mt * 16 + g + i * 8;
                    int n = n0 + wn * 32 + nt * 8 + c2 + j;
                    float v = acc[mt][nt][i * 2 + j];
                    if (MODE == 1) {
                        v += bias[n];
                        int head = n / (3 * HDIM);
                        int r3   = n % (3 * HDIM);
                        int part = r3 / HDIM;
                        int d    = r3 % HDIM;
                        int off  = (((m & 1) * NHEADS + head) * SEQ + (m >> 1)) * HDIM + d;
                        if      (part == 0) q_out[off] = v;
                        else if (part == 1) k_out[off] = v;
                        else                v_out[off] = v;
                    } else {
                        C[(size_t)m * N + n] = v;
                    }
                }
            }
        }
    }
}

// ---------------- split-3 conversion: fp32 -> bf16 hi/lo triplets ----------
// PAT 0 (A): [hi|lo|hi]    PAT 1 (B): [hi|hi|lo]
template<int PAT>
__global__ void conv_split(const float* __restrict__ src,
                           __nv_bfloat16* __restrict__ dst, int R, int K)
{
    int idx = blockIdx.x * blockDim.x + threadIdx.x;
    if (idx >= R * K) return;
    int row = idx / K, col = idx - row * K;
    float x = src[idx];
    __nv_bfloat16 h = __float2bfloat16(x);
    __nv_bfloat16 l = __float2bfloat16(x - __bfloat162float(h));
    size_t base = (size_t)row * (3*K) + col;
    if (PAT == 0) { dst[base] = h; dst[base + K] = l; dst[base + 2*K] = h; }
    else          { dst[base] = h; dst[base + K] = h; dst[base + 2*K] = l; }
}

// ---------------- RoPE tables + apply ---------------------------------------
__global__ void rope_table_kernel() {
    int idx = blockIdx.x * blockDim.x + threadIdx.x;
    if (idx >= SEQ * 64) return;
    int s = idx >> 6;
    int i = idx & 63;
    float inv_f = (float)pow(10000.0, -((double)i) / 64.0);
    float theta = (float)s * inv_f;
    double sn, cs;
    sincos((double)theta, &sn, &cs);
    g_cos[idx] = (float)cs;
    g_sin[idx] = (float)sn;
}

__global__ void rope_apply_kernel() {
    int idx = blockIdx.x * blockDim.x + threadIdx.x;
    int total = BATCH*NHEADS*SEQ*64;
    if (idx >= total) return;
    int i = idx & 63;
    int rowid = idx >> 6;
    int s = rowid & (SEQ - 1);
    float c  = g_cos[s*64 + i];
    float sn = g_sin[s*64 + i];
    int base = rowid * HDIM;
    float q1 = g_q[base + i], q2 = g_q[base + 64 + i];
    float k1 = g_k[base + i], k2 = g_k[base + 64 + i];
    g_q[base + i]      = q1*c - q2*sn;
    g_q[base + 64 + i] = q2*c + q1*sn;
    g_k[base + i]      = k1*c - k2*sn;
    g_k[base + 64 + i] = k2*c + k1*sn;
}

// ---------------- causal flash attention (R1, passing) -----------------------
#define Q_STRIDE 68
#define ATT_SMEM ((128*Q_STRIDE + 128*Q_STRIDE + 64*65 + 3*64) * 4)

__global__ void attn_kernel() {
    extern __shared__ float sm[];
    float* Qst  = sm;
    float* KV   = Qst + 128*Q_STRIDE;
    float* Ss   = KV  + 128*Q_STRIDE;
    float* mrow = Ss  + 64*65;
    float* lrow = mrow + 64;
    float* srow = lrow + 64;

    int tid = threadIdx.x;
    int tx = tid & 15;
    int ty = tid >> 4;
    int qt = blockIdx.x;
    int bh = blockIdx.y;
    int q0 = qt * 64;

    const float* Qg = g_q + (size_t)bh * SEQ * HDIM;
    const float* Kg = g_k + (size_t)bh * SEQ * HDIM;
    const float* Vg = g_v + (size_t)bh * SEQ * HDIM;

#pragma unroll
    for (int t = 0; t < 8; t++) {
        int f4  = tid + t*256;
        int row = f4 >> 5;
        int d   = (f4 & 31) * 4;
        float4 v = *(const float4*)(Qg + (size_t)(q0 + row)*HDIM + d);
        Qst[(d+0)*Q_STRIDE + row] = v.x;
        Qst[(d+1)*Q_STRIDE + row] = v.y;
        Qst[(d+2)*Q_STRIDE + row] = v.z;
        Qst[(d+3)*Q_STRIDE + row] = v.w;
    }
    if (tid < 64) { mrow[tid] = -1e30f; lrow[tid] = 0.0f; }

    float acc[4][8];
#pragma unroll
    for (int i = 0; i < 4; i++)
#pragma unroll
        for (int c = 0; c < 8; c++) acc[i][c] = 0.0f;

    const float rnorm = 0.088388347648318447f;

    for (int kt = 0; kt <= qt; kt++) {
        int k0 = kt * 64;
        __syncthreads();
#pragma unroll
        for (int t = 0; t < 8; t++) {
            int f4  = tid + t*256;
            int row = f4 >> 5;
            int d   = (f4 & 31) * 4;
            float4 v = *(const float4*)(Kg + (size_t)(k0 + row)*HDIM + d);
            KV[(d+0)*Q_STRIDE + row] = v.x;
            KV[(d+1)*Q_STRIDE + row] = v.y;
            KV[(d+2)*Q_STRIDE + row] = v.z;
            KV[(d+3)*Q_STRIDE + row] = v.w;
        }
        __syncthreads();

        float sacc[4][4];
#pragma unroll
        for (int i = 0; i < 4; i++)
#pragma unroll
            for (int j = 0; j < 4; j++) sacc[i][j] = 0.0f;

        for (int d = 0; d < HDIM; d++) {
            float4 q4 = *(const float4*)&Qst[d*Q_STRIDE + ty*4];
            float4 k4 = *(const float4*)&KV [d*Q_STRIDE + tx*4];
            float qa[4] = {q4.x, q4.y, q4.z, q4.w};
            float kb[4] = {k4.x, k4.y, k4.z, k4.w};
#pragma unroll
            for (int i = 0; i < 4; i++)
#pragma unroll
                for (int j = 0; j < 4; j++)
                    sacc[i][j] += qa[i] * kb[j];
        }
#pragma unroll
        for (int i = 0; i < 4; i++) {
            int gi = q0 + ty*4 + i;
#pragma unroll
            for (int j = 0; j < 4; j++) {
                int gj = k0 + tx*4 + j;
                float v = sacc[i][j] * rnorm;
                if (gj > gi) v = -10000.0f;
                Ss[(ty*4 + i)*65 + tx*4 + j] = v;
            }
        }
        __syncthreads();

        if (tid < 64) {
            int r = tid;
            float m_old = mrow[r];
            float mx = m_old;
            for (int j = 0; j < 64; j++) mx = fmaxf(mx, Ss[r*65 + j]);
            float scale = expf(m_old - mx);
            float sum = 0.0f;
            for (int j = 0; j < 64; j++) {
                float p = expf(Ss[r*65 + j] - mx);
                Ss[r*65 + j] = p;
                sum += p;
            }
            mrow[r] = mx;
            lrow[r] = lrow[r] * scale + sum;
            srow[r] = scale;
        }
        __syncthreads();

#pragma unroll
        for (int t = 0; t < 8; t++) {
            int f4  = tid + t*256;
            int row = f4 >> 5;
            int d   = (f4 & 31) * 4;
            float4 v = *(const float4*)(Vg + (size_t)(k0 + row)*HDIM + d);
            *(float4*)&KV[row*HDIM + d] = v;
        }
        __syncthreads();

        float sc[4];
#pragma unroll
        for (int i = 0; i < 4; i++) sc[i] = srow[ty*4 + i];
#pragma unroll
        for (int i = 0; i < 4; i++)
#pragma unroll
            for (int c = 0; c < 8; c++) acc[i][c] *= sc[i];

        for (int j = 0; j < 64; j++) {
            float p[4];
#pragma unroll
            for (int i = 0; i < 4; i++) p[i] = Ss[(ty*4 + i)*65 + j];
            float4 va = *(const float4*)&KV[j*HDIM + tx*8];
            float4 vb = *(const float4*)&KV[j*HDIM + tx*8 + 4];
            float vv[8] = {va.x, va.y, va.z, va.w, vb.x, vb.y, vb.z, vb.w};
#pragma unroll
            for (int i = 0; i < 4; i++)
#pragma unroll
                for (int c = 0; c < 8; c++)
                    acc[i][c] += p[i] * vv[c];
        }
    }

    int b_idx = bh / NHEADS;
    int h_idx = bh % NHEADS;
#pragma unroll
    for (int i = 0; i < 4; i++) {
        float linv = 1.0f / lrow[ty*4 + i];
        int s_idx = q0 + ty*4 + i;
        float* dst = g_ctx + ((size_t)(s_idx*BATCH + b_idx))*HID + h_idx*HDIM + tx*8;
#pragma unroll
        for (int c = 0; c < 8; c++)
            dst[c] = acc[i][c] * linv;
    }
}

// ---------------- tail bias ---------------------------------------------------
__global__ void tail_copy(const float* __restrict__ src, float* __restrict__ dst, int n) {
    int i = blockIdx.x * blockDim.x + threadIdx.x;
    if (i < n) dst[i] = src[i];
}

// ---------------- launch -------------------------------------------------------
extern "C" void kernel_launch(void* const* d_in, const int* in_sizes, int n_in,
                              void* d_out, int out_size)
{
    const float* hidden  = (const float*)d_in[0];
    const float* w_qkv   = (const float*)d_in[2];
    const float* b_qkv   = (const float*)d_in[3];
    const float* w_dense = (const float*)d_in[4];
    const float* b_dense = (const float*)d_in[5];
    float* out = (float*)d_out;

    // device addresses of __device__ symbols
    void *pA, *pBq, *pBd, *pCtx, *pQ, *pK, *pV;
    cudaGetSymbolAddress(&pA,   g_Abuf);
    cudaGetSymbolAddress(&pBq,  g_Bq);
    cudaGetSymbolAddress(&pBd,  g_Bd);
    cudaGetSymbolAddress(&pCtx, g_ctx);
    cudaGetSymbolAddress(&pQ,   g_q);
    cudaGetSymbolAddress(&pK,   g_k);
    cudaGetSymbolAddress(&pV,   g_v);

    cudaFuncSetAttribute(attn_kernel, cudaFuncAttributeMaxDynamicSharedMemorySize, ATT_SMEM);

    // 1) split-convert A (hidden) and B (w_qkv)
    conv_split<0><<<(TOK*HID + 255)/256, 256>>>(hidden, (__nv_bfloat16*)pA, TOK, HID);
    conv_split<1><<<(QKV_N*HID + 255)/256, 256>>>(w_qkv, (__nv_bfloat16*)pBq, QKV_N, HID);

    // 2) QKV projection (HMMA, bias + scatter epilogue)
    hmma_gemm<1><<<dim3(QKV_N/128, TOK/128), 256>>>(
        (const __nv_bfloat16*)pA, (const __nv_bfloat16*)pBq, b_qkv, nullptr,
        (float*)pQ, (float*)pK, (float*)pV, QKV_N);

    // 3) RoPE
    rope_table_kernel<<<(SEQ*64 + 255)/256, 256>>>();
    rope_apply_kernel<<<(BATCH*NHEADS*SEQ*64 + 255)/256, 256>>>();

    // 4) causal attention (fp32)
    attn_kernel<<<dim3(SEQ/64, BATCH*NHEADS), 256, ATT_SMEM>>>();

    // 5) split-convert ctx + w_dense, dense GEMM (HMMA)
    conv_split<0><<<(TOK*HID + 255)/256, 256>>>((const float*)pCtx, (__nv_bfloat16*)pA, TOK, HID);
    conv_split<1><<<(HID*HID + 255)/256, 256>>>(w_dense, (__nv_bfloat16*)pBd, HID, HID);
    hmma_gemm<2><<<dim3(HID/128, TOK/128), 256>>>(
        (const __nv_bfloat16*)pA, (const __nv_bfloat16*)pBd, nullptr, out,
        nullptr, nullptr, nullptr, HID);

    // 6) bias tail if harness flattens the (output, bias) tuple
    int extra = out_size - TOK*HID;
    if (extra > 0)
        tail_copy<<<(extra + 255)/256, 256>>>(b_dense, out + (size_t)TOK*HID, extra);
    (void)in_sizes; (void)n_in;
}

// round 5
// speedup vs baseline: 2.1971x; 1.3760x over previous
#include <cuda_runtime.h>
#include <cuda_bf16.h>
#include <math.h>
#include <stdint.h>

#define SEQ     2048
#define BATCH   2
#define HID     2048
#define NHEADS  16
#define HDIM    128
#define TOK     (SEQ*BATCH)     // 4096
#define QKV_N   (3*HID)         // 6144
#define K3      (3*HID)         // split-3 K' = 6144
#define NBH     (BATCH*NHEADS)  // 32

// ---------------- scratch (device globals; no runtime allocs allowed) -------
__device__ float g_q[NBH*SEQ*HDIM];
__device__ float g_k[NBH*SEQ*HDIM];
__device__ float g_v[NBH*SEQ*HDIM];
__device__ float g_ctx[TOK*HID];
__device__ float g_cos[SEQ*64];
__device__ float g_sin[SEQ*64];
// bf16 split-3 operand buffers (GEMMs)
__device__ __align__(1024) __nv_bfloat16 g_Abuf[TOK*K3];
__device__ __align__(1024) __nv_bfloat16 g_Bq[QKV_N*K3];
__device__ __align__(1024) __nv_bfloat16 g_Bd[HID*K3];
// attention split operands
__device__ __align__(16) __nv_bfloat16 gq_hi[NBH*SEQ*HDIM];
__device__ __align__(16) __nv_bfloat16 gq_lo[NBH*SEQ*HDIM];
__device__ __align__(16) __nv_bfloat16 gk_hi[NBH*SEQ*HDIM];
__device__ __align__(16) __nv_bfloat16 gk_lo[NBH*SEQ*HDIM];
__device__ __align__(16) __nv_bfloat16 gvt_hi[NBH*HDIM*SEQ];   // [bh][d][s]
__device__ __align__(16) __nv_bfloat16 gvt_lo[NBH*HDIM*SEQ];

// ============================================================================
// PTX helpers (base-target-safe)
// ============================================================================
__device__ __forceinline__ uint32_t smem_u32(const void* p) {
    uint32_t a;
    asm("{ .reg .u64 t; cvta.to.shared.u64 t, %1; cvt.u32.u64 %0, t; }"
        : "=r"(a) : "l"(p));
    return a;
}
__device__ __forceinline__ void cpasync16(uint32_t s, const void* g) {
    asm volatile("cp.async.cg.shared.global [%0], [%1], 16;" :: "r"(s), "l"(g));
}
#define CP_COMMIT() asm volatile("cp.async.commit_group;" ::: "memory")
#define CP_WAIT(n)  asm volatile("cp.async.wait_group %0;" :: "n"(n) : "memory")

__device__ __forceinline__ void ldsm4(uint32_t* r, uint32_t a) {
    asm volatile("ldmatrix.sync.aligned.m8n8.x4.shared.b16 {%0,%1,%2,%3}, [%4];"
        : "=r"(r[0]), "=r"(r[1]), "=r"(r[2]), "=r"(r[3]) : "r"(a));
}
__device__ __forceinline__ void ldsm2(uint32_t* r, uint32_t a) {
    asm volatile("ldmatrix.sync.aligned.m8n8.x2.shared.b16 {%0,%1}, [%2];"
        : "=r"(r[0]), "=r"(r[1]) : "r"(a));
}
__device__ __forceinline__ void mma16816(float* c, const uint32_t* a, const uint32_t* b) {
    asm volatile("mma.sync.aligned.m16n8k16.row.col.f32.bf16.bf16.f32 "
        "{%0,%1,%2,%3}, {%4,%5,%6,%7}, {%8,%9}, {%0,%1,%2,%3};"
        : "+f"(c[0]), "+f"(c[1]), "+f"(c[2]), "+f"(c[3])
        : "r"(a[0]), "r"(a[1]), "r"(a[2]), "r"(a[3]), "r"(b[0]), "r"(b[1]));
}

// ============================================================================
// HMMA split-3 bf16 GEMM (unchanged from R4, except MODE1 V epilogue keeps g_v)
// ============================================================================
#define BK 32
#define ASTR 40
#define TILE_B16 (128*ASTR)
#define TILE_BYTES (TILE_B16*2)
#define BUF_BYTES (2*TILE_BYTES)

template<int MODE>
__global__ void __launch_bounds__(256, 2)
hmma_gemm(const __nv_bfloat16* __restrict__ Ag, const __nv_bfloat16* __restrict__ Bg,
          const float* __restrict__ bias, float* __restrict__ C,
          float* __restrict__ q_out, float* __restrict__ k_out, float* __restrict__ v_out,
          int N)
{
    __shared__ __align__(16) __nv_bfloat16 smbuf[2 * 2 * TILE_B16];

    const int tid  = threadIdx.x;
    const int lane = tid & 31;
    const int warp = tid >> 5;
    const int wm = warp >> 2;
    const int wn = warp & 3;
    const int m0 = blockIdx.y * 128;
    const int n0 = blockIdx.x * 128;

    const uint32_t smb = smem_u32(smbuf);
    const int cr = tid >> 2;
    const int ccn = tid & 3;
    const int KT = K3 / BK;

    auto prefetch = [&](int kt, int buf) {
        uint32_t base = smb + buf * BUF_BYTES;
#pragma unroll
        for (int h = 0; h < 2; h++) {
            int r = cr + h * 64;
            uint32_t ad = base + (r * ASTR + ccn * 8) * 2;
            cpasync16(ad, Ag + (size_t)(m0 + r) * K3 + kt * BK + ccn * 8);
            uint32_t bd = base + TILE_BYTES + (r * ASTR + ccn * 8) * 2;
            cpasync16(bd, Bg + (size_t)(n0 + r) * K3 + kt * BK + ccn * 8);
        }
    };

    float acc[4][4][4];
#pragma unroll
    for (int i = 0; i < 4; i++)
#pragma unroll
        for (int j = 0; j < 4; j++)
#pragma unroll
            for (int e = 0; e < 4; e++) acc[i][j][e] = 0.0f;

    const int l16 = lane & 15;
    const uint32_t a_off = (((wm * 64 + l16) * ASTR) + ((lane >> 4) * 8)) * 2;
    const uint32_t b_off = (((wn * 32 + (l16 & 7)) * ASTR) + ((l16 >> 3) * 8)) * 2;

    prefetch(0, 0);
    CP_COMMIT();

    for (int kt = 0; kt < KT; kt++) {
        if (kt + 1 < KT) {
            prefetch(kt + 1, (kt + 1) & 1);
            CP_COMMIT();
            CP_WAIT(1);
        } else {
            CP_WAIT(0);
        }
        __syncthreads();

        uint32_t abase = smb + (kt & 1) * BUF_BYTES + a_off;
        uint32_t bbase = smb + (kt & 1) * BUF_BYTES + TILE_BYTES + b_off;

#pragma unroll
        for (int k16 = 0; k16 < BK; k16 += 16) {
            uint32_t bfr[4][2];
#pragma unroll
            for (int nt = 0; nt < 4; nt++)
                ldsm2(bfr[nt], bbase + (nt * 8 * ASTR + k16) * 2);
#pragma unroll
            for (int mt = 0; mt < 4; mt++) {
                uint32_t afr[4];
                ldsm4(afr, abase + (mt * 16 * ASTR + k16) * 2);
#pragma unroll
                for (int nt = 0; nt < 4; nt++)
                    mma16816(acc[mt][nt], afr, bfr[nt]);
            }
        }
        __syncthreads();
    }

    const int g  = lane >> 2;
    const int c2 = (lane & 3) * 2;
#pragma unroll
    for (int mt = 0; mt < 4; mt++) {
#pragma unroll
        for (int nt = 0; nt < 4; nt++) {
#pragma unroll
            for (int i = 0; i < 2; i++) {
#pragma unroll
                for (int j = 0; j < 2; j++) {
                    int m = m0 + wm * 64 + mt * 16 + g + i * 8;
                    int n = n0 + wn * 32 + nt * 8 + c2 + j;
                    float v = acc[mt][nt][i * 2 + j];
                    if (MODE == 1) {
                        v += bias[n];
                        int head = n / (3 * HDIM);
                        int r3   = n % (3 * HDIM);
                        int part = r3 / HDIM;
                        int d    = r3 % HDIM;
                        int off  = (((m & 1) * NHEADS + head) * SEQ + (m >> 1)) * HDIM + d;
                        if      (part == 0) q_out[off] = v;
                        else if (part == 1) k_out[off] = v;
                        else                v_out[off] = v;
                    } else {
                        C[(size_t)m * N + n] = v;
                    }
                }
            }
        }
    }
}

// ---------------- split-3 conversion (GEMM operands) -------------------------
template<int PAT>
__global__ void conv_split(const float* __restrict__ src,
                           __nv_bfloat16* __restrict__ dst, int R, int K)
{
    int idx = blockIdx.x * blockDim.x + threadIdx.x;
    if (idx >= R * K) return;
    int row = idx / K, col = idx - row * K;
    float x = src[idx];
    __nv_bfloat16 h = __float2bfloat16(x);
    __nv_bfloat16 l = __float2bfloat16(x - __bfloat162float(h));
    size_t base = (size_t)row * (3*K) + col;
    if (PAT == 0) { dst[base] = h; dst[base + K] = l; dst[base + 2*K] = h; }
    else          { dst[base] = h; dst[base + K] = h; dst[base + 2*K] = l; }
}

// ---------------- RoPE tables + apply (apply emits bf16 splits) --------------
__global__ void rope_table_kernel() {
    __shared__ float invf[64];
    if (threadIdx.x < 64)
        invf[threadIdx.x] = (float)pow(10000.0, -((double)threadIdx.x) / 64.0);
    __syncthreads();
    int idx = blockIdx.x * blockDim.x + threadIdx.x;
    if (idx >= SEQ * 64) return;
    int s = idx >> 6;
    int i = idx & 63;
    float theta = (float)s * invf[i];
    double sn, cs;
    sincos((double)theta, &sn, &cs);
    g_cos[idx] = (float)cs;
    g_sin[idx] = (float)sn;
}

__device__ __forceinline__ void split_store(__nv_bfloat16* hi, __nv_bfloat16* lo,
                                            int off, float x) {
    __nv_bfloat16 h = __float2bfloat16(x);
    hi[off] = h;
    lo[off] = __float2bfloat16(x - __bfloat162float(h));
}

__global__ void rope_apply_kernel() {
    int idx = blockIdx.x * blockDim.x + threadIdx.x;
    int total = NBH*SEQ*64;
    if (idx >= total) return;
    int i = idx & 63;
    int rowid = idx >> 6;
    int s = rowid & (SEQ - 1);
    float c  = g_cos[s*64 + i];
    float sn = g_sin[s*64 + i];
    int base = rowid * HDIM;
    float q1 = g_q[base + i], q2 = g_q[base + 64 + i];
    float k1 = g_k[base + i], k2 = g_k[base + 64 + i];
    split_store(gq_hi, gq_lo, base + i,      q1*c - q2*sn);
    split_store(gq_hi, gq_lo, base + 64 + i, q2*c + q1*sn);
    split_store(gk_hi, gk_lo, base + i,      k1*c - k2*sn);
    split_store(gk_hi, gk_lo, base + 64 + i, k2*c + k1*sn);
}

// ---------------- V transpose + split: g_v[bh][s][d] -> gvt[bh][d][s] --------
__global__ void v_transpose_split() {
    __shared__ float t[32][33];
    int bh = blockIdx.z;
    int s0 = blockIdx.x * 32, d0 = blockIdx.y * 32;
    int tx = threadIdx.x, ty = threadIdx.y;   // 32 x 8
#pragma unroll
    for (int i = 0; i < 32; i += 8)
        t[ty + i][tx] = g_v[((size_t)bh*SEQ + s0 + ty + i) * HDIM + d0 + tx];
    __syncthreads();
#pragma unroll
    for (int i = 0; i < 32; i += 8) {
        float x = t[tx][ty + i];
        size_t off = ((size_t)bh*HDIM + d0 + ty + i) * SEQ + s0 + tx;
        __nv_bfloat16 h = __float2bfloat16(x);
        gvt_hi[off] = h;
        gvt_lo[off] = __float2bfloat16(x - __bfloat162float(h));
    }
}

// ============================================================================
// HMMA causal flash attention, split-3 on QK^T and PV.
// CTA: 128 q-rows x one bh. 256 threads (8 warps, 4x2). Key tiles of 64.
// ============================================================================
#define BQ 128
#define BT 64
#define QSTR 136
#define KSTR 136
#define VSTR 72
#define SSTR 68
#define PSTR 72

#define OFF_QHI 0
#define SZ_Q    (BQ*QSTR*2)
#define OFF_QLO (OFF_QHI + SZ_Q)
#define OFF_KHI (OFF_QLO + SZ_Q)
#define SZ_K    (BT*KSTR*2)
#define OFF_KLO (OFF_KHI + SZ_K)
#define OFF_VHI (OFF_KLO + SZ_K)
#define SZ_V    (HDIM*VSTR*2)
#define OFF_VLO (OFF_VHI + SZ_V)
#define OFF_SS  (OFF_VLO + SZ_V)
#define SZ_SS   (BQ*SSTR*4)
#define OFF_PHI (OFF_SS + SZ_SS)
#define SZ_P    (BQ*PSTR*2)
#define OFF_PLO (OFF_PHI + SZ_P)
#define OFF_MR  (OFF_PLO + SZ_P)
#define OFF_LR  (OFF_MR + BQ*4)
#define OFF_SC  (OFF_LR + BQ*4)
#define ATTN_SMEM (OFF_SC + BQ*4)

__global__ void __launch_bounds__(256, 1) attn_hmma() {
    extern __shared__ char smem[];
    const uint32_t sb = smem_u32(smem);

    const int tid  = threadIdx.x;
    const int lane = tid & 31;
    const int warp = tid >> 5;
    const int wm = warp >> 1;              // 0..3 (32 q-rows each)
    const int wn = warp & 1;               // 0..1
    const int qt = gridDim.x - 1 - blockIdx.x;   // heavy tiles first
    const int bh = blockIdx.y;
    const int q0 = qt * BQ;

    const int l16 = lane & 15;
    const int g   = lane >> 2;
    const int c2  = (lane & 3) * 2;

    __nv_bfloat16* s_qhi = (__nv_bfloat16*)(smem + OFF_QHI);
    __nv_bfloat16* s_qlo = (__nv_bfloat16*)(smem + OFF_QLO);
    __nv_bfloat16* s_khi = (__nv_bfloat16*)(smem + OFF_KHI);
    __nv_bfloat16* s_klo = (__nv_bfloat16*)(smem + OFF_KLO);
    __nv_bfloat16* s_vhi = (__nv_bfloat16*)(smem + OFF_VHI);
    __nv_bfloat16* s_vlo = (__nv_bfloat16*)(smem + OFF_VLO);
    float*         s_ss  = (float*)(smem + OFF_SS);
    __nv_bfloat16* s_phi = (__nv_bfloat16*)(smem + OFF_PHI);
    __nv_bfloat16* s_plo = (__nv_bfloat16*)(smem + OFF_PLO);
    float*         mrow  = (float*)(smem + OFF_MR);
    float*         lrow  = (float*)(smem + OFF_LR);
    float*         srow  = (float*)(smem + OFF_SC);

    // ---- load Q tile (hi & lo), once ----
    {
        const __nv_bfloat16* qh = gq_hi + ((size_t)bh*SEQ + q0) * HDIM;
        const __nv_bfloat16* ql = gq_lo + ((size_t)bh*SEQ + q0) * HDIM;
#pragma unroll
        for (int it = 0; it < 8; it++) {
            int t = tid + it*256;
            int row = t >> 4, cc = t & 15;
            *(uint4*)(s_qhi + row*QSTR + cc*8) = *(const uint4*)(qh + row*HDIM + cc*8);
        }
#pragma unroll
        for (int it = 0; it < 8; it++) {
            int t = tid + it*256;
            int row = t >> 4, cc = t & 15;
            *(uint4*)(s_qlo + row*QSTR + cc*8) = *(const uint4*)(ql + row*HDIM + cc*8);
        }
    }
    if (tid < BQ) { mrow[tid] = -1e30f; lrow[tid] = 0.0f; }

    float acc_o[2][8][4];
#pragma unroll
    for (int mt = 0; mt < 2; mt++)
#pragma unroll
        for (int nt = 0; nt < 8; nt++)
#pragma unroll
            for (int e = 0; e < 4; e++) acc_o[mt][nt][e] = 0.0f;

    const float rnorm = 0.088388347648318447f;   // 1/sqrt(128)

    // fragment base addresses
    const uint32_t qhi_b = sb + OFF_QHI + (((wm*32 + l16)*QSTR) + (lane>>4)*8)*2;
    const uint32_t qlo_b = sb + OFF_QLO + (((wm*32 + l16)*QSTR) + (lane>>4)*8)*2;
    const uint32_t khi_b = sb + OFF_KHI + (((wn*32 + (l16&7))*KSTR) + (l16>>3)*8)*2;
    const uint32_t klo_b = sb + OFF_KLO + (((wn*32 + (l16&7))*KSTR) + (l16>>3)*8)*2;
    const uint32_t phi_b = sb + OFF_PHI + (((wm*32 + l16)*PSTR) + (lane>>4)*8)*2;
    const uint32_t plo_b = sb + OFF_PLO + (((wm*32 + l16)*PSTR) + (lane>>4)*8)*2;
    const uint32_t vhi_b = sb + OFF_VHI + (((wn*64 + (l16&7))*VSTR) + (l16>>3)*8)*2;
    const uint32_t vlo_b = sb + OFF_VLO + (((wn*64 + (l16&7))*VSTR) + (l16>>3)*8)*2;

    const int ntiles = 2*qt + 2;
    for (int kt = 0; kt < ntiles; kt++) {
        const int k0 = kt * BT;
        __syncthreads();     // prev iter fully done with K/V/P smem

        // ---- load K tile (hi,lo) and Vt tile (hi,lo) ----
        {
            const __nv_bfloat16* kh = gk_hi + ((size_t)bh*SEQ + k0) * HDIM;
            const __nv_bfloat16* kl = gk_lo + ((size_t)bh*SEQ + k0) * HDIM;
#pragma unroll
            for (int it = 0; it < 4; it++) {
                int t = tid + it*256;
                int row = t >> 4, cc = t & 15;
                *(uint4*)(s_khi + row*KSTR + cc*8) = *(const uint4*)(kh + row*HDIM + cc*8);
            }
#pragma unroll
            for (int it = 0; it < 4; it++) {
                int t = tid + it*256;
                int row = t >> 4, cc = t & 15;
                *(uint4*)(s_klo + row*KSTR + cc*8) = *(const uint4*)(kl + row*HDIM + cc*8);
            }
            const __nv_bfloat16* vh = gvt_hi + (size_t)bh*HDIM*SEQ + k0;
            const __nv_bfloat16* vl = gvt_lo + (size_t)bh*HDIM*SEQ + k0;
#pragma unroll
            for (int it = 0; it < 4; it++) {
                int t = tid + it*256;
                int d = t >> 3, cc = t & 7;
                *(uint4*)(s_vhi + d*VSTR + cc*8) = *(const uint4*)(vh + (size_t)d*SEQ + cc*8);
            }
#pragma unroll
            for (int it = 0; it < 4; it++) {
                int t = tid + it*256;
                int d = t >> 3, cc = t & 7;
                *(uint4*)(s_vlo + d*VSTR + cc*8) = *(const uint4*)(vl + (size_t)d*SEQ + cc*8);
            }
        }
        __syncthreads();

        // ---- S = Q K^T (split-3) ----
        float sacc[2][4][4];
#pragma unroll
        for (int mt = 0; mt < 2; mt++)
#pragma unroll
            for (int nt = 0; nt < 4; nt++)
#pragma unroll
                for (int e = 0; e < 4; e++) sacc[mt][nt][e] = 0.0f;

#pragma unroll
        for (int k16 = 0; k16 < HDIM; k16 += 16) {
            uint32_t bhi[4][2], blo[4][2];
#pragma unroll
            for (int nt = 0; nt < 4; nt++) {
                ldsm2(bhi[nt], khi_b + (nt*8*KSTR + k16)*2);
                ldsm2(blo[nt], klo_b + (nt*8*KSTR + k16)*2);
            }
#pragma unroll
            for (int mt = 0; mt < 2; mt++) {
                uint32_t ahi[4], alo[4];
                ldsm4(ahi, qhi_b + (mt*16*QSTR + k16)*2);
                ldsm4(alo, qlo_b + (mt*16*QSTR + k16)*2);
#pragma unroll
                for (int nt = 0; nt < 4; nt++) {
                    mma16816(sacc[mt][nt], ahi, bhi[nt]);
                    mma16816(sacc[mt][nt], alo, bhi[nt]);
                    mma16816(sacc[mt][nt], ahi, blo[nt]);
                }
            }
        }

        // ---- S -> smem with scale + causal mask ----
#pragma unroll
        for (int mt = 0; mt < 2; mt++) {
#pragma unroll
            for (int nt = 0; nt < 4; nt++) {
#pragma unroll
                for (int i = 0; i < 2; i++) {
#pragma unroll
                    for (int j = 0; j < 2; j++) {
                        int r = wm*32 + mt*16 + g + i*8;
                        int c = wn*32 + nt*8 + c2 + j;
                        float v = sacc[mt][nt][i*2 + j] * rnorm;
                        if (k0 + c > q0 + r) v = -10000.0f;
                        s_ss[r*SSTR + c] = v;
                    }
                }
            }
        }
        __syncthreads();

        // ---- row softmax + P split (one thread per row) ----
        if (tid < BQ) {
            int r = tid;
            float m_old = mrow[r];
            float mx = m_old;
#pragma unroll 8
            for (int c = 0; c < BT; c++) mx = fmaxf(mx, s_ss[r*SSTR + c]);
            float scl = expf(m_old - mx);
            float sum = 0.0f;
#pragma unroll 4
            for (int c = 0; c < BT; c++) {
                float p = expf(s_ss[r*SSTR + c] - mx);
                sum += p;
                __nv_bfloat16 h = __float2bfloat16(p);
                s_phi[r*PSTR + c] = h;
                s_plo[r*PSTR + c] = __float2bfloat16(p - __bfloat162float(h));
            }
            mrow[r] = mx;
            lrow[r] = lrow[r] * scl + sum;
            srow[r] = scl;
        }
        __syncthreads();

        // ---- rescale acc_o, then O += P·Vt (split-3) ----
#pragma unroll
        for (int mt = 0; mt < 2; mt++) {
#pragma unroll
            for (int i = 0; i < 2; i++) {
                float s_ = srow[wm*32 + mt*16 + g + i*8];
#pragma unroll
                for (int nt = 0; nt < 8; nt++) {
                    acc_o[mt][nt][i*2 + 0] *= s_;
                    acc_o[mt][nt][i*2 + 1] *= s_;
                }
            }
        }
#pragma unroll
        for (int k16 = 0; k16 < BT; k16 += 16) {
            uint32_t bvh[8][2], bvl[8][2];
#pragma unroll
            for (int nt = 0; nt < 8; nt++) {
                ldsm2(bvh[nt], vhi_b + (nt*8*VSTR + k16)*2);
                ldsm2(bvl[nt], vlo_b + (nt*8*VSTR + k16)*2);
            }
#pragma unroll
            for (int mt = 0; mt < 2; mt++) {
                uint32_t aph[4], apl[4];
                ldsm4(aph, phi_b + (mt*16*PSTR + k16)*2);
                ldsm4(apl, plo_b + (mt*16*PSTR + k16)*2);
#pragma unroll
                for (int nt = 0; nt < 8; nt++) {
                    mma16816(acc_o[mt][nt], aph, bvh[nt]);
                    mma16816(acc_o[mt][nt], apl, bvh[nt]);
                    mma16816(acc_o[mt][nt], aph, bvl[nt]);
                }
            }
        }
    }

    // ---- finalize: divide by l, write ctx [s,b,h*128+d] ----
    __syncthreads();
    const int b_idx = bh / NHEADS;
    const int h_idx = bh % NHEADS;
#pragma unroll
    for (int mt = 0; mt < 2; mt++) {
#pragma unroll
        for (int i = 0; i < 2; i++) {
            int r = wm*32 + mt*16 + g + i*8;
            float linv = 1.0f / lrow[r];
            int s_idx = q0 + r;
            float* dst = g_ctx + ((size_t)(s_idx*BATCH + b_idx))*HID + h_idx*HDIM + wn*64;
#pragma unroll
            for (int nt = 0; nt < 8; nt++) {
                dst[nt*8 + c2 + 0] = acc_o[mt][nt][i*2 + 0] * linv;
                dst[nt*8 + c2 + 1] = acc_o[mt][nt][i*2 + 1] * linv;
            }
        }
    }
}

// ---------------- tail bias ---------------------------------------------------
__global__ void tail_copy(const float* __restrict__ src, float* __restrict__ dst, int n) {
    int i = blockIdx.x * blockDim.x + threadIdx.x;
    if (i < n) dst[i] = src[i];
}

// ---------------- launch -------------------------------------------------------
extern "C" void kernel_launch(void* const* d_in, const int* in_sizes, int n_in,
                              void* d_out, int out_size)
{
    const float* hidden  = (const float*)d_in[0];
    const float* w_qkv   = (const float*)d_in[2];
    const float* b_qkv   = (const float*)d_in[3];
    const float* w_dense = (const float*)d_in[4];
    const float* b_dense = (const float*)d_in[5];
    float* out = (float*)d_out;

    void *pA, *pBq, *pBd, *pCtx, *pQ, *pK, *pV;
    cudaGetSymbolAddress(&pA,   g_Abuf);
    cudaGetSymbolAddress(&pBq,  g_Bq);
    cudaGetSymbolAddress(&pBd,  g_Bd);
    cudaGetSymbolAddress(&pCtx, g_ctx);
    cudaGetSymbolAddress(&pQ,   g_q);
    cudaGetSymbolAddress(&pK,   g_k);
    cudaGetSymbolAddress(&pV,   g_v);

    cudaFuncSetAttribute(attn_hmma, cudaFuncAttributeMaxDynamicSharedMemorySize, ATTN_SMEM);

    // 1) split-convert A (hidden) and B (w_qkv)
    conv_split<0><<<(TOK*HID + 255)/256, 256>>>(hidden, (__nv_bfloat16*)pA, TOK, HID);
    conv_split<1><<<(QKV_N*HID + 255)/256, 256>>>(w_qkv, (__nv_bfloat16*)pBq, QKV_N, HID);

    // 2) QKV projection (HMMA, bias + scatter epilogue)
    hmma_gemm<1><<<dim3(QKV_N/128, TOK/128), 256>>>(
        (const __nv_bfloat16*)pA, (const __nv_bfloat16*)pBq, b_qkv, nullptr,
        (float*)pQ, (float*)pK, (float*)pV, QKV_N);

    // 3) RoPE (emits bf16 hi/lo Q,K) + V transpose/split
    rope_table_kernel<<<(SEQ*64 + 255)/256, 256>>>();
    rope_apply_kernel<<<(NBH*SEQ*64 + 255)/256, 256>>>();
    v_transpose_split<<<dim3(SEQ/32, HDIM/32, NBH), dim3(32, 8)>>>();

    // 4) causal attention (HMMA split-3)
    attn_hmma<<<dim3(SEQ/BQ, NBH), 256, ATTN_SMEM>>>();

    // 5) split-convert ctx + w_dense, dense GEMM (HMMA)
    conv_split<0><<<(TOK*HID + 255)/256, 256>>>((const float*)pCtx, (__nv_bfloat16*)pA, TOK, HID);
    conv_split<1><<<(HID*HID + 255)/256, 256>>>(w_dense, (__nv_bfloat16*)pBd, HID, HID);
    hmma_gemm<2><<<dim3(HID/128, TOK/128), 256>>>(
        (const __nv_bfloat16*)pA, (const __nv_bfloat16*)pBd, nullptr, out,
        nullptr, nullptr, nullptr, HID);

    // 6) bias tail if harness flattens the (output, bias) tuple
    int extra = out_size - TOK*HID;
    if (extra > 0)
        tail_copy<<<(extra + 255)/256, 256>>>(b_dense, out + (size_t)TOK*HID, extra);
    (void)in_sizes; (void)n_in;
}

// round 6
// speedup vs baseline: 2.3960x; 1.0905x over previous
#include <cuda_runtime.h>
#include <cuda_bf16.h>
#include <math.h>
#include <stdint.h>

#define SEQ     2048
#define BATCH   2
#define HID     2048
#define NHEADS  16
#define HDIM    128
#define TOK     (SEQ*BATCH)     // 4096
#define QKV_N   (3*HID)         // 6144
#define K3      (3*HID)         // split-3 K' = 6144
#define NBH     (BATCH*NHEADS)  // 32

// ---------------- scratch (device globals; no runtime allocs allowed) -------
__device__ float g_q[NBH*SEQ*HDIM];
__device__ float g_k[NBH*SEQ*HDIM];
__device__ float g_v[NBH*SEQ*HDIM];
__device__ float g_cos[SEQ*64];
__device__ float g_sin[SEQ*64];
// bf16 split-3 operand buffers (GEMMs)
__device__ __align__(1024) __nv_bfloat16 g_Abuf[TOK*K3];
__device__ __align__(1024) __nv_bfloat16 g_Bq[QKV_N*K3];
__device__ __align__(1024) __nv_bfloat16 g_Bd[HID*K3];
// attention split operands
__device__ __align__(16) __nv_bfloat16 gq_hi[NBH*SEQ*HDIM];
__device__ __align__(16) __nv_bfloat16 gq_lo[NBH*SEQ*HDIM];
__device__ __align__(16) __nv_bfloat16 gk_hi[NBH*SEQ*HDIM];
__device__ __align__(16) __nv_bfloat16 gk_lo[NBH*SEQ*HDIM];
__device__ __align__(16) __nv_bfloat16 gvt_hi[NBH*HDIM*SEQ];   // [bh][d][s]
__device__ __align__(16) __nv_bfloat16 gvt_lo[NBH*HDIM*SEQ];

// ============================================================================
// PTX helpers (base-target-safe)
// ============================================================================
__device__ __forceinline__ uint32_t smem_u32(const void* p) {
    uint32_t a;
    asm("{ .reg .u64 t; cvta.to.shared.u64 t, %1; cvt.u32.u64 %0, t; }"
        : "=r"(a) : "l"(p));
    return a;
}
__device__ __forceinline__ void cpasync16(uint32_t s, const void* g) {
    asm volatile("cp.async.cg.shared.global [%0], [%1], 16;" :: "r"(s), "l"(g));
}
#define CP_COMMIT() asm volatile("cp.async.commit_group;" ::: "memory")
#define CP_WAIT(n)  asm volatile("cp.async.wait_group %0;" :: "n"(n) : "memory")

__device__ __forceinline__ void ldsm4(uint32_t* r, uint32_t a) {
    asm volatile("ldmatrix.sync.aligned.m8n8.x4.shared.b16 {%0,%1,%2,%3}, [%4];"
        : "=r"(r[0]), "=r"(r[1]), "=r"(r[2]), "=r"(r[3]) : "r"(a));
}
__device__ __forceinline__ void ldsm2(uint32_t* r, uint32_t a) {
    asm volatile("ldmatrix.sync.aligned.m8n8.x2.shared.b16 {%0,%1}, [%2];"
        : "=r"(r[0]), "=r"(r[1]) : "r"(a));
}
__device__ __forceinline__ void mma16816(float* c, const uint32_t* a, const uint32_t* b) {
    asm volatile("mma.sync.aligned.m16n8k16.row.col.f32.bf16.bf16.f32 "
        "{%0,%1,%2,%3}, {%4,%5,%6,%7}, {%8,%9}, {%0,%1,%2,%3};"
        : "+f"(c[0]), "+f"(c[1]), "+f"(c[2]), "+f"(c[3])
        : "r"(a[0]), "r"(a[1]), "r"(a[2]), "r"(a[3]), "r"(b[0]), "r"(b[1]));
}

// ============================================================================
// HMMA split-3 bf16 GEMM: 4-stage cp.async ring, ONE barrier per K-step.
// CTA tile 128x128x32, 256 thr (8 warps 2x4).
// MODE 1: QKV — add bias + scatter to q/k/v.   MODE 2: plain C store.
// ============================================================================
#define BK 32
#define ASTR 40
#define TILE_B16 (128*ASTR)            // 5120 bf16 per operand tile
#define STAGE_B16 (2*TILE_B16)         // A + B
#define STAGE_BYTES (STAGE_B16*2)      // 20480
#define GSTAGES 4
#define GEMM_SMEM (GSTAGES*STAGE_BYTES)  // 81920

template<int MODE>
__global__ void __launch_bounds__(256, 2)
hmma_gemm(const __nv_bfloat16* __restrict__ Ag, const __nv_bfloat16* __restrict__ Bg,
          const float* __restrict__ bias, float* __restrict__ C,
          float* __restrict__ q_out, float* __restrict__ k_out, float* __restrict__ v_out,
          int N)
{
    extern __shared__ __align__(16) __nv_bfloat16 smbuf[];

    const int tid  = threadIdx.x;
    const int lane = tid & 31;
    const int warp = tid >> 5;
    const int wm = warp >> 2;
    const int wn = warp & 3;
    const int m0 = blockIdx.y * 128;
    const int n0 = blockIdx.x * 128;

    const uint32_t smb = smem_u32(smbuf);
    const int cr = tid >> 2;
    const int ccn = tid & 3;
    const int KT = K3 / BK;            // 192

    auto prefetch = [&](int kt, int slot) {
        uint32_t base = smb + slot * STAGE_BYTES;
#pragma unroll
        for (int h = 0; h < 2; h++) {
            int r = cr + h * 64;
            cpasync16(base + (r * ASTR + ccn * 8) * 2,
                      Ag + (size_t)(m0 + r) * K3 + kt * BK + ccn * 8);
            cpasync16(base + TILE_B16*2 + (r * ASTR + ccn * 8) * 2,
                      Bg + (size_t)(n0 + r) * K3 + kt * BK + ccn * 8);
        }
    };

    float acc[4][4][4];
#pragma unroll
    for (int i = 0; i < 4; i++)
#pragma unroll
        for (int j = 0; j < 4; j++)
#pragma unroll
            for (int e = 0; e < 4; e++) acc[i][j][e] = 0.0f;

    const int l16 = lane & 15;
    const uint32_t a_off = (((wm * 64 + l16) * ASTR) + ((lane >> 4) * 8)) * 2;
    const uint32_t b_off = (((wn * 32 + (l16 & 7)) * ASTR) + ((l16 >> 3) * 8)) * 2;

    prefetch(0, 0); CP_COMMIT();
    prefetch(1, 1); CP_COMMIT();
    prefetch(2, 2); CP_COMMIT();

    for (int kt = 0; kt < KT; kt++) {
        CP_WAIT(2);               // stage kt resident (my share)
        __syncthreads();          // everyone's share visible; prev reads retired
        int pf = kt + 3;
        if (pf < KT) prefetch(pf, pf & 3);
        CP_COMMIT();              // unconditional: keeps group accounting uniform

        uint32_t abase = smb + (kt & 3) * STAGE_BYTES + a_off;
        uint32_t bbase = smb + (kt & 3) * STAGE_BYTES + TILE_B16*2 + b_off;

#pragma unroll
        for (int k16 = 0; k16 < BK; k16 += 16) {
            uint32_t bfr[4][2];
#pragma unroll
            for (int nt = 0; nt < 4; nt++)
                ldsm2(bfr[nt], bbase + (nt * 8 * ASTR + k16) * 2);
#pragma unroll
            for (int mt = 0; mt < 4; mt++) {
                uint32_t afr[4];
                ldsm4(afr, abase + (mt * 16 * ASTR + k16) * 2);
#pragma unroll
                for (int nt = 0; nt < 4; nt++)
                    mma16816(acc[mt][nt], afr, bfr[nt]);
            }
        }
    }

    const int g  = lane >> 2;
    const int c2 = (lane & 3) * 2;
#pragma unroll
    for (int mt = 0; mt < 4; mt++) {
#pragma unroll
        for (int nt = 0; nt < 4; nt++) {
#pragma unroll
            for (int i = 0; i < 2; i++) {
#pragma unroll
                for (int j = 0; j < 2; j++) {
                    int m = m0 + wm * 64 + mt * 16 + g + i * 8;
                    int n = n0 + wn * 32 + nt * 8 + c2 + j;
                    float v = acc[mt][nt][i * 2 + j];
                    if (MODE == 1) {
                        v += bias[n];
                        int head = n / (3 * HDIM);
                        int r3   = n % (3 * HDIM);
                        int part = r3 / HDIM;
                        int d    = r3 % HDIM;
                        int off  = (((m & 1) * NHEADS + head) * SEQ + (m >> 1)) * HDIM + d;
                        if      (part == 0) q_out[off] = v;
                        else if (part == 1) k_out[off] = v;
                        else                v_out[off] = v;
                    } else {
                        C[(size_t)m * N + n] = v;
                    }
                }
            }
        }
    }
}

// ---------------- split-3 conversion (GEMM operands) -------------------------
template<int PAT>
__global__ void conv_split(const float* __restrict__ src,
                           __nv_bfloat16* __restrict__ dst, int R, int K)
{
    int idx = blockIdx.x * blockDim.x + threadIdx.x;
    if (idx >= R * K) return;
    int row = idx / K, col = idx - row * K;
    float x = src[idx];
    __nv_bfloat16 h = __float2bfloat16(x);
    __nv_bfloat16 l = __float2bfloat16(x - __bfloat162float(h));
    size_t base = (size_t)row * (3*K) + col;
    if (PAT == 0) { dst[base] = h; dst[base + K] = l; dst[base + 2*K] = h; }
    else          { dst[base] = h; dst[base + K] = h; dst[base + 2*K] = l; }
}

// ---------------- RoPE tables + apply ----------------------------------------
__global__ void rope_table_kernel() {
    __shared__ float invf[64];
    if (threadIdx.x < 64)
        invf[threadIdx.x] = (float)pow(10000.0, -((double)threadIdx.x) / 64.0);
    __syncthreads();
    int idx = blockIdx.x * blockDim.x + threadIdx.x;
    if (idx >= SEQ * 64) return;
    int s = idx >> 6;
    int i = idx & 63;
    float theta = (float)s * invf[i];
    g_cos[idx] = cosf(theta);     // accurate f32 path (not MUFU __cosf)
    g_sin[idx] = sinf(theta);
}

__device__ __forceinline__ void split_store(__nv_bfloat16* hi, __nv_bfloat16* lo,
                                            int off, float x) {
    __nv_bfloat16 h = __float2bfloat16(x);
    hi[off] = h;
    lo[off] = __float2bfloat16(x - __bfloat162float(h));
}

__global__ void rope_apply_kernel() {
    int idx = blockIdx.x * blockDim.x + threadIdx.x;
    int total = NBH*SEQ*64;
    if (idx >= total) return;
    int i = idx & 63;
    int rowid = idx >> 6;
    int s = rowid & (SEQ - 1);
    float c  = g_cos[s*64 + i];
    float sn = g_sin[s*64 + i];
    int base = rowid * HDIM;
    float q1 = g_q[base + i], q2 = g_q[base + 64 + i];
    float k1 = g_k[base + i], k2 = g_k[base + 64 + i];
    split_store(gq_hi, gq_lo, base + i,      q1*c - q2*sn);
    split_store(gq_hi, gq_lo, base + 64 + i, q2*c + q1*sn);
    split_store(gk_hi, gk_lo, base + i,      k1*c - k2*sn);
    split_store(gk_hi, gk_lo, base + 64 + i, k2*c + k1*sn);
}

// ---------------- V transpose + split: g_v[bh][s][d] -> gvt[bh][d][s] --------
__global__ void v_transpose_split() {
    __shared__ float t[32][33];
    int bh = blockIdx.z;
    int s0 = blockIdx.x * 32, d0 = blockIdx.y * 32;
    int tx = threadIdx.x, ty = threadIdx.y;   // 32 x 8
#pragma unroll
    for (int i = 0; i < 32; i += 8)
        t[ty + i][tx] = g_v[((size_t)bh*SEQ + s0 + ty + i) * HDIM + d0 + tx];
    __syncthreads();
#pragma unroll
    for (int i = 0; i < 32; i += 8) {
        float x = t[tx][ty + i];
        size_t off = ((size_t)bh*HDIM + d0 + ty + i) * SEQ + s0 + tx;
        __nv_bfloat16 h = __float2bfloat16(x);
        gvt_hi[off] = h;
        gvt_lo[off] = __float2bfloat16(x - __bfloat162float(h));
    }
}

// ============================================================================
// HMMA causal flash attention, split-3 on QK^T and PV.
// CTA: 128 q-rows x one bh. 256 threads (8 warps, 4x2). Key tiles of 64.
// Softmax: 2 threads per row, __expf. Epilogue writes dense-GEMM A' directly.
// ============================================================================
#define BQ 128
#define BT 64
#define QSTR 136
#define KSTR 136
#define VSTR 72
#define SSTR 68
#define PSTR 72

#define OFF_QHI 0
#define SZ_Q    (BQ*QSTR*2)
#define OFF_QLO (OFF_QHI + SZ_Q)
#define OFF_KHI (OFF_QLO + SZ_Q)
#define SZ_K    (BT*KSTR*2)
#define OFF_KLO (OFF_KHI + SZ_K)
#define OFF_VHI (OFF_KLO + SZ_K)
#define SZ_V    (HDIM*VSTR*2)
#define OFF_VLO (OFF_VHI + SZ_V)
#define OFF_SS  (OFF_VLO + SZ_V)
#define SZ_SS   (BQ*SSTR*4)
#define OFF_PHI (OFF_SS + SZ_SS)
#define SZ_P    (BQ*PSTR*2)
#define OFF_PLO (OFF_PHI + SZ_P)
#define OFF_MR  (OFF_PLO + SZ_P)
#define OFF_LR  (OFF_MR + BQ*4)
#define OFF_SC  (OFF_LR + BQ*4)
#define ATTN_SMEM (OFF_SC + BQ*4)

__global__ void __launch_bounds__(256, 1) attn_hmma(__nv_bfloat16* __restrict__ Aout) {
    extern __shared__ char smem[];
    const uint32_t sb = smem_u32(smem);

    const int tid  = threadIdx.x;
    const int lane = tid & 31;
    const int warp = tid >> 5;
    const int wm = warp >> 1;              // 0..3 (32 q-rows each)
    const int wn = warp & 1;               // 0..1
    const int qt = gridDim.x - 1 - blockIdx.x;   // heavy tiles first
    const int bh = blockIdx.y;
    const int q0 = qt * BQ;

    const int l16 = lane & 15;
    const int g   = lane >> 2;
    const int c2  = (lane & 3) * 2;

    __nv_bfloat16* s_qhi = (__nv_bfloat16*)(smem + OFF_QHI);
    __nv_bfloat16* s_qlo = (__nv_bfloat16*)(smem + OFF_QLO);
    __nv_bfloat16* s_khi = (__nv_bfloat16*)(smem + OFF_KHI);
    __nv_bfloat16* s_klo = (__nv_bfloat16*)(smem + OFF_KLO);
    __nv_bfloat16* s_vhi = (__nv_bfloat16*)(smem + OFF_VHI);
    __nv_bfloat16* s_vlo = (__nv_bfloat16*)(smem + OFF_VLO);
    float*         s_ss  = (float*)(smem + OFF_SS);
    __nv_bfloat16* s_phi = (__nv_bfloat16*)(smem + OFF_PHI);
    __nv_bfloat16* s_plo = (__nv_bfloat16*)(smem + OFF_PLO);
    float*         mrow  = (float*)(smem + OFF_MR);
    float*         lrow  = (float*)(smem + OFF_LR);
    float*         srow  = (float*)(smem + OFF_SC);

    // ---- load Q tile (hi & lo), once ----
    {
        const __nv_bfloat16* qh = gq_hi + ((size_t)bh*SEQ + q0) * HDIM;
        const __nv_bfloat16* ql = gq_lo + ((size_t)bh*SEQ + q0) * HDIM;
#pragma unroll
        for (int it = 0; it < 8; it++) {
            int t = tid + it*256;
            int row = t >> 4, cc = t & 15;
            *(uint4*)(s_qhi + row*QSTR + cc*8) = *(const uint4*)(qh + row*HDIM + cc*8);
        }
#pragma unroll
        for (int it = 0; it < 8; it++) {
            int t = tid + it*256;
            int row = t >> 4, cc = t & 15;
            *(uint4*)(s_qlo + row*QSTR + cc*8) = *(const uint4*)(ql + row*HDIM + cc*8);
        }
    }
    if (tid < BQ) { mrow[tid] = -1e30f; lrow[tid] = 0.0f; }

    float acc_o[2][8][4];
#pragma unroll
    for (int mt = 0; mt < 2; mt++)
#pragma unroll
        for (int nt = 0; nt < 8; nt++)
#pragma unroll
            for (int e = 0; e < 4; e++) acc_o[mt][nt][e] = 0.0f;

    const float rnorm = 0.088388347648318447f;   // 1/sqrt(128)

    const uint32_t qhi_b = sb + OFF_QHI + (((wm*32 + l16)*QSTR) + (lane>>4)*8)*2;
    const uint32_t qlo_b = sb + OFF_QLO + (((wm*32 + l16)*QSTR) + (lane>>4)*8)*2;
    const uint32_t khi_b = sb + OFF_KHI + (((wn*32 + (l16&7))*KSTR) + (l16>>3)*8)*2;
    const uint32_t klo_b = sb + OFF_KLO + (((wn*32 + (l16&7))*KSTR) + (l16>>3)*8)*2;
    const uint32_t phi_b = sb + OFF_PHI + (((wm*32 + l16)*PSTR) + (lane>>4)*8)*2;
    const uint32_t plo_b = sb + OFF_PLO + (((wm*32 + l16)*PSTR) + (lane>>4)*8)*2;
    const uint32_t vhi_b = sb + OFF_VHI + (((wn*64 + (l16&7))*VSTR) + (l16>>3)*8)*2;
    const uint32_t vlo_b = sb + OFF_VLO + (((wn*64 + (l16&7))*VSTR) + (l16>>3)*8)*2;

    const int ntiles = 2*qt + 2;
    for (int kt = 0; kt < ntiles; kt++) {
        const int k0 = kt * BT;
        __syncthreads();

        // ---- load K tile (hi,lo) and Vt tile (hi,lo) ----
        {
            const __nv_bfloat16* kh = gk_hi + ((size_t)bh*SEQ + k0) * HDIM;
            const __nv_bfloat16* kl = gk_lo + ((size_t)bh*SEQ + k0) * HDIM;
#pragma unroll
            for (int it = 0; it < 4; it++) {
                int t = tid + it*256;
                int row = t >> 4, cc = t & 15;
                *(uint4*)(s_khi + row*KSTR + cc*8) = *(const uint4*)(kh + row*HDIM + cc*8);
            }
#pragma unroll
            for (int it = 0; it < 4; it++) {
                int t = tid + it*256;
                int row = t >> 4, cc = t & 15;
                *(uint4*)(s_klo + row*KSTR + cc*8) = *(const uint4*)(kl + row*HDIM + cc*8);
            }
            const __nv_bfloat16* vh = gvt_hi + (size_t)bh*HDIM*SEQ + k0;
            const __nv_bfloat16* vl = gvt_lo + (size_t)bh*HDIM*SEQ + k0;
#pragma unroll
            for (int it = 0; it < 4; it++) {
                int t = tid + it*256;
                int d = t >> 3, cc = t & 7;
                *(uint4*)(s_vhi + d*VSTR + cc*8) = *(const uint4*)(vh + (size_t)d*SEQ + cc*8);
            }
#pragma unroll
            for (int it = 0; it < 4; it++) {
                int t = tid + it*256;
                int d = t >> 3, cc = t & 7;
                *(uint4*)(s_vlo + d*VSTR + cc*8) = *(const uint4*)(vl + (size_t)d*SEQ + cc*8);
            }
        }
        __syncthreads();

        // ---- S = Q K^T (split-3) ----
        float sacc[2][4][4];
#pragma unroll
        for (int mt = 0; mt < 2; mt++)
#pragma unroll
            for (int nt = 0; nt < 4; nt++)
#pragma unroll
                for (int e = 0; e < 4; e++) sacc[mt][nt][e] = 0.0f;

#pragma unroll
        for (int k16 = 0; k16 < HDIM; k16 += 16) {
            uint32_t bhi[4][2], blo[4][2];
#pragma unroll
            for (int nt = 0; nt < 4; nt++) {
                ldsm2(bhi[nt], khi_b + (nt*8*KSTR + k16)*2);
                ldsm2(blo[nt], klo_b + (nt*8*KSTR + k16)*2);
            }
#pragma unroll
            for (int mt = 0; mt < 2; mt++) {
                uint32_t ahi[4], alo[4];
                ldsm4(ahi, qhi_b + (mt*16*QSTR + k16)*2);
                ldsm4(alo, qlo_b + (mt*16*QSTR + k16)*2);
#pragma unroll
                for (int nt = 0; nt < 4; nt++) {
                    mma16816(sacc[mt][nt], ahi, bhi[nt]);
                    mma16816(sacc[mt][nt], alo, bhi[nt]);
                    mma16816(sacc[mt][nt], ahi, blo[nt]);
                }
            }
        }

        // ---- S -> smem with scale + causal mask ----
#pragma unroll
        for (int mt = 0; mt < 2; mt++) {
#pragma unroll
            for (int nt = 0; nt < 4; nt++) {
#pragma unroll
                for (int i = 0; i < 2; i++) {
#pragma unroll
                    for (int j = 0; j < 2; j++) {
                        int r = wm*32 + mt*16 + g + i*8;
                        int c = wn*32 + nt*8 + c2 + j;
                        float v = sacc[mt][nt][i*2 + j] * rnorm;
                        if (k0 + c > q0 + r) v = -10000.0f;
                        s_ss[r*SSTR + c] = v;
                    }
                }
            }
        }
        __syncthreads();

        // ---- row softmax + P split: 2 threads per row, __expf ----
        {
            int r  = tid >> 1;
            int hf = tid & 1;
            float* row = s_ss + r*SSTR + hf*32;
            float m_old = mrow[r];
            float mx = m_old;
#pragma unroll 8
            for (int c = 0; c < 32; c++) mx = fmaxf(mx, row[c]);
            mx = fmaxf(mx, __shfl_xor_sync(0xFFFFFFFFu, mx, 1));
            float sum = 0.0f;
            __nv_bfloat16* ph = s_phi + r*PSTR + hf*32;
            __nv_bfloat16* pl = s_plo + r*PSTR + hf*32;
#pragma unroll 8
            for (int c = 0; c < 32; c++) {
                float p = __expf(row[c] - mx);
                sum += p;
                __nv_bfloat16 h = __float2bfloat16(p);
                ph[c] = h;
                pl[c] = __float2bfloat16(p - __bfloat162float(h));
            }
            sum += __shfl_xor_sync(0xFFFFFFFFu, sum, 1);
            if (hf == 0) {
                float scl = __expf(m_old - mx);
                mrow[r] = mx;
                lrow[r] = lrow[r] * scl + sum;
                srow[r] = scl;
            }
        }
        __syncthreads();

        // ---- rescale acc_o, then O += P·Vt (split-3) ----
#pragma unroll
        for (int mt = 0; mt < 2; mt++) {
#pragma unroll
            for (int i = 0; i < 2; i++) {
                float s_ = srow[wm*32 + mt*16 + g + i*8];
#pragma unroll
                for (int nt = 0; nt < 8; nt++) {
                    acc_o[mt][nt][i*2 + 0] *= s_;
                    acc_o[mt][nt][i*2 + 1] *= s_;
                }
            }
        }
#pragma unroll
        for (int k16 = 0; k16 < BT; k16 += 16) {
            uint32_t bvh[8][2], bvl[8][2];
#pragma unroll
            for (int nt = 0; nt < 8; nt++) {
                ldsm2(bvh[nt], vhi_b + (nt*8*VSTR + k16)*2);
                ldsm2(bvl[nt], vlo_b + (nt*8*VSTR + k16)*2);
            }
#pragma unroll
            for (int mt = 0; mt < 2; mt++) {
                uint32_t aph[4], apl[4];
                ldsm4(aph, phi_b + (mt*16*PSTR + k16)*2);
                ldsm4(apl, plo_b + (mt*16*PSTR + k16)*2);
#pragma unroll
                for (int nt = 0; nt < 8; nt++) {
                    mma16816(acc_o[mt][nt], aph, bvh[nt]);
                    mma16816(acc_o[mt][nt], apl, bvh[nt]);
                    mma16816(acc_o[mt][nt], aph, bvl[nt]);
                }
            }
        }
    }

    // ---- finalize: divide by l, write dense-GEMM A' (hi|lo|hi) directly ----
    __syncthreads();
    const int b_idx = bh / NHEADS;
    const int h_idx = bh % NHEADS;
#pragma unroll
    for (int mt = 0; mt < 2; mt++) {
#pragma unroll
        for (int i = 0; i < 2; i++) {
            int r = wm*32 + mt*16 + g + i*8;
            float linv = 1.0f / lrow[r];
            int s_idx = q0 + r;
            size_t tok = (size_t)(s_idx*BATCH + b_idx);
            __nv_bfloat16* dst = Aout + tok*K3 + h_idx*HDIM + wn*64;
#pragma unroll
            for (int nt = 0; nt < 8; nt++) {
#pragma unroll
                for (int j = 0; j < 2; j++) {
                    float v = acc_o[mt][nt][i*2 + j] * linv;
                    __nv_bfloat16 h = __float2bfloat16(v);
                    __nv_bfloat16 l = __float2bfloat16(v - __bfloat162float(h));
                    int cc = nt*8 + c2 + j;
                    dst[cc]         = h;
                    dst[HID + cc]   = l;
                    dst[2*HID + cc] = h;
                }
            }
        }
    }
}

// ---------------- tail bias ---------------------------------------------------
__global__ void tail_copy(const float* __restrict__ src, float* __restrict__ dst, int n) {
    int i = blockIdx.x * blockDim.x + threadIdx.x;
    if (i < n) dst[i] = src[i];
}

// ---------------- launch -------------------------------------------------------
extern "C" void kernel_launch(void* const* d_in, const int* in_sizes, int n_in,
                              void* d_out, int out_size)
{
    const float* hidden  = (const float*)d_in[0];
    const float* w_qkv   = (const float*)d_in[2];
    const float* b_qkv   = (const float*)d_in[3];
    const float* w_dense = (const float*)d_in[4];
    const float* b_dense = (const float*)d_in[5];
    float* out = (float*)d_out;

    void *pA, *pBq, *pBd, *pQ, *pK, *pV;
    cudaGetSymbolAddress(&pA,   g_Abuf);
    cudaGetSymbolAddress(&pBq,  g_Bq);
    cudaGetSymbolAddress(&pBd,  g_Bd);
    cudaGetSymbolAddress(&pQ,   g_q);
    cudaGetSymbolAddress(&pK,   g_k);
    cudaGetSymbolAddress(&pV,   g_v);

    cudaFuncSetAttribute(hmma_gemm<1>, cudaFuncAttributeMaxDynamicSharedMemorySize, GEMM_SMEM);
    cudaFuncSetAttribute(hmma_gemm<2>, cudaFuncAttributeMaxDynamicSharedMemorySize, GEMM_SMEM);
    cudaFuncSetAttribute(attn_hmma, cudaFuncAttributeMaxDynamicSharedMemorySize, ATTN_SMEM);

    // 1) split-convert A (hidden) and B (w_qkv)
    conv_split<0><<<(TOK*HID + 255)/256, 256>>>(hidden, (__nv_bfloat16*)pA, TOK, HID);
    conv_split<1><<<(QKV_N*HID + 255)/256, 256>>>(w_qkv, (__nv_bfloat16*)pBq, QKV_N, HID);

    // 2) QKV projection (HMMA, bias + scatter epilogue)
    hmma_gemm<1><<<dim3(QKV_N/128, TOK/128), 256, GEMM_SMEM>>>(
        (const __nv_bfloat16*)pA, (const __nv_bfloat16*)pBq, b_qkv, nullptr,
        (float*)pQ, (float*)pK, (float*)pV, QKV_N);

    // 3) RoPE (emits bf16 hi/lo Q,K) + V transpose/split
    rope_table_kernel<<<(SEQ*64 + 255)/256, 256>>>();
    rope_apply_kernel<<<(NBH*SEQ*64 + 255)/256, 256>>>();
    v_transpose_split<<<dim3(SEQ/32, HDIM/32, NBH), dim3(32, 8)>>>();

    // 4) causal attention (HMMA split-3); epilogue writes dense A' into g_Abuf
    attn_hmma<<<dim3(SEQ/BQ, NBH), 256, ATTN_SMEM>>>((__nv_bfloat16*)pA);

    // 5) w_dense split + dense GEMM (HMMA)
    conv_split<1><<<(HID*HID + 255)/256, 256>>>(w_dense, (__nv_bfloat16*)pBd, HID, HID);
    hmma_gemm<2><<<dim3(HID/128, TOK/128), 256, GEMM_SMEM>>>(
        (const __nv_bfloat16*)pA, (const __nv_bfloat16*)pBd, nullptr, out,
        nullptr, nullptr, nullptr, HID);

    // 6) bias tail if harness flattens the (output, bias) tuple
    int extra = out_size - TOK*HID;
    if (extra > 0)
        tail_copy<<<(extra + 255)/256, 256>>>(b_dense, out + (size_t)TOK*HID, extra);
    (void)in_sizes; (void)n_in;
}

// round 7
// speedup vs baseline: 2.4796x; 1.0349x over previous
#include <cuda_runtime.h>
#include <cuda_bf16.h>
#include <math.h>
#include <stdint.h>

#define SEQ     2048
#define BATCH   2
#define HID     2048
#define NHEADS  16
#define HDIM    128
#define TOK     (SEQ*BATCH)     // 4096
#define QKV_N   (3*HID)         // 6144
#define K3      (3*HID)         // split-3 K' = 6144
#define NBH     (BATCH*NHEADS)  // 32

// ---------------- scratch (device globals; no runtime allocs allowed) -------
__device__ float g_q[NBH*SEQ*HDIM];
__device__ float g_k[NBH*SEQ*HDIM];
__device__ float g_v[NBH*SEQ*HDIM];
__device__ float g_cos[SEQ*64];
__device__ float g_sin[SEQ*64];
// bf16 split-3 operand buffers (GEMMs)
__device__ __align__(1024) __nv_bfloat16 g_Abuf[TOK*K3];
__device__ __align__(1024) __nv_bfloat16 g_Bq[QKV_N*K3];
__device__ __align__(1024) __nv_bfloat16 g_Bd[HID*K3];
// attention split operands
__device__ __align__(16) __nv_bfloat16 gq_hi[NBH*SEQ*HDIM];
__device__ __align__(16) __nv_bfloat16 gq_lo[NBH*SEQ*HDIM];
__device__ __align__(16) __nv_bfloat16 gk_hi[NBH*SEQ*HDIM];
__device__ __align__(16) __nv_bfloat16 gk_lo[NBH*SEQ*HDIM];
__device__ __align__(16) __nv_bfloat16 gvt_hi[NBH*HDIM*SEQ];   // [bh][d][s]
__device__ __align__(16) __nv_bfloat16 gvt_lo[NBH*HDIM*SEQ];

// ============================================================================
// PTX helpers (base-target-safe)
// ============================================================================
__device__ __forceinline__ uint32_t smem_u32(const void* p) {
    uint32_t a;
    asm("{ .reg .u64 t; cvta.to.shared.u64 t, %1; cvt.u32.u64 %0, t; }"
        : "=r"(a) : "l"(p));
    return a;
}
__device__ __forceinline__ void cpasync16(uint32_t s, const void* g) {
    asm volatile("cp.async.cg.shared.global [%0], [%1], 16;" :: "r"(s), "l"(g));
}
#define CP_COMMIT() asm volatile("cp.async.commit_group;" ::: "memory")
#define CP_WAIT(n)  asm volatile("cp.async.wait_group %0;" :: "n"(n) : "memory")

__device__ __forceinline__ void ldsm4(uint32_t* r, uint32_t a) {
    asm volatile("ldmatrix.sync.aligned.m8n8.x4.shared.b16 {%0,%1,%2,%3}, [%4];"
        : "=r"(r[0]), "=r"(r[1]), "=r"(r[2]), "=r"(r[3]) : "r"(a));
}
__device__ __forceinline__ void ldsm2(uint32_t* r, uint32_t a) {
    asm volatile("ldmatrix.sync.aligned.m8n8.x2.shared.b16 {%0,%1}, [%2];"
        : "=r"(r[0]), "=r"(r[1]) : "r"(a));
}
__device__ __forceinline__ void mma16816(float* c, const uint32_t* a, const uint32_t* b) {
    asm volatile("mma.sync.aligned.m16n8k16.row.col.f32.bf16.bf16.f32 "
        "{%0,%1,%2,%3}, {%4,%5,%6,%7}, {%8,%9}, {%0,%1,%2,%3};"
        : "+f"(c[0]), "+f"(c[1]), "+f"(c[2]), "+f"(c[3])
        : "r"(a[0]), "r"(a[1]), "r"(a[2]), "r"(a[3]), "r"(b[0]), "r"(b[1]));
}

// ============================================================================
// HMMA split-3 bf16 GEMM: 4-stage cp.async ring, ONE barrier per K-step.
// ============================================================================
#define BK 32
#define ASTR 40
#define TILE_B16 (128*ASTR)
#define STAGE_B16 (2*TILE_B16)
#define STAGE_BYTES (STAGE_B16*2)
#define GSTAGES 4
#define GEMM_SMEM (GSTAGES*STAGE_BYTES)

template<int MODE>
__global__ void __launch_bounds__(256, 2)
hmma_gemm(const __nv_bfloat16* __restrict__ Ag, const __nv_bfloat16* __restrict__ Bg,
          const float* __restrict__ bias, float* __restrict__ C,
          float* __restrict__ q_out, float* __restrict__ k_out, float* __restrict__ v_out,
          int N)
{
    extern __shared__ __align__(16) __nv_bfloat16 smbuf[];

    const int tid  = threadIdx.x;
    const int lane = tid & 31;
    const int warp = tid >> 5;
    const int wm = warp >> 2;
    const int wn = warp & 3;
    const int m0 = blockIdx.y * 128;
    const int n0 = blockIdx.x * 128;

    const uint32_t smb = smem_u32(smbuf);
    const int cr = tid >> 2;
    const int ccn = tid & 3;
    const int KT = K3 / BK;

    auto prefetch = [&](int kt, int slot) {
        uint32_t base = smb + slot * STAGE_BYTES;
#pragma unroll
        for (int h = 0; h < 2; h++) {
            int r = cr + h * 64;
            cpasync16(base + (r * ASTR + ccn * 8) * 2,
                      Ag + (size_t)(m0 + r) * K3 + kt * BK + ccn * 8);
            cpasync16(base + TILE_B16*2 + (r * ASTR + ccn * 8) * 2,
                      Bg + (size_t)(n0 + r) * K3 + kt * BK + ccn * 8);
        }
    };

    float acc[4][4][4];
#pragma unroll
    for (int i = 0; i < 4; i++)
#pragma unroll
        for (int j = 0; j < 4; j++)
#pragma unroll
            for (int e = 0; e < 4; e++) acc[i][j][e] = 0.0f;

    const int l16 = lane & 15;
    const uint32_t a_off = (((wm * 64 + l16) * ASTR) + ((lane >> 4) * 8)) * 2;
    const uint32_t b_off = (((wn * 32 + (l16 & 7)) * ASTR) + ((l16 >> 3) * 8)) * 2;

    prefetch(0, 0); CP_COMMIT();
    prefetch(1, 1); CP_COMMIT();
    prefetch(2, 2); CP_COMMIT();

    for (int kt = 0; kt < KT; kt++) {
        CP_WAIT(2);
        __syncthreads();
        int pf = kt + 3;
        if (pf < KT) prefetch(pf, pf & 3);
        CP_COMMIT();

        uint32_t abase = smb + (kt & 3) * STAGE_BYTES + a_off;
        uint32_t bbase = smb + (kt & 3) * STAGE_BYTES + TILE_B16*2 + b_off;

#pragma unroll
        for (int k16 = 0; k16 < BK; k16 += 16) {
            uint32_t bfr[4][2];
#pragma unroll
            for (int nt = 0; nt < 4; nt++)
                ldsm2(bfr[nt], bbase + (nt * 8 * ASTR + k16) * 2);
#pragma unroll
            for (int mt = 0; mt < 4; mt++) {
                uint32_t afr[4];
                ldsm4(afr, abase + (mt * 16 * ASTR + k16) * 2);
#pragma unroll
                for (int nt = 0; nt < 4; nt++)
                    mma16816(acc[mt][nt], afr, bfr[nt]);
            }
        }
    }

    const int g  = lane >> 2;
    const int c2 = (lane & 3) * 2;
#pragma unroll
    for (int mt = 0; mt < 4; mt++) {
#pragma unroll
        for (int nt = 0; nt < 4; nt++) {
#pragma unroll
            for (int i = 0; i < 2; i++) {
#pragma unroll
                for (int j = 0; j < 2; j++) {
                    int m = m0 + wm * 64 + mt * 16 + g + i * 8;
                    int n = n0 + wn * 32 + nt * 8 + c2 + j;
                    float v = acc[mt][nt][i * 2 + j];
                    if (MODE == 1) {
                        v += bias[n];
                        int head = n / (3 * HDIM);
                        int r3   = n % (3 * HDIM);
                        int part = r3 / HDIM;
                        int d    = r3 % HDIM;
                        int off  = (((m & 1) * NHEADS + head) * SEQ + (m >> 1)) * HDIM + d;
                        if      (part == 0) q_out[off] = v;
                        else if (part == 1) k_out[off] = v;
                        else                v_out[off] = v;
                    } else {
                        C[(size_t)m * N + n] = v;
                    }
                }
            }
        }
    }
}

// ---------------- split-3 conversion (GEMM operands) -------------------------
template<int PAT>
__global__ void conv_split(const float* __restrict__ src,
                           __nv_bfloat16* __restrict__ dst, int R, int K)
{
    int idx = blockIdx.x * blockDim.x + threadIdx.x;
    if (idx >= R * K) return;
    int row = idx / K, col = idx - row * K;
    float x = src[idx];
    __nv_bfloat16 h = __float2bfloat16(x);
    __nv_bfloat16 l = __float2bfloat16(x - __bfloat162float(h));
    size_t base = (size_t)row * (3*K) + col;
    if (PAT == 0) { dst[base] = h; dst[base + K] = l; dst[base + 2*K] = h; }
    else          { dst[base] = h; dst[base + K] = h; dst[base + 2*K] = l; }
}

// ---------------- RoPE tables + apply ----------------------------------------
__global__ void rope_table_kernel() {
    __shared__ float invf[64];
    if (threadIdx.x < 64)
        invf[threadIdx.x] = (float)pow(10000.0, -((double)threadIdx.x) / 64.0);
    __syncthreads();
    int idx = blockIdx.x * blockDim.x + threadIdx.x;
    if (idx >= SEQ * 64) return;
    int s = idx >> 6;
    int i = idx & 63;
    float theta = (float)s * invf[i];
    g_cos[idx] = cosf(theta);
    g_sin[idx] = sinf(theta);
}

__device__ __forceinline__ void split_store(__nv_bfloat16* hi, __nv_bfloat16* lo,
                                            int off, float x) {
    __nv_bfloat16 h = __float2bfloat16(x);
    hi[off] = h;
    lo[off] = __float2bfloat16(x - __bfloat162float(h));
}

__global__ void rope_apply_kernel() {
    int idx = blockIdx.x * blockDim.x + threadIdx.x;
    int total = NBH*SEQ*64;
    if (idx >= total) return;
    int i = idx & 63;
    int rowid = idx >> 6;
    int s = rowid & (SEQ - 1);
    float c  = g_cos[s*64 + i];
    float sn = g_sin[s*64 + i];
    int base = rowid * HDIM;
    float q1 = g_q[base + i], q2 = g_q[base + 64 + i];
    float k1 = g_k[base + i], k2 = g_k[base + 64 + i];
    split_store(gq_hi, gq_lo, base + i,      q1*c - q2*sn);
    split_store(gq_hi, gq_lo, base + 64 + i, q2*c + q1*sn);
    split_store(gk_hi, gk_lo, base + i,      k1*c - k2*sn);
    split_store(gk_hi, gk_lo, base + 64 + i, k2*c + k1*sn);
}

// ---------------- V transpose + split: g_v[bh][s][d] -> gvt[bh][d][s] --------
__global__ void v_transpose_split() {
    __shared__ float t[32][33];
    int bh = blockIdx.z;
    int s0 = blockIdx.x * 32, d0 = blockIdx.y * 32;
    int tx = threadIdx.x, ty = threadIdx.y;   // 32 x 8
#pragma unroll
    for (int i = 0; i < 32; i += 8)
        t[ty + i][tx] = g_v[((size_t)bh*SEQ + s0 + ty + i) * HDIM + d0 + tx];
    __syncthreads();
#pragma unroll
    for (int i = 0; i < 32; i += 8) {
        float x = t[tx][ty + i];
        size_t off = ((size_t)bh*HDIM + d0 + ty + i) * SEQ + s0 + tx;
        __nv_bfloat16 h = __float2bfloat16(x);
        gvt_hi[off] = h;
        gvt_lo[off] = __float2bfloat16(x - __bfloat162float(h));
    }
}

// ============================================================================
// HMMA causal flash attention, split-3 on QK^T and PV, cp.async-pipelined K/V.
// K(t+1) prefetched into K buffer during softmax/PV(t); V(t+1) at tile end,
// in flight through S(t+1). wait_group retires in commit order, so wait(1)
// at loop top == K(t) resident; wait(1) mid-tile (after K(t+1) commit) ==
// V(t) resident. Unconditional commits keep the accounting uniform.
// ============================================================================
#define BQ 128
#define BT 64
#define QSTR 136
#define KSTR 136
#define VSTR 72
#define SSTR 68
#define PSTR 72

#define OFF_QHI 0
#define SZ_Q    (BQ*QSTR*2)
#define OFF_QLO (OFF_QHI + SZ_Q)
#define OFF_KHI (OFF_QLO + SZ_Q)
#define SZ_K    (BT*KSTR*2)
#define OFF_KLO (OFF_KHI + SZ_K)
#define OFF_VHI (OFF_KLO + SZ_K)
#define SZ_V    (HDIM*VSTR*2)
#define OFF_VLO (OFF_VHI + SZ_V)
#define OFF_SS  (OFF_VLO + SZ_V)
#define SZ_SS   (BQ*SSTR*4)
#define OFF_PHI (OFF_SS + SZ_SS)
#define SZ_P    (BQ*PSTR*2)
#define OFF_PLO (OFF_PHI + SZ_P)
#define OFF_MR  (OFF_PLO + SZ_P)
#define OFF_LR  (OFF_MR + BQ*4)
#define OFF_SC  (OFF_LR + BQ*4)
#define ATTN_SMEM (OFF_SC + BQ*4)

__global__ void __launch_bounds__(256, 1) attn_hmma(__nv_bfloat16* __restrict__ Aout) {
    extern __shared__ char smem[];
    const uint32_t sb = smem_u32(smem);

    const int tid  = threadIdx.x;
    const int lane = tid & 31;
    const int warp = tid >> 5;
    const int wm = warp >> 1;
    const int wn = warp & 1;
    const int qt = gridDim.x - 1 - blockIdx.x;   // heavy tiles first
    const int bh = blockIdx.y;
    const int q0 = qt * BQ;

    const int l16 = lane & 15;
    const int g   = lane >> 2;
    const int c2  = (lane & 3) * 2;

    __nv_bfloat16* s_qhi = (__nv_bfloat16*)(smem + OFF_QHI);
    __nv_bfloat16* s_qlo = (__nv_bfloat16*)(smem + OFF_QLO);
    float*         s_ss  = (float*)(smem + OFF_SS);
    __nv_bfloat16* s_phi = (__nv_bfloat16*)(smem + OFF_PHI);
    __nv_bfloat16* s_plo = (__nv_bfloat16*)(smem + OFF_PLO);
    float*         mrow  = (float*)(smem + OFF_MR);
    float*         lrow  = (float*)(smem + OFF_LR);
    float*         srow  = (float*)(smem + OFF_SC);

    const __nv_bfloat16* Kh = gk_hi + (size_t)bh*SEQ*HDIM;
    const __nv_bfloat16* Kl = gk_lo + (size_t)bh*SEQ*HDIM;
    const __nv_bfloat16* Vh = gvt_hi + (size_t)bh*HDIM*SEQ;
    const __nv_bfloat16* Vl = gvt_lo + (size_t)bh*HDIM*SEQ;

    // K tile prefetch: 64 rows x 256B (hi) + (lo); 4+4 chunks per thread
    auto prefetch_k = [&](int k0) {
#pragma unroll
        for (int it = 0; it < 4; it++) {
            int t = tid + it*256;
            int row = t >> 4, cc = t & 15;
            cpasync16(sb + OFF_KHI + (row*KSTR + cc*8)*2,
                      Kh + (size_t)(k0 + row)*HDIM + cc*8);
        }
#pragma unroll
        for (int it = 0; it < 4; it++) {
            int t = tid + it*256;
            int row = t >> 4, cc = t & 15;
            cpasync16(sb + OFF_KLO + (row*KSTR + cc*8)*2,
                      Kl + (size_t)(k0 + row)*HDIM + cc*8);
        }
    };
    // V tile prefetch: 128 d-rows x 128B (hi) + (lo)
    auto prefetch_v = [&](int k0) {
#pragma unroll
        for (int it = 0; it < 4; it++) {
            int t = tid + it*256;
            int d = t >> 3, cc = t & 7;
            cpasync16(sb + OFF_VHI + (d*VSTR + cc*8)*2,
                      Vh + (size_t)d*SEQ + k0 + cc*8);
        }
#pragma unroll
        for (int it = 0; it < 4; it++) {
            int t = tid + it*256;
            int d = t >> 3, cc = t & 7;
            cpasync16(sb + OFF_VLO + (d*VSTR + cc*8)*2,
                      Vl + (size_t)d*SEQ + k0 + cc*8);
        }
    };

    // preloop: K(0) then V(0) in flight
    prefetch_k(0); CP_COMMIT();
    prefetch_v(0); CP_COMMIT();

    // Q tile (hi & lo), once
    {
        const __nv_bfloat16* qh = gq_hi + ((size_t)bh*SEQ + q0) * HDIM;
        const __nv_bfloat16* ql = gq_lo + ((size_t)bh*SEQ + q0) * HDIM;
#pragma unroll
        for (int it = 0; it < 8; it++) {
            int t = tid + it*256;
            int row = t >> 4, cc = t & 15;
            *(uint4*)(s_qhi + row*QSTR + cc*8) = *(const uint4*)(qh + row*HDIM + cc*8);
        }
#pragma unroll
        for (int it = 0; it < 8; it++) {
            int t = tid + it*256;
            int row = t >> 4, cc = t & 15;
            *(uint4*)(s_qlo + row*QSTR + cc*8) = *(const uint4*)(ql + row*HDIM + cc*8);
        }
    }
    if (tid < BQ) { mrow[tid] = -1e30f; lrow[tid] = 0.0f; }

    float acc_o[2][8][4];
#pragma unroll
    for (int mt = 0; mt < 2; mt++)
#pragma unroll
        for (int nt = 0; nt < 8; nt++)
#pragma unroll
            for (int e = 0; e < 4; e++) acc_o[mt][nt][e] = 0.0f;

    const float rnorm = 0.088388347648318447f;

    const uint32_t qhi_b = sb + OFF_QHI + (((wm*32 + l16)*QSTR) + (lane>>4)*8)*2;
    const uint32_t qlo_b = sb + OFF_QLO + (((wm*32 + l16)*QSTR) + (lane>>4)*8)*2;
    const uint32_t khi_b = sb + OFF_KHI + (((wn*32 + (l16&7))*KSTR) + (l16>>3)*8)*2;
    const uint32_t klo_b = sb + OFF_KLO + (((wn*32 + (l16&7))*KSTR) + (l16>>3)*8)*2;
    const uint32_t phi_b = sb + OFF_PHI + (((wm*32 + l16)*PSTR) + (lane>>4)*8)*2;
    const uint32_t plo_b = sb + OFF_PLO + (((wm*32 + l16)*PSTR) + (lane>>4)*8)*2;
    const uint32_t vhi_b = sb + OFF_VHI + (((wn*64 + (l16&7))*VSTR) + (l16>>3)*8)*2;
    const uint32_t vlo_b = sb + OFF_VLO + (((wn*64 + (l16&7))*VSTR) + (l16>>3)*8)*2;

    const int ntiles = 2*qt + 2;
    for (int kt = 0; kt < ntiles; kt++) {
        const int k0 = kt * BT;

        CP_WAIT(1);          // K(kt) resident (all groups except newest done)
        __syncthreads();     // cross-thread visibility (K, and Q on iter 0)

        // ---- S = Q K^T (split-3) ----
        float sacc[2][4][4];
#pragma unroll
        for (int mt = 0; mt < 2; mt++)
#pragma unroll
            for (int nt = 0; nt < 4; nt++)
#pragma unroll
                for (int e = 0; e < 4; e++) sacc[mt][nt][e] = 0.0f;

#pragma unroll
        for (int k16 = 0; k16 < HDIM; k16 += 16) {
            uint32_t bhi[4][2], blo[4][2];
#pragma unroll
            for (int nt = 0; nt < 4; nt++) {
                ldsm2(bhi[nt], khi_b + (nt*8*KSTR + k16)*2);
                ldsm2(blo[nt], klo_b + (nt*8*KSTR + k16)*2);
            }
#pragma unroll
            for (int mt = 0; mt < 2; mt++) {
                uint32_t ahi[4], alo[4];
                ldsm4(ahi, qhi_b + (mt*16*QSTR + k16)*2);
                ldsm4(alo, qlo_b + (mt*16*QSTR + k16)*2);
#pragma unroll
                for (int nt = 0; nt < 4; nt++) {
                    mma16816(sacc[mt][nt], ahi, bhi[nt]);
                    mma16816(sacc[mt][nt], alo, bhi[nt]);
                    mma16816(sacc[mt][nt], ahi, blo[nt]);
                }
            }
        }

        // ---- S -> smem with scale + causal mask ----
#pragma unroll
        for (int mt = 0; mt < 2; mt++) {
#pragma unroll
            for (int nt = 0; nt < 4; nt++) {
#pragma unroll
                for (int i = 0; i < 2; i++) {
#pragma unroll
                    for (int j = 0; j < 2; j++) {
                        int r = wm*32 + mt*16 + g + i*8;
                        int c = wn*32 + nt*8 + c2 + j;
                        float v = sacc[mt][nt][i*2 + j] * rnorm;
                        if (k0 + c > q0 + r) v = -10000.0f;
                        s_ss[r*SSTR + c] = v;
                    }
                }
            }
        }
        __syncthreads();     // S visible; all K(kt) reads retired

        // prefetch K(kt+1) into (now-dead) K buffer; hidden by softmax+PV
        if (kt + 1 < ntiles) prefetch_k(k0 + BT);
        CP_COMMIT();         // unconditional: uniform group accounting

        // ---- row softmax + P split: 2 threads per row, __expf ----
        {
            int r  = tid >> 1;
            int hf = tid & 1;
            float* row = s_ss + r*SSTR + hf*32;
            float m_old = mrow[r];
            float mx = m_old;
#pragma unroll 8
            for (int c = 0; c < 32; c++) mx = fmaxf(mx, row[c]);
            mx = fmaxf(mx, __shfl_xor_sync(0xFFFFFFFFu, mx, 1));
            float sum = 0.0f;
            __nv_bfloat16* ph = s_phi + r*PSTR + hf*32;
            __nv_bfloat16* pl = s_plo + r*PSTR + hf*32;
#pragma unroll 8
            for (int c = 0; c < 32; c++) {
                float p = __expf(row[c] - mx);
                sum += p;
                __nv_bfloat16 h = __float2bfloat16(p);
                ph[c] = h;
                pl[c] = __float2bfloat16(p - __bfloat162float(h));
            }
            sum += __shfl_xor_sync(0xFFFFFFFFu, sum, 1);
            if (hf == 0) {
                float scl = __expf(m_old - mx);
                mrow[r] = mx;
                lrow[r] = lrow[r] * scl + sum;
                srow[r] = scl;
            }
        }

        CP_WAIT(1);          // V(kt) resident (only K(kt+1) may remain pending)
        __syncthreads();     // P visible + everyone's V done

        // ---- rescale acc_o, then O += P·Vt (split-3) ----
#pragma unroll
        for (int mt = 0; mt < 2; mt++) {
#pragma unroll
            for (int i = 0; i < 2; i++) {
                float s_ = srow[wm*32 + mt*16 + g + i*8];
#pragma unroll
                for (int nt = 0; nt < 8; nt++) {
                    acc_o[mt][nt][i*2 + 0] *= s_;
                    acc_o[mt][nt][i*2 + 1] *= s_;
                }
            }
        }
#pragma unroll
        for (int k16 = 0; k16 < BT; k16 += 16) {
            uint32_t bvh[8][2], bvl[8][2];
#pragma unroll
            for (int nt = 0; nt < 8; nt++) {
                ldsm2(bvh[nt], vhi_b + (nt*8*VSTR + k16)*2);
                ldsm2(bvl[nt], vlo_b + (nt*8*VSTR + k16)*2);
            }
#pragma unroll
            for (int mt = 0; mt < 2; mt++) {
                uint32_t aph[4], apl[4];
                ldsm4(aph, phi_b + (mt*16*PSTR + k16)*2);
                ldsm4(apl, plo_b + (mt*16*PSTR + k16)*2);
#pragma unroll
                for (int nt = 0; nt < 8; nt++) {
                    mma16816(acc_o[mt][nt], aph, bvh[nt]);
                    mma16816(acc_o[mt][nt], apl, bvh[nt]);
                    mma16816(acc_o[mt][nt], aph, bvl[nt]);
                }
            }
        }
        __syncthreads();     // all V(kt) reads retired before overwrite

        // prefetch V(kt+1); in flight through S(kt+1) compute
        if (kt + 1 < ntiles) prefetch_v(k0 + BT);
        CP_COMMIT();
    }

    // ---- finalize: divide by l, write dense-GEMM A' (hi|lo|hi) directly ----
    const int b_idx = bh / NHEADS;
    const int h_idx = bh % NHEADS;
#pragma unroll
    for (int mt = 0; mt < 2; mt++) {
#pragma unroll
        for (int i = 0; i < 2; i++) {
            int r = wm*32 + mt*16 + g + i*8;
            float linv = 1.0f / lrow[r];
            int s_idx = q0 + r;
            size_t tok = (size_t)(s_idx*BATCH + b_idx);
            __nv_bfloat16* dst = Aout + tok*K3 + h_idx*HDIM + wn*64;
#pragma unroll
            for (int nt = 0; nt < 8; nt++) {
#pragma unroll
                for (int j = 0; j < 2; j++) {
                    float v = acc_o[mt][nt][i*2 + j] * linv;
                    __nv_bfloat16 h = __float2bfloat16(v);
                    __nv_bfloat16 l = __float2bfloat16(v - __bfloat162float(h));
                    int cc = nt*8 + c2 + j;
                    dst[cc]         = h;
                    dst[HID + cc]   = l;
                    dst[2*HID + cc] = h;
                }
            }
        }
    }
}

// ---------------- tail bias ---------------------------------------------------
__global__ void tail_copy(const float* __restrict__ src, float* __restrict__ dst, int n) {
    int i = blockIdx.x * blockDim.x + threadIdx.x;
    if (i < n) dst[i] = src[i];
}

// ---------------- launch -------------------------------------------------------
extern "C" void kernel_launch(void* const* d_in, const int* in_sizes, int n_in,
                              void* d_out, int out_size)
{
    const float* hidden  = (const float*)d_in[0];
    const float* w_qkv   = (const float*)d_in[2];
    const float* b_qkv   = (const float*)d_in[3];
    const float* w_dense = (const float*)d_in[4];
    const float* b_dense = (const float*)d_in[5];
    float* out = (float*)d_out;

    void *pA, *pBq, *pBd, *pQ, *pK, *pV;
    cudaGetSymbolAddress(&pA,   g_Abuf);
    cudaGetSymbolAddress(&pBq,  g_Bq);
    cudaGetSymbolAddress(&pBd,  g_Bd);
    cudaGetSymbolAddress(&pQ,   g_q);
    cudaGetSymbolAddress(&pK,   g_k);
    cudaGetSymbolAddress(&pV,   g_v);

    cudaFuncSetAttribute(hmma_gemm<1>, cudaFuncAttributeMaxDynamicSharedMemorySize, GEMM_SMEM);
    cudaFuncSetAttribute(hmma_gemm<2>, cudaFuncAttributeMaxDynamicSharedMemorySize, GEMM_SMEM);
    cudaFuncSetAttribute(attn_hmma, cudaFuncAttributeMaxDynamicSharedMemorySize, ATTN_SMEM);

    // 1) split-convert A (hidden) and B (w_qkv)
    conv_split<0><<<(TOK*HID + 255)/256, 256>>>(hidden, (__nv_bfloat16*)pA, TOK, HID);
    conv_split<1><<<(QKV_N*HID + 255)/256, 256>>>(w_qkv, (__nv_bfloat16*)pBq, QKV_N, HID);

    // 2) QKV projection (HMMA, bias + scatter epilogue)
    hmma_gemm<1><<<dim3(QKV_N/128, TOK/128), 256, GEMM_SMEM>>>(
        (const __nv_bfloat16*)pA, (const __nv_bfloat16*)pBq, b_qkv, nullptr,
        (float*)pQ, (float*)pK, (float*)pV, QKV_N);

    // 3) RoPE (emits bf16 hi/lo Q,K) + V transpose/split
    rope_table_kernel<<<(SEQ*64 + 255)/256, 256>>>();
    rope_apply_kernel<<<(NBH*SEQ*64 + 255)/256, 256>>>();
    v_transpose_split<<<dim3(SEQ/32, HDIM/32, NBH), dim3(32, 8)>>>();

    // 4) causal attention (HMMA split-3, cp.async pipelined)
    attn_hmma<<<dim3(SEQ/BQ, NBH), 256, ATTN_SMEM>>>((__nv_bfloat16*)pA);

    // 5) w_dense split + dense GEMM (HMMA)
    conv_split<1><<<(HID*HID + 255)/256, 256>>>(w_dense, (__nv_bfloat16*)pBd, HID, HID);
    hmma_gemm<2><<<dim3(HID/128, TOK/128), 256, GEMM_SMEM>>>(
        (const __nv_bfloat16*)pA, (const __nv_bfloat16*)pBd, nullptr, out,
        nullptr, nullptr, nullptr, HID);

    // 6) bias tail if harness flattens the (output, bias) tuple
    int extra = out_size - TOK*HID;
    if (extra > 0)
        tail_copy<<<(extra + 255)/256, 256>>>(b_dense, out + (size_t)TOK*HID, extra);
    (void)in_sizes; (void)n_in;
}

// round 8
// speedup vs baseline: 3.2629x; 1.3159x over previous
#include <cuda_runtime.h>
#include <cuda_bf16.h>
#include <cuda_fp16.h>
#include <math.h>
#include <stdint.h>

#define SEQ     2048
#define BATCH   2
#define HID     2048
#define NHEADS  16
#define HDIM    128
#define TOK     (SEQ*BATCH)     // 4096
#define QKV_N   (3*HID)         // 6144
#define K2      (2*HID)         // fp16 split-2 K' = 4096
#define NBH     (BATCH*NHEADS)  // 32

// ---------------- scratch (device globals; no runtime allocs allowed) -------
__device__ float g_q[NBH*SEQ*HDIM];
__device__ float g_k[NBH*SEQ*HDIM];
__device__ float g_v[NBH*SEQ*HDIM];
__device__ float g_cos[SEQ*64];
__device__ float g_sin[SEQ*64];
// fp16 split-2 operand buffers (GEMMs)
__device__ __align__(1024) __half g_Abuf[TOK*K2];
__device__ __align__(1024) __half g_Bq[QKV_N*K2];
__device__ __align__(1024) __half g_Bd[HID*K2];
// attention split operands (bf16 split-3, unchanged)
__device__ __align__(16) __nv_bfloat16 gq_hi[NBH*SEQ*HDIM];
__device__ __align__(16) __nv_bfloat16 gq_lo[NBH*SEQ*HDIM];
__device__ __align__(16) __nv_bfloat16 gk_hi[NBH*SEQ*HDIM];
__device__ __align__(16) __nv_bfloat16 gk_lo[NBH*SEQ*HDIM];
__device__ __align__(16) __nv_bfloat16 gvt_hi[NBH*HDIM*SEQ];   // [bh][d][s]
__device__ __align__(16) __nv_bfloat16 gvt_lo[NBH*HDIM*SEQ];

// ============================================================================
// PTX helpers (base-target-safe)
// ============================================================================
__device__ __forceinline__ uint32_t smem_u32(const void* p) {
    uint32_t a;
    asm("{ .reg .u64 t; cvta.to.shared.u64 t, %1; cvt.u32.u64 %0, t; }"
        : "=r"(a) : "l"(p));
    return a;
}
__device__ __forceinline__ void cpasync16(uint32_t s, const void* g) {
    asm volatile("cp.async.cg.shared.global [%0], [%1], 16;" :: "r"(s), "l"(g));
}
#define CP_COMMIT() asm volatile("cp.async.commit_group;" ::: "memory")
#define CP_WAIT(n)  asm volatile("cp.async.wait_group %0;" :: "n"(n) : "memory")

__device__ __forceinline__ void ldsm4(uint32_t* r, uint32_t a) {
    asm volatile("ldmatrix.sync.aligned.m8n8.x4.shared.b16 {%0,%1,%2,%3}, [%4];"
        : "=r"(r[0]), "=r"(r[1]), "=r"(r[2]), "=r"(r[3]) : "r"(a));
}
__device__ __forceinline__ void ldsm2(uint32_t* r, uint32_t a) {
    asm volatile("ldmatrix.sync.aligned.m8n8.x2.shared.b16 {%0,%1}, [%2];"
        : "=r"(r[0]), "=r"(r[1]) : "r"(a));
}
// bf16 variant (attention)
__device__ __forceinline__ void mma16816(float* c, const uint32_t* a, const uint32_t* b) {
    asm volatile("mma.sync.aligned.m16n8k16.row.col.f32.bf16.bf16.f32 "
        "{%0,%1,%2,%3}, {%4,%5,%6,%7}, {%8,%9}, {%0,%1,%2,%3};"
        : "+f"(c[0]), "+f"(c[1]), "+f"(c[2]), "+f"(c[3])
        : "r"(a[0]), "r"(a[1]), "r"(a[2]), "r"(a[3]), "r"(b[0]), "r"(b[1]));
}
// fp16 variant (GEMMs)
__device__ __forceinline__ void mma16816h(float* c, const uint32_t* a, const uint32_t* b) {
    asm volatile("mma.sync.aligned.m16n8k16.row.col.f32.f16.f16.f32 "
        "{%0,%1,%2,%3}, {%4,%5,%6,%7}, {%8,%9}, {%0,%1,%2,%3};"
        : "+f"(c[0]), "+f"(c[1]), "+f"(c[2]), "+f"(c[3])
        : "r"(a[0]), "r"(a[1]), "r"(a[2]), "r"(a[3]), "r"(b[0]), "r"(b[1]));
}

// ============================================================================
// HMMA fp16 split-2 GEMM: C[M,N] = A'[M,K2] * B'[N,K2]^T (fp32 accum).
// 4-stage cp.async ring, ONE barrier per K-step. CTA tile 128x128x32.
// MODE 1: QKV — add bias + scatter to q/k/v.   MODE 2: plain C store.
// ============================================================================
#define BK 32
#define ASTR 40
#define TILE_B16 (128*ASTR)
#define STAGE_B16 (2*TILE_B16)
#define STAGE_BYTES (STAGE_B16*2)
#define GSTAGES 4
#define GEMM_SMEM (GSTAGES*STAGE_BYTES)

template<int MODE>
__global__ void __launch_bounds__(256, 2)
hmma_gemm(const __half* __restrict__ Ag, const __half* __restrict__ Bg,
          const float* __restrict__ bias, float* __restrict__ C,
          float* __restrict__ q_out, float* __restrict__ k_out, float* __restrict__ v_out,
          int N)
{
    extern __shared__ __align__(16) __half smbuf[];

    const int tid  = threadIdx.x;
    const int lane = tid & 31;
    const int warp = tid >> 5;
    const int wm = warp >> 2;
    const int wn = warp & 3;
    const int m0 = blockIdx.y * 128;
    const int n0 = blockIdx.x * 128;

    const uint32_t smb = smem_u32(smbuf);
    const int cr = tid >> 2;
    const int ccn = tid & 3;
    const int KT = K2 / BK;            // 128

    auto prefetch = [&](int kt, int slot) {
        uint32_t base = smb + slot * STAGE_BYTES;
#pragma unroll
        for (int h = 0; h < 2; h++) {
            int r = cr + h * 64;
            cpasync16(base + (r * ASTR + ccn * 8) * 2,
                      Ag + (size_t)(m0 + r) * K2 + kt * BK + ccn * 8);
            cpasync16(base + TILE_B16*2 + (r * ASTR + ccn * 8) * 2,
                      Bg + (size_t)(n0 + r) * K2 + kt * BK + ccn * 8);
        }
    };

    float acc[4][4][4];
#pragma unroll
    for (int i = 0; i < 4; i++)
#pragma unroll
        for (int j = 0; j < 4; j++)
#pragma unroll
            for (int e = 0; e < 4; e++) acc[i][j][e] = 0.0f;

    const int l16 = lane & 15;
    const uint32_t a_off = (((wm * 64 + l16) * ASTR) + ((lane >> 4) * 8)) * 2;
    const uint32_t b_off = (((wn * 32 + (l16 & 7)) * ASTR) + ((l16 >> 3) * 8)) * 2;

    prefetch(0, 0); CP_COMMIT();
    prefetch(1, 1); CP_COMMIT();
    prefetch(2, 2); CP_COMMIT();

    for (int kt = 0; kt < KT; kt++) {
        CP_WAIT(2);
        __syncthreads();
        int pf = kt + 3;
        if (pf < KT) prefetch(pf, pf & 3);
        CP_COMMIT();

        uint32_t abase = smb + (kt & 3) * STAGE_BYTES + a_off;
        uint32_t bbase = smb + (kt & 3) * STAGE_BYTES + TILE_B16*2 + b_off;

#pragma unroll
        for (int k16 = 0; k16 < BK; k16 += 16) {
            uint32_t bfr[4][2];
#pragma unroll
            for (int nt = 0; nt < 4; nt++)
                ldsm2(bfr[nt], bbase + (nt * 8 * ASTR + k16) * 2);
#pragma unroll
            for (int mt = 0; mt < 4; mt++) {
                uint32_t afr[4];
                ldsm4(afr, abase + (mt * 16 * ASTR + k16) * 2);
#pragma unroll
                for (int nt = 0; nt < 4; nt++)
                    mma16816h(acc[mt][nt], afr, bfr[nt]);
            }
        }
    }

    const int g  = lane >> 2;
    const int c2 = (lane & 3) * 2;
#pragma unroll
    for (int mt = 0; mt < 4; mt++) {
#pragma unroll
        for (int nt = 0; nt < 4; nt++) {
#pragma unroll
            for (int i = 0; i < 2; i++) {
#pragma unroll
                for (int j = 0; j < 2; j++) {
                    int m = m0 + wm * 64 + mt * 16 + g + i * 8;
                    int n = n0 + wn * 32 + nt * 8 + c2 + j;
                    float v = acc[mt][nt][i * 2 + j];
                    if (MODE == 1) {
                        v += bias[n];
                        int head = n / (3 * HDIM);
                        int r3   = n % (3 * HDIM);
                        int part = r3 / HDIM;
                        int d    = r3 % HDIM;
                        int off  = (((m & 1) * NHEADS + head) * SEQ + (m >> 1)) * HDIM + d;
                        if      (part == 0) q_out[off] = v;
                        else if (part == 1) k_out[off] = v;
                        else                v_out[off] = v;
                    } else {
                        C[(size_t)m * N + n] = v;
                    }
                }
            }
        }
    }
}

// ---------------- fp16 split-2 conversion (vectorized) -----------------------
// PAT 0 (A): [hi|lo]    PAT 1 (B): [hi|hi]
template<int PAT>
__global__ void conv_split(const float* __restrict__ src,
                           __half* __restrict__ dst, int R, int K)
{
    int idx = blockIdx.x * blockDim.x + threadIdx.x;     // float4 index
    int kq = K >> 2;
    if (idx >= R * kq) return;
    int row = idx / kq, c4 = idx - row * kq;
    float4 x = ((const float4*)src)[idx];
    __half hi[4];
    hi[0] = __float2half(x.x); hi[1] = __float2half(x.y);
    hi[2] = __float2half(x.z); hi[3] = __float2half(x.w);
    size_t base = (size_t)row * (2*K) + c4 * 4;
    *(uint2*)(dst + base) = *(uint2*)hi;
    if (PAT == 0) {
        __half lo[4];
        lo[0] = __float2half(x.x - __half2float(hi[0]));
        lo[1] = __float2half(x.y - __half2float(hi[1]));
        lo[2] = __float2half(x.z - __half2float(hi[2]));
        lo[3] = __float2half(x.w - __half2float(hi[3]));
        *(uint2*)(dst + base + K) = *(uint2*)lo;
    } else {
        *(uint2*)(dst + base + K) = *(uint2*)hi;
    }
}

// ---------------- RoPE tables + apply ----------------------------------------
__global__ void rope_table_kernel() {
    __shared__ float invf[64];
    if (threadIdx.x < 64)
        invf[threadIdx.x] = (float)pow(10000.0, -((double)threadIdx.x) / 64.0);
    __syncthreads();
    int idx = blockIdx.x * blockDim.x + threadIdx.x;
    if (idx >= SEQ * 64) return;
    int s = idx >> 6;
    int i = idx & 63;
    float theta = (float)s * invf[i];
    g_cos[idx] = cosf(theta);
    g_sin[idx] = sinf(theta);
}

__device__ __forceinline__ void split_store(__nv_bfloat16* hi, __nv_bfloat16* lo,
                                            int off, float x) {
    __nv_bfloat16 h = __float2bfloat16(x);
    hi[off] = h;
    lo[off] = __float2bfloat16(x - __bfloat162float(h));
}

__global__ void rope_apply_kernel() {
    int idx = blockIdx.x * blockDim.x + threadIdx.x;
    int total = NBH*SEQ*64;
    if (idx >= total) return;
    int i = idx & 63;
    int rowid = idx >> 6;
    int s = rowid & (SEQ - 1);
    float c  = g_cos[s*64 + i];
    float sn = g_sin[s*64 + i];
    int base = rowid * HDIM;
    float q1 = g_q[base + i], q2 = g_q[base + 64 + i];
    float k1 = g_k[base + i], k2 = g_k[base + 64 + i];
    split_store(gq_hi, gq_lo, base + i,      q1*c - q2*sn);
    split_store(gq_hi, gq_lo, base + 64 + i, q2*c + q1*sn);
    split_store(gk_hi, gk_lo, base + i,      k1*c - k2*sn);
    split_store(gk_hi, gk_lo, base + 64 + i, k2*c + k1*sn);
}

// ---------------- V transpose + split: g_v[bh][s][d] -> gvt[bh][d][s] --------
__global__ void v_transpose_split() {
    __shared__ float t[32][33];
    int bh = blockIdx.z;
    int s0 = blockIdx.x * 32, d0 = blockIdx.y * 32;
    int tx = threadIdx.x, ty = threadIdx.y;   // 32 x 8
#pragma unroll
    for (int i = 0; i < 32; i += 8)
        t[ty + i][tx] = g_v[((size_t)bh*SEQ + s0 + ty + i) * HDIM + d0 + tx];
    __syncthreads();
#pragma unroll
    for (int i = 0; i < 32; i += 8) {
        float x = t[tx][ty + i];
        size_t off = ((size_t)bh*HDIM + d0 + ty + i) * SEQ + s0 + tx;
        __nv_bfloat16 h = __float2bfloat16(x);
        gvt_hi[off] = h;
        gvt_lo[off] = __float2bfloat16(x - __bfloat162float(h));
    }
}

// ============================================================================
// HMMA causal flash attention (bf16 split-3, cp.async pipelined) — unchanged
// except epilogue emits fp16 split-2 dense-GEMM A' rows.
// ============================================================================
#define BQ 128
#define BT 64
#define QSTR 136
#define KSTR 136
#define VSTR 72
#define SSTR 68
#define PSTR 72

#define OFF_QHI 0
#define SZ_Q    (BQ*QSTR*2)
#define OFF_QLO (OFF_QHI + SZ_Q)
#define OFF_KHI (OFF_QLO + SZ_Q)
#define SZ_K    (BT*KSTR*2)
#define OFF_KLO (OFF_KHI + SZ_K)
#define OFF_VHI (OFF_KLO + SZ_K)
#define SZ_V    (HDIM*VSTR*2)
#define OFF_VLO (OFF_VHI + SZ_V)
#define OFF_SS  (OFF_VLO + SZ_V)
#define SZ_SS   (BQ*SSTR*4)
#define OFF_PHI (OFF_SS + SZ_SS)
#define SZ_P    (BQ*PSTR*2)
#define OFF_PLO (OFF_PHI + SZ_P)
#define OFF_MR  (OFF_PLO + SZ_P)
#define OFF_LR  (OFF_MR + BQ*4)
#define OFF_SC  (OFF_LR + BQ*4)
#define ATTN_SMEM (OFF_SC + BQ*4)

__global__ void __launch_bounds__(256, 1) attn_hmma(__half* __restrict__ Aout) {
    extern __shared__ char smem[];
    const uint32_t sb = smem_u32(smem);

    const int tid  = threadIdx.x;
    const int lane = tid & 31;
    const int warp = tid >> 5;
    const int wm = warp >> 1;
    const int wn = warp & 1;
    const int qt = gridDim.x - 1 - blockIdx.x;   // heavy tiles first
    const int bh = blockIdx.y;
    const int q0 = qt * BQ;

    const int l16 = lane & 15;
    const int g   = lane >> 2;
    const int c2  = (lane & 3) * 2;

    __nv_bfloat16* s_qhi = (__nv_bfloat16*)(smem + OFF_QHI);
    __nv_bfloat16* s_qlo = (__nv_bfloat16*)(smem + OFF_QLO);
    float*         s_ss  = (float*)(smem + OFF_SS);
    __nv_bfloat16* s_phi = (__nv_bfloat16*)(smem + OFF_PHI);
    __nv_bfloat16* s_plo = (__nv_bfloat16*)(smem + OFF_PLO);
    float*         mrow  = (float*)(smem + OFF_MR);
    float*         lrow  = (float*)(smem + OFF_LR);
    float*         srow  = (float*)(smem + OFF_SC);

    const __nv_bfloat16* Kh = gk_hi + (size_t)bh*SEQ*HDIM;
    const __nv_bfloat16* Kl = gk_lo + (size_t)bh*SEQ*HDIM;
    const __nv_bfloat16* Vh = gvt_hi + (size_t)bh*HDIM*SEQ;
    const __nv_bfloat16* Vl = gvt_lo + (size_t)bh*HDIM*SEQ;

    auto prefetch_k = [&](int k0) {
#pragma unroll
        for (int it = 0; it < 4; it++) {
            int t = tid + it*256;
            int row = t >> 4, cc = t & 15;
            cpasync16(sb + OFF_KHI + (row*KSTR + cc*8)*2,
                      Kh + (size_t)(k0 + row)*HDIM + cc*8);
        }
#pragma unroll
        for (int it = 0; it < 4; it++) {
            int t = tid + it*256;
            int row = t >> 4, cc = t & 15;
            cpasync16(sb + OFF_KLO + (row*KSTR + cc*8)*2,
                      Kl + (size_t)(k0 + row)*HDIM + cc*8);
        }
    };
    auto prefetch_v = [&](int k0) {
#pragma unroll
        for (int it = 0; it < 4; it++) {
            int t = tid + it*256;
            int d = t >> 3, cc = t & 7;
            cpasync16(sb + OFF_VHI + (d*VSTR + cc*8)*2,
                      Vh + (size_t)d*SEQ + k0 + cc*8);
        }
#pragma unroll
        for (int it = 0; it < 4; it++) {
            int t = tid + it*256;
            int d = t >> 3, cc = t & 7;
            cpasync16(sb + OFF_VLO + (d*VSTR + cc*8)*2,
                      Vl + (size_t)d*SEQ + k0 + cc*8);
        }
    };

    prefetch_k(0); CP_COMMIT();
    prefetch_v(0); CP_COMMIT();

    {
        const __nv_bfloat16* qh = gq_hi + ((size_t)bh*SEQ + q0) * HDIM;
        const __nv_bfloat16* ql = gq_lo + ((size_t)bh*SEQ + q0) * HDIM;
#pragma unroll
        for (int it = 0; it < 8; it++) {
            int t = tid + it*256;
            int row = t >> 4, cc = t & 15;
            *(uint4*)(s_qhi + row*QSTR + cc*8) = *(const uint4*)(qh + row*HDIM + cc*8);
        }
#pragma unroll
        for (int it = 0; it < 8; it++) {
            int t = tid + it*256;
            int row = t >> 4, cc = t & 15;
            *(uint4*)(s_qlo + row*QSTR + cc*8) = *(const uint4*)(ql + row*HDIM + cc*8);
        }
    }
    if (tid < BQ) { mrow[tid] = -1e30f; lrow[tid] = 0.0f; }

    float acc_o[2][8][4];
#pragma unroll
    for (int mt = 0; mt < 2; mt++)
#pragma unroll
        for (int nt = 0; nt < 8; nt++)
#pragma unroll
            for (int e = 0; e < 4; e++) acc_o[mt][nt][e] = 0.0f;

    const float rnorm = 0.088388347648318447f;

    const uint32_t qhi_b = sb + OFF_QHI + (((wm*32 + l16)*QSTR) + (lane>>4)*8)*2;
    const uint32_t qlo_b = sb + OFF_QLO + (((wm*32 + l16)*QSTR) + (lane>>4)*8)*2;
    const uint32_t khi_b = sb + OFF_KHI + (((wn*32 + (l16&7))*KSTR) + (l16>>3)*8)*2;
    const uint32_t klo_b = sb + OFF_KLO + (((wn*32 + (l16&7))*KSTR) + (l16>>3)*8)*2;
    const uint32_t phi_b = sb + OFF_PHI + (((wm*32 + l16)*PSTR) + (lane>>4)*8)*2;
    const uint32_t plo_b = sb + OFF_PLO + (((wm*32 + l16)*PSTR) + (lane>>4)*8)*2;
    const uint32_t vhi_b = sb + OFF_VHI + (((wn*64 + (l16&7))*VSTR) + (l16>>3)*8)*2;
    const uint32_t vlo_b = sb + OFF_VLO + (((wn*64 + (l16&7))*VSTR) + (l16>>3)*8)*2;

    const int ntiles = 2*qt + 2;
    for (int kt = 0; kt < ntiles; kt++) {
        const int k0 = kt * BT;

        CP_WAIT(1);
        __syncthreads();

        // ---- S = Q K^T (split-3) ----
        float sacc[2][4][4];
#pragma unroll
        for (int mt = 0; mt < 2; mt++)
#pragma unroll
            for (int nt = 0; nt < 4; nt++)
#pragma unroll
                for (int e = 0; e < 4; e++) sacc[mt][nt][e] = 0.0f;

#pragma unroll
        for (int k16 = 0; k16 < HDIM; k16 += 16) {
            uint32_t bhi[4][2], blo[4][2];
#pragma unroll
            for (int nt = 0; nt < 4; nt++) {
                ldsm2(bhi[nt], khi_b + (nt*8*KSTR + k16)*2);
                ldsm2(blo[nt], klo_b + (nt*8*KSTR + k16)*2);
            }
#pragma unroll
            for (int mt = 0; mt < 2; mt++) {
                uint32_t ahi[4], alo[4];
                ldsm4(ahi, qhi_b + (mt*16*QSTR + k16)*2);
                ldsm4(alo, qlo_b + (mt*16*QSTR + k16)*2);
#pragma unroll
                for (int nt = 0; nt < 4; nt++) {
                    mma16816(sacc[mt][nt], ahi, bhi[nt]);
                    mma16816(sacc[mt][nt], alo, bhi[nt]);
                    mma16816(sacc[mt][nt], ahi, blo[nt]);
                }
            }
        }

        // ---- S -> smem with scale + causal mask ----
#pragma unroll
        for (int mt = 0; mt < 2; mt++) {
#pragma unroll
            for (int nt = 0; nt < 4; nt++) {
#pragma unroll
                for (int i = 0; i < 2; i++) {
#pragma unroll
                    for (int j = 0; j < 2; j++) {
                        int r = wm*32 + mt*16 + g + i*8;
                        int c = wn*32 + nt*8 + c2 + j;
                        float v = sacc[mt][nt][i*2 + j] * rnorm;
                        if (k0 + c > q0 + r) v = -10000.0f;
                        s_ss[r*SSTR + c] = v;
                    }
                }
            }
        }
        __syncthreads();

        if (kt + 1 < ntiles) prefetch_k(k0 + BT);
        CP_COMMIT();

        // ---- row softmax + P split: 2 threads per row, __expf ----
        {
            int r  = tid >> 1;
            int hf = tid & 1;
            float* row = s_ss + r*SSTR + hf*32;
            float m_old = mrow[r];
            float mx = m_old;
#pragma unroll 8
            for (int c = 0; c < 32; c++) mx = fmaxf(mx, row[c]);
            mx = fmaxf(mx, __shfl_xor_sync(0xFFFFFFFFu, mx, 1));
            float sum = 0.0f;
            __nv_bfloat16* ph = s_phi + r*PSTR + hf*32;
            __nv_bfloat16* pl = s_plo + r*PSTR + hf*32;
#pragma unroll 8
            for (int c = 0; c < 32; c++) {
                float p = __expf(row[c] - mx);
                sum += p;
                __nv_bfloat16 h = __float2bfloat16(p);
                ph[c] = h;
                pl[c] = __float2bfloat16(p - __bfloat162float(h));
            }
            sum += __shfl_xor_sync(0xFFFFFFFFu, sum, 1);
            if (hf == 0) {
                float scl = __expf(m_old - mx);
                mrow[r] = mx;
                lrow[r] = lrow[r] * scl + sum;
                srow[r] = scl;
            }
        }

        CP_WAIT(1);
        __syncthreads();

        // ---- rescale acc_o, then O += P·Vt (split-3) ----
#pragma unroll
        for (int mt = 0; mt < 2; mt++) {
#pragma unroll
            for (int i = 0; i < 2; i++) {
                float s_ = srow[wm*32 + mt*16 + g + i*8];
#pragma unroll
                for (int nt = 0; nt < 8; nt++) {
                    acc_o[mt][nt][i*2 + 0] *= s_;
                    acc_o[mt][nt][i*2 + 1] *= s_;
                }
            }
        }
#pragma unroll
        for (int k16 = 0; k16 < BT; k16 += 16) {
            uint32_t bvh[8][2], bvl[8][2];
#pragma unroll
            for (int nt = 0; nt < 8; nt++) {
                ldsm2(bvh[nt], vhi_b + (nt*8*VSTR + k16)*2);
                ldsm2(bvl[nt], vlo_b + (nt*8*VSTR + k16)*2);
            }
#pragma unroll
            for (int mt = 0; mt < 2; mt++) {
                uint32_t aph[4], apl[4];
                ldsm4(aph, phi_b + (mt*16*PSTR + k16)*2);
                ldsm4(apl, plo_b + (mt*16*PSTR + k16)*2);
#pragma unroll
                for (int nt = 0; nt < 8; nt++) {
                    mma16816(acc_o[mt][nt], aph, bvh[nt]);
                    mma16816(acc_o[mt][nt], apl, bvh[nt]);
                    mma16816(acc_o[mt][nt], aph, bvl[nt]);
                }
            }
        }
        __syncthreads();

        if (kt + 1 < ntiles) prefetch_v(k0 + BT);
        CP_COMMIT();
    }

    // ---- finalize: divide by l, write fp16 split-2 dense-GEMM A' ----
    const int b_idx = bh / NHEADS;
    const int h_idx = bh % NHEADS;
#pragma unroll
    for (int mt = 0; mt < 2; mt++) {
#pragma unroll
        for (int i = 0; i < 2; i++) {
            int r = wm*32 + mt*16 + g + i*8;
            float linv = 1.0f / lrow[r];
            int s_idx = q0 + r;
            size_t tok = (size_t)(s_idx*BATCH + b_idx);
            __half* dst = Aout + tok*K2 + h_idx*HDIM + wn*64;
#pragma unroll
            for (int nt = 0; nt < 8; nt++) {
#pragma unroll
                for (int j = 0; j < 2; j++) {
                    float v = acc_o[mt][nt][i*2 + j] * linv;
                    __half h = __float2half(v);
                    __half l = __float2half(v - __half2float(h));
                    int cc = nt*8 + c2 + j;
                    dst[cc]       = h;
                    dst[HID + cc] = l;
                }
            }
        }
    }
}

// ---------------- tail bias ---------------------------------------------------
__global__ void tail_copy(const float* __restrict__ src, float* __restrict__ dst, int n) {
    int i = blockIdx.x * blockDim.x + threadIdx.x;
    if (i < n) dst[i] = src[i];
}

// ---------------- launch -------------------------------------------------------
extern "C" void kernel_launch(void* const* d_in, const int* in_sizes, int n_in,
                              void* d_out, int out_size)
{
    const float* hidden  = (const float*)d_in[0];
    const float* w_qkv   = (const float*)d_in[2];
    const float* b_qkv   = (const float*)d_in[3];
    const float* w_dense = (const float*)d_in[4];
    const float* b_dense = (const float*)d_in[5];
    float* out = (float*)d_out;

    void *pA, *pBq, *pBd, *pQ, *pK, *pV;
    cudaGetSymbolAddress(&pA,   g_Abuf);
    cudaGetSymbolAddress(&pBq,  g_Bq);
    cudaGetSymbolAddress(&pBd,  g_Bd);
    cudaGetSymbolAddress(&pQ,   g_q);
    cudaGetSymbolAddress(&pK,   g_k);
    cudaGetSymbolAddress(&pV,   g_v);

    cudaFuncSetAttribute(hmma_gemm<1>, cudaFuncAttributeMaxDynamicSharedMemorySize, GEMM_SMEM);
    cudaFuncSetAttribute(hmma_gemm<2>, cudaFuncAttributeMaxDynamicSharedMemorySize, GEMM_SMEM);
    cudaFuncSetAttribute(attn_hmma, cudaFuncAttributeMaxDynamicSharedMemorySize, ATTN_SMEM);

    // 1) split-convert A (hidden) and B (w_qkv) to fp16 split-2
    conv_split<0><<<(TOK*HID/4 + 255)/256, 256>>>(hidden, (__half*)pA, TOK, HID);
    conv_split<1><<<(QKV_N*HID/4 + 255)/256, 256>>>(w_qkv, (__half*)pBq, QKV_N, HID);

    // 2) QKV projection (fp16 HMMA, bias + scatter epilogue)
    hmma_gemm<1><<<dim3(QKV_N/128, TOK/128), 256, GEMM_SMEM>>>(
        (const __half*)pA, (const __half*)pBq, b_qkv, nullptr,
        (float*)pQ, (float*)pK, (float*)pV, QKV_N);

    // 3) RoPE (emits bf16 hi/lo Q,K) + V transpose/split
    rope_table_kernel<<<(SEQ*64 + 255)/256, 256>>>();
    rope_apply_kernel<<<(NBH*SEQ*64 + 255)/256, 256>>>();
    v_transpose_split<<<dim3(SEQ/32, HDIM/32, NBH), dim3(32, 8)>>>();

    // 4) causal attention (bf16 split-3, cp.async pipelined)
    attn_hmma<<<dim3(SEQ/BQ, NBH), 256, ATTN_SMEM>>>((__half*)pA);

    // 5) w_dense split + dense GEMM (fp16 HMMA)
    conv_split<1><<<(HID*HID/4 + 255)/256, 256>>>(w_dense, (__half*)pBd, HID, HID);
    hmma_gemm<2><<<dim3(HID/128, TOK/128), 256, GEMM_SMEM>>>(
        (const __half*)pA, (const __half*)pBd, nullptr, out,
        nullptr, nullptr, nullptr, HID);

    // 6) bias tail if harness flattens the (output, bias) tuple
    int extra = out_size - TOK*HID;
    if (extra > 0)
        tail_copy<<<(extra + 255)/256, 256>>>(b_dense, out + (size_t)TOK*HID, extra);
    (void)in_sizes; (void)n_in;
}

// round 9
// speedup vs baseline: 3.3015x; 1.0118x over previous
#include <cuda_runtime.h>
#include <cuda_bf16.h>
#include <cuda_fp16.h>
#include <math.h>
#include <stdint.h>

#define SEQ     2048
#define BATCH   2
#define HID     2048
#define NHEADS  16
#define HDIM    128
#define TOK     (SEQ*BATCH)     // 4096
#define QKV_N   (3*HID)         // 6144
#define K2      (2*HID)         // fp16 split-2 K' = 4096
#define NBH     (BATCH*NHEADS)  // 32

// ---------------- scratch (device globals; no runtime allocs allowed) -------
__device__ float g_q[NBH*SEQ*HDIM];
__device__ float g_k[NBH*SEQ*HDIM];
__device__ float g_v[NBH*SEQ*HDIM];
__device__ float g_cos[SEQ*64];
__device__ float g_sin[SEQ*64];
// fp16 split-2 operand buffers (GEMMs)
__device__ __align__(1024) __half g_Abuf[TOK*K2];
__device__ __align__(1024) __half g_Bq[QKV_N*K2];
__device__ __align__(1024) __half g_Bd[HID*K2];
// attention split operands (fp16 split-2)
__device__ __align__(16) __half gq_hi[NBH*SEQ*HDIM];
__device__ __align__(16) __half gq_lo[NBH*SEQ*HDIM];
__device__ __align__(16) __half gk_hi[NBH*SEQ*HDIM];
__device__ __align__(16) __half gk_lo[NBH*SEQ*HDIM];
__device__ __align__(16) __half gvt_hi[NBH*HDIM*SEQ];   // [bh][d][s]
__device__ __align__(16) __half gvt_lo[NBH*HDIM*SEQ];

// ============================================================================
// PTX helpers (base-target-safe)
// ============================================================================
__device__ __forceinline__ uint32_t smem_u32(const void* p) {
    uint32_t a;
    asm("{ .reg .u64 t; cvta.to.shared.u64 t, %1; cvt.u32.u64 %0, t; }"
        : "=r"(a) : "l"(p));
    return a;
}
__device__ __forceinline__ void cpasync16(uint32_t s, const void* g) {
    asm volatile("cp.async.cg.shared.global [%0], [%1], 16;" :: "r"(s), "l"(g));
}
#define CP_COMMIT() asm volatile("cp.async.commit_group;" ::: "memory")
#define CP_WAIT(n)  asm volatile("cp.async.wait_group %0;" :: "n"(n) : "memory")

__device__ __forceinline__ void ldsm4(uint32_t* r, uint32_t a) {
    asm volatile("ldmatrix.sync.aligned.m8n8.x4.shared.b16 {%0,%1,%2,%3}, [%4];"
        : "=r"(r[0]), "=r"(r[1]), "=r"(r[2]), "=r"(r[3]) : "r"(a));
}
__device__ __forceinline__ void ldsm2(uint32_t* r, uint32_t a) {
    asm volatile("ldmatrix.sync.aligned.m8n8.x2.shared.b16 {%0,%1}, [%2];"
        : "=r"(r[0]), "=r"(r[1]) : "r"(a));
}
// fp16 MMA (GEMMs + attention)
__device__ __forceinline__ void mma16816h(float* c, const uint32_t* a, const uint32_t* b) {
    asm volatile("mma.sync.aligned.m16n8k16.row.col.f32.f16.f16.f32 "
        "{%0,%1,%2,%3}, {%4,%5,%6,%7}, {%8,%9}, {%0,%1,%2,%3};"
        : "+f"(c[0]), "+f"(c[1]), "+f"(c[2]), "+f"(c[3])
        : "r"(a[0]), "r"(a[1]), "r"(a[2]), "r"(a[3]), "r"(b[0]), "r"(b[1]));
}

// ============================================================================
// HMMA fp16 split-2 GEMM: C[M,N] = A'[M,K2] * B'[N,K2]^T (fp32 accum).
// 4-stage cp.async ring, ONE barrier per K-step. CTA tile 128x128x32.
// MODE 1: QKV — add bias + scatter to q/k/v.   MODE 2: plain C store.
// ============================================================================
#define BK 32
#define ASTR 40
#define TILE_B16 (128*ASTR)
#define STAGE_B16 (2*TILE_B16)
#define STAGE_BYTES (STAGE_B16*2)
#define GSTAGES 4
#define GEMM_SMEM (GSTAGES*STAGE_BYTES)

template<int MODE>
__global__ void __launch_bounds__(256, 2)
hmma_gemm(const __half* __restrict__ Ag, const __half* __restrict__ Bg,
          const float* __restrict__ bias, float* __restrict__ C,
          float* __restrict__ q_out, float* __restrict__ k_out, float* __restrict__ v_out,
          int N)
{
    extern __shared__ __align__(16) __half smbuf[];

    const int tid  = threadIdx.x;
    const int lane = tid & 31;
    const int warp = tid >> 5;
    const int wm = warp >> 2;
    const int wn = warp & 3;
    const int m0 = blockIdx.y * 128;
    const int n0 = blockIdx.x * 128;

    const uint32_t smb = smem_u32(smbuf);
    const int cr = tid >> 2;
    const int ccn = tid & 3;
    const int KT = K2 / BK;            // 128

    auto prefetch = [&](int kt, int slot) {
        uint32_t base = smb + slot * STAGE_BYTES;
#pragma unroll
        for (int h = 0; h < 2; h++) {
            int r = cr + h * 64;
            cpasync16(base + (r * ASTR + ccn * 8) * 2,
                      Ag + (size_t)(m0 + r) * K2 + kt * BK + ccn * 8);
            cpasync16(base + TILE_B16*2 + (r * ASTR + ccn * 8) * 2,
                      Bg + (size_t)(n0 + r) * K2 + kt * BK + ccn * 8);
        }
    };

    float acc[4][4][4];
#pragma unroll
    for (int i = 0; i < 4; i++)
#pragma unroll
        for (int j = 0; j < 4; j++)
#pragma unroll
            for (int e = 0; e < 4; e++) acc[i][j][e] = 0.0f;

    const int l16 = lane & 15;
    const uint32_t a_off = (((wm * 64 + l16) * ASTR) + ((lane >> 4) * 8)) * 2;
    const uint32_t b_off = (((wn * 32 + (l16 & 7)) * ASTR) + ((l16 >> 3) * 8)) * 2;

    prefetch(0, 0); CP_COMMIT();
    prefetch(1, 1); CP_COMMIT();
    prefetch(2, 2); CP_COMMIT();

    for (int kt = 0; kt < KT; kt++) {
        CP_WAIT(2);
        __syncthreads();
        int pf = kt + 3;
        if (pf < KT) prefetch(pf, pf & 3);
        CP_COMMIT();

        uint32_t abase = smb + (kt & 3) * STAGE_BYTES + a_off;
        uint32_t bbase = smb + (kt & 3) * STAGE_BYTES + TILE_B16*2 + b_off;

#pragma unroll
        for (int k16 = 0; k16 < BK; k16 += 16) {
            uint32_t bfr[4][2];
#pragma unroll
            for (int nt = 0; nt < 4; nt++)
                ldsm2(bfr[nt], bbase + (nt * 8 * ASTR + k16) * 2);
#pragma unroll
            for (int mt = 0; mt < 4; mt++) {
                uint32_t afr[4];
                ldsm4(afr, abase + (mt * 16 * ASTR + k16) * 2);
#pragma unroll
                for (int nt = 0; nt < 4; nt++)
                    mma16816h(acc[mt][nt], afr, bfr[nt]);
            }
        }
    }

    const int g  = lane >> 2;
    const int c2 = (lane & 3) * 2;
#pragma unroll
    for (int mt = 0; mt < 4; mt++) {
#pragma unroll
        for (int nt = 0; nt < 4; nt++) {
#pragma unroll
            for (int i = 0; i < 2; i++) {
#pragma unroll
                for (int j = 0; j < 2; j++) {
                    int m = m0 + wm * 64 + mt * 16 + g + i * 8;
                    int n = n0 + wn * 32 + nt * 8 + c2 + j;
                    float v = acc[mt][nt][i * 2 + j];
                    if (MODE == 1) {
                        v += bias[n];
                        int head = n / (3 * HDIM);
                        int r3   = n % (3 * HDIM);
                        int part = r3 / HDIM;
                        int d    = r3 % HDIM;
                        int off  = (((m & 1) * NHEADS + head) * SEQ + (m >> 1)) * HDIM + d;
                        if      (part == 0) q_out[off] = v;
                        else if (part == 1) k_out[off] = v;
                        else                v_out[off] = v;
                    } else {
                        C[(size_t)m * N + n] = v;
                    }
                }
            }
        }
    }
}

// ---------------- fp16 split-2 conversion (vectorized) -----------------------
// PAT 0 (A): [hi|lo]    PAT 1 (B): [hi|hi]
template<int PAT>
__global__ void conv_split(const float* __restrict__ src,
                           __half* __restrict__ dst, int R, int K)
{
    int idx = blockIdx.x * blockDim.x + threadIdx.x;     // float4 index
    int kq = K >> 2;
    if (idx >= R * kq) return;
    int row = idx / kq, c4 = idx - row * kq;
    float4 x = ((const float4*)src)[idx];
    __half hi[4];
    hi[0] = __float2half(x.x); hi[1] = __float2half(x.y);
    hi[2] = __float2half(x.z); hi[3] = __float2half(x.w);
    size_t base = (size_t)row * (2*K) + c4 * 4;
    *(uint2*)(dst + base) = *(uint2*)hi;
    if (PAT == 0) {
        __half lo[4];
        lo[0] = __float2half(x.x - __half2float(hi[0]));
        lo[1] = __float2half(x.y - __half2float(hi[1]));
        lo[2] = __float2half(x.z - __half2float(hi[2]));
        lo[3] = __float2half(x.w - __half2float(hi[3]));
        *(uint2*)(dst + base + K) = *(uint2*)lo;
    } else {
        *(uint2*)(dst + base + K) = *(uint2*)hi;
    }
}

// ---------------- RoPE tables + apply ----------------------------------------
__global__ void rope_table_kernel() {
    __shared__ float invf[64];
    if (threadIdx.x < 64)
        invf[threadIdx.x] = (float)pow(10000.0, -((double)threadIdx.x) / 64.0);
    __syncthreads();
    int idx = blockIdx.x * blockDim.x + threadIdx.x;
    if (idx >= SEQ * 64) return;
    int s = idx >> 6;
    int i = idx & 63;
    float theta = (float)s * invf[i];
    g_cos[idx] = cosf(theta);
    g_sin[idx] = sinf(theta);
}

__device__ __forceinline__ void split_store_h(__half* hi, __half* lo,
                                              int off, float x) {
    __half h = __float2half(x);
    hi[off] = h;
    lo[off] = __float2half(x - __half2float(h));
}

__global__ void rope_apply_kernel() {
    int idx = blockIdx.x * blockDim.x + threadIdx.x;
    int total = NBH*SEQ*64;
    if (idx >= total) return;
    int i = idx & 63;
    int rowid = idx >> 6;
    int s = rowid & (SEQ - 1);
    float c  = g_cos[s*64 + i];
    float sn = g_sin[s*64 + i];
    int base = rowid * HDIM;
    float q1 = g_q[base + i], q2 = g_q[base + 64 + i];
    float k1 = g_k[base + i], k2 = g_k[base + 64 + i];
    split_store_h(gq_hi, gq_lo, base + i,      q1*c - q2*sn);
    split_store_h(gq_hi, gq_lo, base + 64 + i, q2*c + q1*sn);
    split_store_h(gk_hi, gk_lo, base + i,      k1*c - k2*sn);
    split_store_h(gk_hi, gk_lo, base + 64 + i, k2*c + k1*sn);
}

// ---------------- V transpose + split: g_v[bh][s][d] -> gvt[bh][d][s] --------
__global__ void v_transpose_split() {
    __shared__ float t[32][33];
    int bh = blockIdx.z;
    int s0 = blockIdx.x * 32, d0 = blockIdx.y * 32;
    int tx = threadIdx.x, ty = threadIdx.y;   // 32 x 8
#pragma unroll
    for (int i = 0; i < 32; i += 8)
        t[ty + i][tx] = g_v[((size_t)bh*SEQ + s0 + ty + i) * HDIM + d0 + tx];
    __syncthreads();
#pragma unroll
    for (int i = 0; i < 32; i += 8) {
        float x = t[tx][ty + i];
        size_t off = ((size_t)bh*HDIM + d0 + ty + i) * SEQ + s0 + tx;
        __half h = __float2half(x);
        gvt_hi[off] = h;
        gvt_lo[off] = __float2half(x - __half2float(h));
    }
}

// ============================================================================
// HMMA causal flash attention, fp16 split-2 on QK^T and PV, cp.async pipelined.
// CTA: 128 q-rows x one bh. 256 threads (8 warps, 4x2). Key tiles of 64.
// Epilogue emits fp16 split-2 dense-GEMM A' rows.
// ============================================================================
#define BQ 128
#define BT 64
#define QSTR 136
#define KSTR 136
#define VSTR 72
#define SSTR 68
#define PSTR 72

#define OFF_QHI 0
#define SZ_Q    (BQ*QSTR*2)
#define OFF_QLO (OFF_QHI + SZ_Q)
#define OFF_KHI (OFF_QLO + SZ_Q)
#define SZ_K    (BT*KSTR*2)
#define OFF_KLO (OFF_KHI + SZ_K)
#define OFF_VHI (OFF_KLO + SZ_K)
#define SZ_V    (HDIM*VSTR*2)
#define OFF_VLO (OFF_VHI + SZ_V)
#define OFF_SS  (OFF_VLO + SZ_V)
#define SZ_SS   (BQ*SSTR*4)
#define OFF_PHI (OFF_SS + SZ_SS)
#define SZ_P    (BQ*PSTR*2)
#define OFF_PLO (OFF_PHI + SZ_P)
#define OFF_MR  (OFF_PLO + SZ_P)
#define OFF_LR  (OFF_MR + BQ*4)
#define OFF_SC  (OFF_LR + BQ*4)
#define ATTN_SMEM (OFF_SC + BQ*4)

__global__ void __launch_bounds__(256, 1) attn_hmma(__half* __restrict__ Aout) {
    extern __shared__ char smem[];
    const uint32_t sb = smem_u32(smem);

    const int tid  = threadIdx.x;
    const int lane = tid & 31;
    const int warp = tid >> 5;
    const int wm = warp >> 1;
    const int wn = warp & 1;
    const int qt = gridDim.x - 1 - blockIdx.x;   // heavy tiles first
    const int bh = blockIdx.y;
    const int q0 = qt * BQ;

    const int l16 = lane & 15;
    const int g   = lane >> 2;
    const int c2  = (lane & 3) * 2;

    __half* s_qhi = (__half*)(smem + OFF_QHI);
    __half* s_qlo = (__half*)(smem + OFF_QLO);
    float*  s_ss  = (float*)(smem + OFF_SS);
    __half* s_phi = (__half*)(smem + OFF_PHI);
    __half* s_plo = (__half*)(smem + OFF_PLO);
    float*  mrow  = (float*)(smem + OFF_MR);
    float*  lrow  = (float*)(smem + OFF_LR);
    float*  srow  = (float*)(smem + OFF_SC);

    const __half* Kh = gk_hi + (size_t)bh*SEQ*HDIM;
    const __half* Kl = gk_lo + (size_t)bh*SEQ*HDIM;
    const __half* Vh = gvt_hi + (size_t)bh*HDIM*SEQ;
    const __half* Vl = gvt_lo + (size_t)bh*HDIM*SEQ;

    auto prefetch_k = [&](int k0) {
#pragma unroll
        for (int it = 0; it < 4; it++) {
            int t = tid + it*256;
            int row = t >> 4, cc = t & 15;
            cpasync16(sb + OFF_KHI + (row*KSTR + cc*8)*2,
                      Kh + (size_t)(k0 + row)*HDIM + cc*8);
        }
#pragma unroll
        for (int it = 0; it < 4; it++) {
            int t = tid + it*256;
            int row = t >> 4, cc = t & 15;
            cpasync16(sb + OFF_KLO + (row*KSTR + cc*8)*2,
                      Kl + (size_t)(k0 + row)*HDIM + cc*8);
        }
    };
    auto prefetch_v = [&](int k0) {
#pragma unroll
        for (int it = 0; it < 4; it++) {
            int t = tid + it*256;
            int d = t >> 3, cc = t & 7;
            cpasync16(sb + OFF_VHI + (d*VSTR + cc*8)*2,
                      Vh + (size_t)d*SEQ + k0 + cc*8);
        }
#pragma unroll
        for (int it = 0; it < 4; it++) {
            int t = tid + it*256;
            int d = t >> 3, cc = t & 7;
            cpasync16(sb + OFF_VLO + (d*VSTR + cc*8)*2,
                      Vl + (size_t)d*SEQ + k0 + cc*8);
        }
    };

    prefetch_k(0); CP_COMMIT();
    prefetch_v(0); CP_COMMIT();

    {
        const __half* qh = gq_hi + ((size_t)bh*SEQ + q0) * HDIM;
        const __half* ql = gq_lo + ((size_t)bh*SEQ + q0) * HDIM;
#pragma unroll
        for (int it = 0; it < 8; it++) {
            int t = tid + it*256;
            int row = t >> 4, cc = t & 15;
            *(uint4*)(s_qhi + row*QSTR + cc*8) = *(const uint4*)(qh + row*HDIM + cc*8);
        }
#pragma unroll
        for (int it = 0; it < 8; it++) {
            int t = tid + it*256;
            int row = t >> 4, cc = t & 15;
            *(uint4*)(s_qlo + row*QSTR + cc*8) = *(const uint4*)(ql + row*HDIM + cc*8);
        }
    }
    if (tid < BQ) { mrow[tid] = -1e30f; lrow[tid] = 0.0f; }

    float acc_o[2][8][4];
#pragma unroll
    for (int mt = 0; mt < 2; mt++)
#pragma unroll
        for (int nt = 0; nt < 8; nt++)
#pragma unroll
            for (int e = 0; e < 4; e++) acc_o[mt][nt][e] = 0.0f;

    const float rnorm = 0.088388347648318447f;

    const uint32_t qhi_b = sb + OFF_QHI + (((wm*32 + l16)*QSTR) + (lane>>4)*8)*2;
    const uint32_t qlo_b = sb + OFF_QLO + (((wm*32 + l16)*QSTR) + (lane>>4)*8)*2;
    const uint32_t khi_b = sb + OFF_KHI + (((wn*32 + (l16&7))*KSTR) + (l16>>3)*8)*2;
    const uint32_t klo_b = sb + OFF_KLO + (((wn*32 + (l16&7))*KSTR) + (l16>>3)*8)*2;
    const uint32_t phi_b = sb + OFF_PHI + (((wm*32 + l16)*PSTR) + (lane>>4)*8)*2;
    const uint32_t plo_b = sb + OFF_PLO + (((wm*32 + l16)*PSTR) + (lane>>4)*8)*2;
    const uint32_t vhi_b = sb + OFF_VHI + (((wn*64 + (l16&7))*VSTR) + (l16>>3)*8)*2;
    const uint32_t vlo_b = sb + OFF_VLO + (((wn*64 + (l16&7))*VSTR) + (l16>>3)*8)*2;

    const int ntiles = 2*qt + 2;
    for (int kt = 0; kt < ntiles; kt++) {
        const int k0 = kt * BT;

        CP_WAIT(1);          // K(kt) resident
        __syncthreads();

        // ---- S = Q K^T (fp16 split-2: hi*hi + lo*hi) ----
        float sacc[2][4][4];
#pragma unroll
        for (int mt = 0; mt < 2; mt++)
#pragma unroll
            for (int nt = 0; nt < 4; nt++)
#pragma unroll
                for (int e = 0; e < 4; e++) sacc[mt][nt][e] = 0.0f;

#pragma unroll
        for (int k16 = 0; k16 < HDIM; k16 += 16) {
            uint32_t bhi[4][2], blo[4][2];
#pragma unroll
            for (int nt = 0; nt < 4; nt++) {
                ldsm2(bhi[nt], khi_b + (nt*8*KSTR + k16)*2);
                ldsm2(blo[nt], klo_b + (nt*8*KSTR + k16)*2);
            }
#pragma unroll
            for (int mt = 0; mt < 2; mt++) {
                uint32_t ahi[4], alo[4];
                ldsm4(ahi, qhi_b + (mt*16*QSTR + k16)*2);
                ldsm4(alo, qlo_b + (mt*16*QSTR + k16)*2);
#pragma unroll
                for (int nt = 0; nt < 4; nt++) {
                    mma16816h(sacc[mt][nt], ahi, bhi[nt]);
                    mma16816h(sacc[mt][nt], alo, bhi[nt]);
                    mma16816h(sacc[mt][nt], ahi, blo[nt]);
                }
            }
        }

        // ---- S -> smem with scale + causal mask ----
#pragma unroll
        for (int mt = 0; mt < 2; mt++) {
#pragma unroll
            for (int nt = 0; nt < 4; nt++) {
#pragma unroll
                for (int i = 0; i < 2; i++) {
#pragma unroll
                    for (int j = 0; j < 2; j++) {
                        int r = wm*32 + mt*16 + g + i*8;
                        int c = wn*32 + nt*8 + c2 + j;
                        float v = sacc[mt][nt][i*2 + j] * rnorm;
                        if (k0 + c > q0 + r) v = -10000.0f;
                        s_ss[r*SSTR + c] = v;
                    }
                }
            }
        }
        __syncthreads();     // S visible; K(kt) reads retired

        if (kt + 1 < ntiles) prefetch_k(k0 + BT);
        CP_COMMIT();

        // ---- row softmax + P split (fp16): 2 threads per row, __expf ----
        {
            int r  = tid >> 1;
            int hf = tid & 1;
            float* row = s_ss + r*SSTR + hf*32;
            float m_old = mrow[r];
            float mx = m_old;
#pragma unroll 8
            for (int c = 0; c < 32; c++) mx = fmaxf(mx, row[c]);
            mx = fmaxf(mx, __shfl_xor_sync(0xFFFFFFFFu, mx, 1));
            float sum = 0.0f;
            __half* ph = s_phi + r*PSTR + hf*32;
            __half* pl = s_plo + r*PSTR + hf*32;
#pragma unroll 8
            for (int c = 0; c < 32; c++) {
                float p = __expf(row[c] - mx);
                sum += p;
                __half h = __float2half(p);
                ph[c] = h;
                pl[c] = __float2half(p - __half2float(h));
            }
            sum += __shfl_xor_sync(0xFFFFFFFFu, sum, 1);
            if (hf == 0) {
                float scl = __expf(m_old - mx);
                mrow[r] = mx;
                lrow[r] = lrow[r] * scl + sum;
                srow[r] = scl;
            }
        }

        CP_WAIT(1);          // V(kt) resident
        __syncthreads();

        // ---- rescale acc_o, then O += P·Vt (fp16 split-2) ----
#pragma unroll
        for (int mt = 0; mt < 2; mt++) {
#pragma unroll
            for (int i = 0; i < 2; i++) {
                float s_ = srow[wm*32 + mt*16 + g + i*8];
#pragma unroll
                for (int nt = 0; nt < 8; nt++) {
                    acc_o[mt][nt][i*2 + 0] *= s_;
                    acc_o[mt][nt][i*2 + 1] *= s_;
                }
            }
        }
#pragma unroll
        for (int k16 = 0; k16 < BT; k16 += 16) {
            uint32_t bvh[8][2], bvl[8][2];
#pragma unroll
            for (int nt = 0; nt < 8; nt++) {
                ldsm2(bvh[nt], vhi_b + (nt*8*VSTR + k16)*2);
                ldsm2(bvl[nt], vlo_b + (nt*8*VSTR + k16)*2);
            }
#pragma unroll
            for (int mt = 0; mt < 2; mt++) {
                uint32_t aph[4], apl[4];
                ldsm4(aph, phi_b + (mt*16*PSTR + k16)*2);
                ldsm4(apl, plo_b + (mt*16*PSTR + k16)*2);
#pragma unroll
                for (int nt = 0; nt < 8; nt++) {
                    mma16816h(acc_o[mt][nt], aph, bvh[nt]);
                    mma16816h(acc_o[mt][nt], apl, bvh[nt]);
                    mma16816h(acc_o[mt][nt], aph, bvl[nt]);
                }
            }
        }
        __syncthreads();

        if (kt + 1 < ntiles) prefetch_v(k0 + BT);
        CP_COMMIT();
    }

    // ---- finalize: divide by l, write fp16 split-2 dense-GEMM A' ----
    const int b_idx = bh / NHEADS;
    const int h_idx = bh % NHEADS;
#pragma unroll
    for (int mt = 0; mt < 2; mt++) {
#pragma unroll
        for (int i = 0; i < 2; i++) {
            int r = wm*32 + mt*16 + g + i*8;
            float linv = 1.0f / lrow[r];
            int s_idx = q0 + r;
            size_t tok = (size_t)(s_idx*BATCH + b_idx);
            __half* dst = Aout + tok*K2 + h_idx*HDIM + wn*64;
#pragma unroll
            for (int nt = 0; nt < 8; nt++) {
#pragma unroll
                for (int j = 0; j < 2; j++) {
                    float v = acc_o[mt][nt][i*2 + j] * linv;
                    __half h = __float2half(v);
                    __half l = __float2half(v - __half2float(h));
                    int cc = nt*8 + c2 + j;
                    dst[cc]       = h;
                    dst[HID + cc] = l;
                }
            }
        }
    }
}

// ---------------- tail bias ---------------------------------------------------
__global__ void tail_copy(const float* __restrict__ src, float* __restrict__ dst, int n) {
    int i = blockIdx.x * blockDim.x + threadIdx.x;
    if (i < n) dst[i] = src[i];
}

// ---------------- launch -------------------------------------------------------
extern "C" void kernel_launch(void* const* d_in, const int* in_sizes, int n_in,
                              void* d_out, int out_size)
{
    const float* hidden  = (const float*)d_in[0];
    const float* w_qkv   = (const float*)d_in[2];
    const float* b_qkv   = (const float*)d_in[3];
    const float* w_dense = (const float*)d_in[4];
    const float* b_dense = (const float*)d_in[5];
    float* out = (float*)d_out;

    void *pA, *pBq, *pBd, *pQ, *pK, *pV;
    cudaGetSymbolAddress(&pA,   g_Abuf);
    cudaGetSymbolAddress(&pBq,  g_Bq);
    cudaGetSymbolAddress(&pBd,  g_Bd);
    cudaGetSymbolAddress(&pQ,   g_q);
    cudaGetSymbolAddress(&pK,   g_k);
    cudaGetSymbolAddress(&pV,   g_v);

    cudaFuncSetAttribute(hmma_gemm<1>, cudaFuncAttributeMaxDynamicSharedMemorySize, GEMM_SMEM);
    cudaFuncSetAttribute(hmma_gemm<2>, cudaFuncAttributeMaxDynamicSharedMemorySize, GEMM_SMEM);
    cudaFuncSetAttribute(attn_hmma, cudaFuncAttributeMaxDynamicSharedMemorySize, ATTN_SMEM);

    // 1) split-convert A (hidden) and B (w_qkv) to fp16 split-2
    conv_split<0><<<(TOK*HID/4 + 255)/256, 256>>>(hidden, (__half*)pA, TOK, HID);
    conv_split<1><<<(QKV_N*HID/4 + 255)/256, 256>>>(w_qkv, (__half*)pBq, QKV_N, HID);

    // 2) QKV projection (fp16 HMMA, bias + scatter epilogue)
    hmma_gemm<1><<<dim3(QKV_N/128, TOK/128), 256, GEMM_SMEM>>>(
        (const __half*)pA, (const __half*)pBq, b_qkv, nullptr,
        (float*)pQ, (float*)pK, (float*)pV, QKV_N);

    // 3) RoPE (emits fp16 hi/lo Q,K) + V transpose/split (fp16)
    rope_table_kernel<<<(SEQ*64 + 255)/256, 256>>>();
    rope_apply_kernel<<<(NBH*SEQ*64 + 255)/256, 256>>>();
    v_transpose_split<<<dim3(SEQ/32, HDIM/32, NBH), dim3(32, 8)>>>();

    // 4) causal attention (fp16 split-2, cp.async pipelined)
    attn_hmma<<<dim3(SEQ/BQ, NBH), 256, ATTN_SMEM>>>((__half*)pA);

    // 5) w_dense split + dense GEMM (fp16 HMMA)
    conv_split<1><<<(HID*HID/4 + 255)/256, 256>>>(w_dense, (__half*)pBd, HID, HID);
    hmma_gemm<2><<<dim3(HID/128, TOK/128), 256, GEMM_SMEM>>>(
        (const __half*)pA, (const __half*)pBd, nullptr, out,
        nullptr, nullptr, nullptr, HID);

    // 6) bias tail if harness flattens the (output, bias) tuple
    int extra = out_size - TOK*HID;
    if (extra > 0)
        tail_copy<<<(extra + 255)/256, 256>>>(b_dense, out + (size_t)TOK*HID, extra);
    (void)in_sizes; (void)n_in;
}

// round 10
// speedup vs baseline: 3.5920x; 1.0880x over previous
#include <cuda_runtime.h>
#include <cuda_bf16.h>
#include <cuda_fp16.h>
#include <math.h>
#include <stdint.h>

#define SEQ     2048
#define BATCH   2
#define HID     2048
#define NHEADS  16
#define HDIM    128
#define TOK     (SEQ*BATCH)     // 4096
#define QKV_N   (3*HID)         // 6144
#define K2      (2*HID)         // fp16 split-2 K' = 4096
#define NBH     (BATCH*NHEADS)  // 32

// ---------------- scratch (device globals; no runtime allocs allowed) -------
__device__ float g_q[NBH*SEQ*HDIM];
__device__ float g_k[NBH*SEQ*HDIM];
__device__ float g_v[NBH*SEQ*HDIM];
__device__ float g_cos[SEQ*64];
__device__ float g_sin[SEQ*64];
// fp16 split-2 operand buffers (GEMMs)
__device__ __align__(1024) __half g_Abuf[TOK*K2];
__device__ __align__(1024) __half g_Bq[QKV_N*K2];
__device__ __align__(1024) __half g_Bd[HID*K2];
// attention operands: Q split-2 (hi+lo), K/V hi-only
__device__ __align__(16) __half gq_hi[NBH*SEQ*HDIM];
__device__ __align__(16) __half gq_lo[NBH*SEQ*HDIM];
__device__ __align__(16) __half gk_hi[NBH*SEQ*HDIM];
__device__ __align__(16) __half gvt_hi[NBH*HDIM*SEQ];   // [bh][d][s]

// ============================================================================
// PTX helpers (base-target-safe)
// ============================================================================
__device__ __forceinline__ uint32_t smem_u32(const void* p) {
    uint32_t a;
    asm("{ .reg .u64 t; cvta.to.shared.u64 t, %1; cvt.u32.u64 %0, t; }"
        : "=r"(a) : "l"(p));
    return a;
}
__device__ __forceinline__ void cpasync16(uint32_t s, const void* g) {
    asm volatile("cp.async.cg.shared.global [%0], [%1], 16;" :: "r"(s), "l"(g));
}
#define CP_COMMIT() asm volatile("cp.async.commit_group;" ::: "memory")
#define CP_WAIT(n)  asm volatile("cp.async.wait_group %0;" :: "n"(n) : "memory")

__device__ __forceinline__ void ldsm4(uint32_t* r, uint32_t a) {
    asm volatile("ldmatrix.sync.aligned.m8n8.x4.shared.b16 {%0,%1,%2,%3}, [%4];"
        : "=r"(r[0]), "=r"(r[1]), "=r"(r[2]), "=r"(r[3]) : "r"(a));
}
__device__ __forceinline__ void ldsm2(uint32_t* r, uint32_t a) {
    asm volatile("ldmatrix.sync.aligned.m8n8.x2.shared.b16 {%0,%1}, [%2];"
        : "=r"(r[0]), "=r"(r[1]) : "r"(a));
}
// fp16 MMA (GEMMs + attention)
__device__ __forceinline__ void mma16816h(float* c, const uint32_t* a, const uint32_t* b) {
    asm volatile("mma.sync.aligned.m16n8k16.row.col.f32.f16.f16.f32 "
        "{%0,%1,%2,%3}, {%4,%5,%6,%7}, {%8,%9}, {%0,%1,%2,%3};"
        : "+f"(c[0]), "+f"(c[1]), "+f"(c[2]), "+f"(c[3])
        : "r"(a[0]), "r"(a[1]), "r"(a[2]), "r"(a[3]), "r"(b[0]), "r"(b[1]));
}

// ============================================================================
// HMMA fp16 split-2 GEMM: unchanged from R9 (passing, ~390 TF/s effective)
// ============================================================================
#define BK 32
#define ASTR 40
#define TILE_B16 (128*ASTR)
#define STAGE_B16 (2*TILE_B16)
#define STAGE_BYTES (STAGE_B16*2)
#define GSTAGES 4
#define GEMM_SMEM (GSTAGES*STAGE_BYTES)

template<int MODE>
__global__ void __launch_bounds__(256, 2)
hmma_gemm(const __half* __restrict__ Ag, const __half* __restrict__ Bg,
          const float* __restrict__ bias, float* __restrict__ C,
          float* __restrict__ q_out, float* __restrict__ k_out, float* __restrict__ v_out,
          int N)
{
    extern __shared__ __align__(16) __half smbuf[];

    const int tid  = threadIdx.x;
    const int lane = tid & 31;
    const int warp = tid >> 5;
    const int wm = warp >> 2;
    const int wn = warp & 3;
    const int m0 = blockIdx.y * 128;
    const int n0 = blockIdx.x * 128;

    const uint32_t smb = smem_u32(smbuf);
    const int cr = tid >> 2;
    const int ccn = tid & 3;
    const int KT = K2 / BK;            // 128

    auto prefetch = [&](int kt, int slot) {
        uint32_t base = smb + slot * STAGE_BYTES;
#pragma unroll
        for (int h = 0; h < 2; h++) {
            int r = cr + h * 64;
            cpasync16(base + (r * ASTR + ccn * 8) * 2,
                      Ag + (size_t)(m0 + r) * K2 + kt * BK + ccn * 8);
            cpasync16(base + TILE_B16*2 + (r * ASTR + ccn * 8) * 2,
                      Bg + (size_t)(n0 + r) * K2 + kt * BK + ccn * 8);
        }
    };

    float acc[4][4][4];
#pragma unroll
    for (int i = 0; i < 4; i++)
#pragma unroll
        for (int j = 0; j < 4; j++)
#pragma unroll
            for (int e = 0; e < 4; e++) acc[i][j][e] = 0.0f;

    const int l16 = lane & 15;
    const uint32_t a_off = (((wm * 64 + l16) * ASTR) + ((lane >> 4) * 8)) * 2;
    const uint32_t b_off = (((wn * 32 + (l16 & 7)) * ASTR) + ((l16 >> 3) * 8)) * 2;

    prefetch(0, 0); CP_COMMIT();
    prefetch(1, 1); CP_COMMIT();
    prefetch(2, 2); CP_COMMIT();

    for (int kt = 0; kt < KT; kt++) {
        CP_WAIT(2);
        __syncthreads();
        int pf = kt + 3;
        if (pf < KT) prefetch(pf, pf & 3);
        CP_COMMIT();

        uint32_t abase = smb + (kt & 3) * STAGE_BYTES + a_off;
        uint32_t bbase = smb + (kt & 3) * STAGE_BYTES + TILE_B16*2 + b_off;

#pragma unroll
        for (int k16 = 0; k16 < BK; k16 += 16) {
            uint32_t bfr[4][2];
#pragma unroll
            for (int nt = 0; nt < 4; nt++)
                ldsm2(bfr[nt], bbase + (nt * 8 * ASTR + k16) * 2);
#pragma unroll
            for (int mt = 0; mt < 4; mt++) {
                uint32_t afr[4];
                ldsm4(afr, abase + (mt * 16 * ASTR + k16) * 2);
#pragma unroll
                for (int nt = 0; nt < 4; nt++)
                    mma16816h(acc[mt][nt], afr, bfr[nt]);
            }
        }
    }

    const int g  = lane >> 2;
    const int c2 = (lane & 3) * 2;
#pragma unroll
    for (int mt = 0; mt < 4; mt++) {
#pragma unroll
        for (int nt = 0; nt < 4; nt++) {
#pragma unroll
            for (int i = 0; i < 2; i++) {
#pragma unroll
                for (int j = 0; j < 2; j++) {
                    int m = m0 + wm * 64 + mt * 16 + g + i * 8;
                    int n = n0 + wn * 32 + nt * 8 + c2 + j;
                    float v = acc[mt][nt][i * 2 + j];
                    if (MODE == 1) {
                        v += bias[n];
                        int head = n / (3 * HDIM);
                        int r3   = n % (3 * HDIM);
                        int part = r3 / HDIM;
                        int d    = r3 % HDIM;
                        int off  = (((m & 1) * NHEADS + head) * SEQ + (m >> 1)) * HDIM + d;
                        if      (part == 0) q_out[off] = v;
                        else if (part == 1) k_out[off] = v;
                        else                v_out[off] = v;
                    } else {
                        C[(size_t)m * N + n] = v;
                    }
                }
            }
        }
    }
}

// ---------------- fp16 split-2 conversion (vectorized) -----------------------
// PAT 0 (A): [hi|lo]    PAT 1 (B): [hi|hi]
template<int PAT>
__global__ void conv_split(const float* __restrict__ src,
                           __half* __restrict__ dst, int R, int K)
{
    int idx = blockIdx.x * blockDim.x + threadIdx.x;     // float4 index
    int kq = K >> 2;
    if (idx >= R * kq) return;
    int row = idx / kq, c4 = idx - row * kq;
    float4 x = ((const float4*)src)[idx];
    __half hi[4];
    hi[0] = __float2half(x.x); hi[1] = __float2half(x.y);
    hi[2] = __float2half(x.z); hi[3] = __float2half(x.w);
    size_t base = (size_t)row * (2*K) + c4 * 4;
    *(uint2*)(dst + base) = *(uint2*)hi;
    if (PAT == 0) {
        __half lo[4];
        lo[0] = __float2half(x.x - __half2float(hi[0]));
        lo[1] = __float2half(x.y - __half2float(hi[1]));
        lo[2] = __float2half(x.z - __half2float(hi[2]));
        lo[3] = __float2half(x.w - __half2float(hi[3]));
        *(uint2*)(dst + base + K) = *(uint2*)lo;
    } else {
        *(uint2*)(dst + base + K) = *(uint2*)hi;
    }
}

// ---------------- RoPE tables + apply ----------------------------------------
__global__ void rope_table_kernel() {
    __shared__ float invf[64];
    if (threadIdx.x < 64)
        invf[threadIdx.x] = (float)pow(10000.0, -((double)threadIdx.x) / 64.0);
    __syncthreads();
    int idx = blockIdx.x * blockDim.x + threadIdx.x;
    if (idx >= SEQ * 64) return;
    int s = idx >> 6;
    int i = idx & 63;
    float theta = (float)s * invf[i];
    g_cos[idx] = cosf(theta);
    g_sin[idx] = sinf(theta);
}

__device__ __forceinline__ void split_store_h(__half* hi, __half* lo,
                                              int off, float x) {
    __half h = __float2half(x);
    hi[off] = h;
    lo[off] = __float2half(x - __half2float(h));
}

__global__ void rope_apply_kernel() {
    int idx = blockIdx.x * blockDim.x + threadIdx.x;
    int total = NBH*SEQ*64;
    if (idx >= total) return;
    int i = idx & 63;
    int rowid = idx >> 6;
    int s = rowid & (SEQ - 1);
    float c  = g_cos[s*64 + i];
    float sn = g_sin[s*64 + i];
    int base = rowid * HDIM;
    float q1 = g_q[base + i], q2 = g_q[base + 64 + i];
    float k1 = g_k[base + i], k2 = g_k[base + 64 + i];
    split_store_h(gq_hi, gq_lo, base + i,      q1*c - q2*sn);
    split_store_h(gq_hi, gq_lo, base + 64 + i, q2*c + q1*sn);
    gk_hi[base + i]      = __float2half(k1*c - k2*sn);    // K hi-only
    gk_hi[base + 64 + i] = __float2half(k2*c + k1*sn);
}

// ---------------- V transpose: g_v[bh][s][d] -> gvt_hi[bh][d][s] -------------
__global__ void v_transpose_split() {
    __shared__ float t[32][33];
    int bh = blockIdx.z;
    int s0 = blockIdx.x * 32, d0 = blockIdx.y * 32;
    int tx = threadIdx.x, ty = threadIdx.y;   // 32 x 8
#pragma unroll
    for (int i = 0; i < 32; i += 8)
        t[ty + i][tx] = g_v[((size_t)bh*SEQ + s0 + ty + i) * HDIM + d0 + tx];
    __syncthreads();
#pragma unroll
    for (int i = 0; i < 32; i += 8) {
        float x = t[tx][ty + i];
        size_t off = ((size_t)bh*HDIM + d0 + ty + i) * SEQ + s0 + tx;
        gvt_hi[off] = __float2half(x);                    // V hi-only
    }
}

// ============================================================================
// HMMA causal flash attention, fp16 split-2:
//   S = q_hi*k_hi + q_lo*k_hi   (K hi-only)
//   O = p_hi*v_hi + p_lo*v_hi   (V hi-only)
// cp.async pipelined K/V; epilogue emits fp16 split-2 dense-GEMM A'.
// ============================================================================
#define BQ 128
#define BT 64
#define QSTR 136
#define KSTR 136
#define VSTR 72
#define SSTR 68
#define PSTR 72

#define OFF_QHI 0
#define SZ_Q    (BQ*QSTR*2)
#define OFF_QLO (OFF_QHI + SZ_Q)
#define OFF_KHI (OFF_QLO + SZ_Q)
#define SZ_K    (BT*KSTR*2)
#define OFF_VHI (OFF_KHI + SZ_K)
#define SZ_V    (HDIM*VSTR*2)
#define OFF_SS  (OFF_VHI + SZ_V)
#define SZ_SS   (BQ*SSTR*4)
#define OFF_PHI (OFF_SS + SZ_SS)
#define SZ_P    (BQ*PSTR*2)
#define OFF_PLO (OFF_PHI + SZ_P)
#define OFF_MR  (OFF_PLO + SZ_P)
#define OFF_LR  (OFF_MR + BQ*4)
#define OFF_SC  (OFF_LR + BQ*4)
#define ATTN_SMEM (OFF_SC + BQ*4)

__global__ void __launch_bounds__(256, 1) attn_hmma(__half* __restrict__ Aout) {
    extern __shared__ char smem[];
    const uint32_t sb = smem_u32(smem);

    const int tid  = threadIdx.x;
    const int lane = tid & 31;
    const int warp = tid >> 5;
    const int wm = warp >> 1;
    const int wn = warp & 1;
    const int qt = gridDim.x - 1 - blockIdx.x;   // heavy tiles first
    const int bh = blockIdx.y;
    const int q0 = qt * BQ;

    const int l16 = lane & 15;
    const int g   = lane >> 2;
    const int c2  = (lane & 3) * 2;

    __half* s_qhi = (__half*)(smem + OFF_QHI);
    __half* s_qlo = (__half*)(smem + OFF_QLO);
    float*  s_ss  = (float*)(smem + OFF_SS);
    __half* s_phi = (__half*)(smem + OFF_PHI);
    __half* s_plo = (__half*)(smem + OFF_PLO);
    float*  mrow  = (float*)(smem + OFF_MR);
    float*  lrow  = (float*)(smem + OFF_LR);
    float*  srow  = (float*)(smem + OFF_SC);

    const __half* Kh = gk_hi + (size_t)bh*SEQ*HDIM;
    const __half* Vh = gvt_hi + (size_t)bh*HDIM*SEQ;

    // K hi tile: 64 rows x 256B; 4 chunks per thread
    auto prefetch_k = [&](int k0) {
#pragma unroll
        for (int it = 0; it < 4; it++) {
            int t = tid + it*256;
            int row = t >> 4, cc = t & 15;
            cpasync16(sb + OFF_KHI + (row*KSTR + cc*8)*2,
                      Kh + (size_t)(k0 + row)*HDIM + cc*8);
        }
    };
    // V hi tile: 128 d-rows x 128B
    auto prefetch_v = [&](int k0) {
#pragma unroll
        for (int it = 0; it < 4; it++) {
            int t = tid + it*256;
            int d = t >> 3, cc = t & 7;
            cpasync16(sb + OFF_VHI + (d*VSTR + cc*8)*2,
                      Vh + (size_t)d*SEQ + k0 + cc*8);
        }
    };

    prefetch_k(0); CP_COMMIT();
    prefetch_v(0); CP_COMMIT();

    {
        const __half* qh = gq_hi + ((size_t)bh*SEQ + q0) * HDIM;
        const __half* ql = gq_lo + ((size_t)bh*SEQ + q0) * HDIM;
#pragma unroll
        for (int it = 0; it < 8; it++) {
            int t = tid + it*256;
            int row = t >> 4, cc = t & 15;
            *(uint4*)(s_qhi + row*QSTR + cc*8) = *(const uint4*)(qh + row*HDIM + cc*8);
        }
#pragma unroll
        for (int it = 0; it < 8; it++) {
            int t = tid + it*256;
            int row = t >> 4, cc = t & 15;
            *(uint4*)(s_qlo + row*QSTR + cc*8) = *(const uint4*)(ql + row*HDIM + cc*8);
        }
    }
    if (tid < BQ) { mrow[tid] = -1e30f; lrow[tid] = 0.0f; }

    float acc_o[2][8][4];
#pragma unroll
    for (int mt = 0; mt < 2; mt++)
#pragma unroll
        for (int nt = 0; nt < 8; nt++)
#pragma unroll
            for (int e = 0; e < 4; e++) acc_o[mt][nt][e] = 0.0f;

    const float rnorm = 0.088388347648318447f;

    const uint32_t qhi_b = sb + OFF_QHI + (((wm*32 + l16)*QSTR) + (lane>>4)*8)*2;
    const uint32_t qlo_b = sb + OFF_QLO + (((wm*32 + l16)*QSTR) + (lane>>4)*8)*2;
    const uint32_t khi_b = sb + OFF_KHI + (((wn*32 + (l16&7))*KSTR) + (l16>>3)*8)*2;
    const uint32_t phi_b = sb + OFF_PHI + (((wm*32 + l16)*PSTR) + (lane>>4)*8)*2;
    const uint32_t plo_b = sb + OFF_PLO + (((wm*32 + l16)*PSTR) + (lane>>4)*8)*2;
    const uint32_t vhi_b = sb + OFF_VHI + (((wn*64 + (l16&7))*VSTR) + (l16>>3)*8)*2;

    const int ntiles = 2*qt + 2;
    for (int kt = 0; kt < ntiles; kt++) {
        const int k0 = kt * BT;

        CP_WAIT(1);          // K(kt) resident
        __syncthreads();

        // ---- S = q_hi*k_hi + q_lo*k_hi ----
        float sacc[2][4][4];
#pragma unroll
        for (int mt = 0; mt < 2; mt++)
#pragma unroll
            for (int nt = 0; nt < 4; nt++)
#pragma unroll
                for (int e = 0; e < 4; e++) sacc[mt][nt][e] = 0.0f;

#pragma unroll
        for (int k16 = 0; k16 < HDIM; k16 += 16) {
            uint32_t bhi[4][2];
#pragma unroll
            for (int nt = 0; nt < 4; nt++)
                ldsm2(bhi[nt], khi_b + (nt*8*KSTR + k16)*2);
#pragma unroll
            for (int mt = 0; mt < 2; mt++) {
                uint32_t ahi[4], alo[4];
                ldsm4(ahi, qhi_b + (mt*16*QSTR + k16)*2);
                ldsm4(alo, qlo_b + (mt*16*QSTR + k16)*2);
#pragma unroll
                for (int nt = 0; nt < 4; nt++) {
                    mma16816h(sacc[mt][nt], ahi, bhi[nt]);
                    mma16816h(sacc[mt][nt], alo, bhi[nt]);
                }
            }
        }

        // ---- S -> smem with scale + causal mask ----
#pragma unroll
        for (int mt = 0; mt < 2; mt++) {
#pragma unroll
            for (int nt = 0; nt < 4; nt++) {
#pragma unroll
                for (int i = 0; i < 2; i++) {
#pragma unroll
                    for (int j = 0; j < 2; j++) {
                        int r = wm*32 + mt*16 + g + i*8;
                        int c = wn*32 + nt*8 + c2 + j;
                        float v = sacc[mt][nt][i*2 + j] * rnorm;
                        if (k0 + c > q0 + r) v = -10000.0f;
                        s_ss[r*SSTR + c] = v;
                    }
                }
            }
        }
        __syncthreads();     // S visible; K(kt) reads retired

        if (kt + 1 < ntiles) prefetch_k(k0 + BT);
        CP_COMMIT();

        // ---- row softmax + P split (fp16): 2 threads per row, __expf ----
        {
            int r  = tid >> 1;
            int hf = tid & 1;
            float* row = s_ss + r*SSTR + hf*32;
            float m_old = mrow[r];
            float mx = m_old;
#pragma unroll 8
            for (int c = 0; c < 32; c++) mx = fmaxf(mx, row[c]);
            mx = fmaxf(mx, __shfl_xor_sync(0xFFFFFFFFu, mx, 1));
            float sum = 0.0f;
            __half* ph = s_phi + r*PSTR + hf*32;
            __half* pl = s_plo + r*PSTR + hf*32;
#pragma unroll 8
            for (int c = 0; c < 32; c++) {
                float p = __expf(row[c] - mx);
                sum += p;
                __half h = __float2half(p);
                ph[c] = h;
                pl[c] = __float2half(p - __half2float(h));
            }
            sum += __shfl_xor_sync(0xFFFFFFFFu, sum, 1);
            if (hf == 0) {
                float scl = __expf(m_old - mx);
                mrow[r] = mx;
                lrow[r] = lrow[r] * scl + sum;
                srow[r] = scl;
            }
        }

        CP_WAIT(1);          // V(kt) resident
        __syncthreads();

        // ---- rescale acc_o, then O += p_hi*v_hi + p_lo*v_hi ----
#pragma unroll
        for (int mt = 0; mt < 2; mt++) {
#pragma unroll
            for (int i = 0; i < 2; i++) {
                float s_ = srow[wm*32 + mt*16 + g + i*8];
#pragma unroll
                for (int nt = 0; nt < 8; nt++) {
                    acc_o[mt][nt][i*2 + 0] *= s_;
                    acc_o[mt][nt][i*2 + 1] *= s_;
                }
            }
        }
#pragma unroll
        for (int k16 = 0; k16 < BT; k16 += 16) {
            uint32_t bvh[8][2];
#pragma unroll
            for (int nt = 0; nt < 8; nt++)
                ldsm2(bvh[nt], vhi_b + (nt*8*VSTR + k16)*2);
#pragma unroll
            for (int mt = 0; mt < 2; mt++) {
                uint32_t aph[4], apl[4];
                ldsm4(aph, phi_b + (mt*16*PSTR + k16)*2);
                ldsm4(apl, plo_b + (mt*16*PSTR + k16)*2);
#pragma unroll
                for (int nt = 0; nt < 8; nt++) {
                    mma16816h(acc_o[mt][nt], aph, bvh[nt]);
                    mma16816h(acc_o[mt][nt], apl, bvh[nt]);
                }
            }
        }
        __syncthreads();

        if (kt + 1 < ntiles) prefetch_v(k0 + BT);
        CP_COMMIT();
    }

    // ---- finalize: divide by l, write fp16 split-2 dense-GEMM A' ----
    const int b_idx = bh / NHEADS;
    const int h_idx = bh % NHEADS;
#pragma unroll
    for (int mt = 0; mt < 2; mt++) {
#pragma unroll
        for (int i = 0; i < 2; i++) {
            int r = wm*32 + mt*16 + g + i*8;
            float linv = 1.0f / lrow[r];
            int s_idx = q0 + r;
            size_t tok = (size_t)(s_idx*BATCH + b_idx);
            __half* dst = Aout + tok*K2 + h_idx*HDIM + wn*64;
#pragma unroll
            for (int nt = 0; nt < 8; nt++) {
#pragma unroll
                for (int j = 0; j < 2; j++) {
                    float v = acc_o[mt][nt][i*2 + j] * linv;
                    __half h = __float2half(v);
                    __half l = __float2half(v - __half2float(h));
                    int cc = nt*8 + c2 + j;
                    dst[cc]       = h;
                    dst[HID + cc] = l;
                }
            }
        }
    }
}

// ---------------- tail bias ---------------------------------------------------
__global__ void tail_copy(const float* __restrict__ src, float* __restrict__ dst, int n) {
    int i = blockIdx.x * blockDim.x + threadIdx.x;
    if (i < n) dst[i] = src[i];
}

// ---------------- launch -------------------------------------------------------
extern "C" void kernel_launch(void* const* d_in, const int* in_sizes, int n_in,
                              void* d_out, int out_size)
{
    const float* hidden  = (const float*)d_in[0];
    const float* w_qkv   = (const float*)d_in[2];
    const float* b_qkv   = (const float*)d_in[3];
    const float* w_dense = (const float*)d_in[4];
    const float* b_dense = (const float*)d_in[5];
    float* out = (float*)d_out;

    void *pA, *pBq, *pBd, *pQ, *pK, *pV;
    cudaGetSymbolAddress(&pA,   g_Abuf);
    cudaGetSymbolAddress(&pBq,  g_Bq);
    cudaGetSymbolAddress(&pBd,  g_Bd);
    cudaGetSymbolAddress(&pQ,   g_q);
    cudaGetSymbolAddress(&pK,   g_k);
    cudaGetSymbolAddress(&pV,   g_v);

    cudaFuncSetAttribute(hmma_gemm<1>, cudaFuncAttributeMaxDynamicSharedMemorySize, GEMM_SMEM);
    cudaFuncSetAttribute(hmma_gemm<2>, cudaFuncAttributeMaxDynamicSharedMemorySize, GEMM_SMEM);
    cudaFuncSetAttribute(attn_hmma, cudaFuncAttributeMaxDynamicSharedMemorySize, ATTN_SMEM);

    // 1) split-convert A (hidden) and B (w_qkv) to fp16 split-2
    conv_split<0><<<(TOK*HID/4 + 255)/256, 256>>>(hidden, (__half*)pA, TOK, HID);
    conv_split<1><<<(QKV_N*HID/4 + 255)/256, 256>>>(w_qkv, (__half*)pBq, QKV_N, HID);

    // 2) QKV projection (fp16 HMMA, bias + scatter epilogue)
    hmma_gemm<1><<<dim3(QKV_N/128, TOK/128), 256, GEMM_SMEM>>>(
        (const __half*)pA, (const __half*)pBq, b_qkv, nullptr,
        (float*)pQ, (float*)pK, (float*)pV, QKV_N);

    // 3) RoPE (Q hi/lo, K hi) + V transpose (hi)
    rope_table_kernel<<<(SEQ*64 + 255)/256, 256>>>();
    rope_apply_kernel<<<(NBH*SEQ*64 + 255)/256, 256>>>();
    v_transpose_split<<<dim3(SEQ/32, HDIM/32, NBH), dim3(32, 8)>>>();

    // 4) causal attention (fp16 split-2, 2-term MMAs, cp.async pipelined)
    attn_hmma<<<dim3(SEQ/BQ, NBH), 256, ATTN_SMEM>>>((__half*)pA);

    // 5) w_dense split + dense GEMM (fp16 HMMA)
    conv_split<1><<<(HID*HID/4 + 255)/256, 256>>>(w_dense, (__half*)pBd, HID, HID);
    hmma_gemm<2><<<dim3(HID/128, TOK/128), 256, GEMM_SMEM>>>(
        (const __half*)pA, (const __half*)pBd, nullptr, out,
        nullptr, nullptr, nullptr, HID);

    // 6) bias tail if harness flattens the (output, bias) tuple
    int extra = out_size - TOK*HID;
    if (extra > 0)
        tail_copy<<<(extra + 255)/256, 256>>>(b_dense, out + (size_t)TOK*HID, extra);
    (void)in_sizes; (void)n_in;
}

// round 11
// speedup vs baseline: 4.1397x; 1.1525x over previous
#include <cuda_runtime.h>
#include <cuda_bf16.h>
#include <cuda_fp16.h>
#include <math.h>
#include <stdint.h>

#define SEQ     2048
#define BATCH   2
#define HID     2048
#define NHEADS  16
#define HDIM    128
#define TOK     (SEQ*BATCH)     // 4096
#define QKV_N   (3*HID)         // 6144
#define K2      (2*HID)         // fp16 split-2 K' = 4096
#define NBH     (BATCH*NHEADS)  // 32

// ---------------- scratch (device globals; no runtime allocs allowed) -------
__device__ float g_q[NBH*SEQ*HDIM];
__device__ float g_k[NBH*SEQ*HDIM];
__device__ float g_v[NBH*SEQ*HDIM];
__device__ float g_cos[SEQ*64];
__device__ float g_sin[SEQ*64];
// fp16 split-2 operand buffers (GEMMs)
__device__ __align__(1024) __half g_Abuf[TOK*K2];
__device__ __align__(1024) __half g_Bq[QKV_N*K2];
__device__ __align__(1024) __half g_Bd[HID*K2];
// attention operands: Q split-2 (hi+lo), K/V hi-only
__device__ __align__(16) __half gq_hi[NBH*SEQ*HDIM];
__device__ __align__(16) __half gq_lo[NBH*SEQ*HDIM];
__device__ __align__(16) __half gk_hi[NBH*SEQ*HDIM];
__device__ __align__(16) __half gvt_hi[NBH*HDIM*SEQ];   // [bh][d][s]

// ============================================================================
// PTX helpers (base-target-safe)
// ============================================================================
__device__ __forceinline__ uint32_t smem_u32(const void* p) {
    uint32_t a;
    asm("{ .reg .u64 t; cvta.to.shared.u64 t, %1; cvt.u32.u64 %0, t; }"
        : "=r"(a) : "l"(p));
    return a;
}
__device__ __forceinline__ void cpasync16(uint32_t s, const void* g) {
    asm volatile("cp.async.cg.shared.global [%0], [%1], 16;" :: "r"(s), "l"(g));
}
#define CP_COMMIT() asm volatile("cp.async.commit_group;" ::: "memory")
#define CP_WAIT(n)  asm volatile("cp.async.wait_group %0;" :: "n"(n) : "memory")

__device__ __forceinline__ void ldsm4(uint32_t* r, uint32_t a) {
    asm volatile("ldmatrix.sync.aligned.m8n8.x4.shared.b16 {%0,%1,%2,%3}, [%4];"
        : "=r"(r[0]), "=r"(r[1]), "=r"(r[2]), "=r"(r[3]) : "r"(a));
}
__device__ __forceinline__ void ldsm2(uint32_t* r, uint32_t a) {
    asm volatile("ldmatrix.sync.aligned.m8n8.x2.shared.b16 {%0,%1}, [%2];"
        : "=r"(r[0]), "=r"(r[1]) : "r"(a));
}
__device__ __forceinline__ void mma16816h(float* c, const uint32_t* a, const uint32_t* b) {
    asm volatile("mma.sync.aligned.m16n8k16.row.col.f32.f16.f16.f32 "
        "{%0,%1,%2,%3}, {%4,%5,%6,%7}, {%8,%9}, {%0,%1,%2,%3};"
        : "+f"(c[0]), "+f"(c[1]), "+f"(c[2]), "+f"(c[3])
        : "r"(a[0]), "r"(a[1]), "r"(a[2]), "r"(a[3]), "r"(b[0]), "r"(b[1]));
}
// pack two floats into fp16x2 hi + residual lo fragments
__device__ __forceinline__ void split_pack(float a, float b, uint32_t& hi, uint32_t& lo) {
    __half ha = __float2half(a), hb = __float2half(b);
    __half la = __float2half(a - __half2float(ha));
    __half lb = __float2half(b - __half2float(hb));
    hi = (uint32_t)__half_as_ushort(ha) | ((uint32_t)__half_as_ushort(hb) << 16);
    lo = (uint32_t)__half_as_ushort(la) | ((uint32_t)__half_as_ushort(lb) << 16);
}

// ============================================================================
// HMMA fp16 split-2 GEMM: BK=64, 3-stage cp.async ring, one barrier per K-step.
// CTA tile 128x128x64, 256 thr (8 warps 2x4).
// ============================================================================
#define BK 64
#define ASTR 72
#define TILE_B16 (128*ASTR)            // 9216 halfs per operand tile
#define STAGE_B16 (2*TILE_B16)
#define STAGE_BYTES (STAGE_B16*2)      // 36864
#define GSTAGES 3
#define GEMM_SMEM (GSTAGES*STAGE_BYTES)  // 110592

template<int MODE>
__global__ void __launch_bounds__(256, 2)
hmma_gemm(const __half* __restrict__ Ag, const __half* __restrict__ Bg,
          const float* __restrict__ bias, float* __restrict__ C,
          float* __restrict__ q_out, float* __restrict__ k_out, float* __restrict__ v_out,
          int N)
{
    extern __shared__ __align__(16) __half smbuf[];

    const int tid  = threadIdx.x;
    const int lane = tid & 31;
    const int warp = tid >> 5;
    const int wm = warp >> 2;
    const int wn = warp & 3;
    const int m0 = blockIdx.y * 128;
    const int n0 = blockIdx.x * 128;

    const uint32_t smb = smem_u32(smbuf);
    const int cr = tid >> 3;           // row 0..31 (x4 groups)
    const int ccn = tid & 7;           // 16B chunk in 128B row
    const int KT = K2 / BK;            // 64

    auto prefetch = [&](int kt, int slot) {
        uint32_t base = smb + slot * STAGE_BYTES;
#pragma unroll
        for (int h = 0; h < 4; h++) {
            int r = cr + h * 32;
            cpasync16(base + (r * ASTR + ccn * 8) * 2,
                      Ag + (size_t)(m0 + r) * K2 + kt * BK + ccn * 8);
            cpasync16(base + TILE_B16*2 + (r * ASTR + ccn * 8) * 2,
                      Bg + (size_t)(n0 + r) * K2 + kt * BK + ccn * 8);
        }
    };

    float acc[4][4][4];
#pragma unroll
    for (int i = 0; i < 4; i++)
#pragma unroll
        for (int j = 0; j < 4; j++)
#pragma unroll
            for (int e = 0; e < 4; e++) acc[i][j][e] = 0.0f;

    const int l16 = lane & 15;
    const uint32_t a_off = (((wm * 64 + l16) * ASTR) + ((lane >> 4) * 8)) * 2;
    const uint32_t b_off = (((wn * 32 + (l16 & 7)) * ASTR) + ((l16 >> 3) * 8)) * 2;

    prefetch(0, 0); CP_COMMIT();
    prefetch(1, 1); CP_COMMIT();

    int slot = 0, pslot = 2;
    for (int kt = 0; kt < KT; kt++) {
        CP_WAIT(1);
        __syncthreads();
        int pf = kt + 2;
        if (pf < KT) prefetch(pf, pslot);
        CP_COMMIT();

        uint32_t abase = smb + slot * STAGE_BYTES + a_off;
        uint32_t bbase = smb + slot * STAGE_BYTES + TILE_B16*2 + b_off;

#pragma unroll
        for (int k16 = 0; k16 < BK; k16 += 16) {
            uint32_t bfr[4][2];
#pragma unroll
            for (int nt = 0; nt < 4; nt++)
                ldsm2(bfr[nt], bbase + (nt * 8 * ASTR + k16) * 2);
#pragma unroll
            for (int mt = 0; mt < 4; mt++) {
                uint32_t afr[4];
                ldsm4(afr, abase + (mt * 16 * ASTR + k16) * 2);
#pragma unroll
                for (int nt = 0; nt < 4; nt++)
                    mma16816h(acc[mt][nt], afr, bfr[nt]);
            }
        }
        if (++slot == 3) slot = 0;
        if (++pslot == 3) pslot = 0;
    }

    const int g  = lane >> 2;
    const int c2 = (lane & 3) * 2;
#pragma unroll
    for (int mt = 0; mt < 4; mt++) {
#pragma unroll
        for (int nt = 0; nt < 4; nt++) {
#pragma unroll
            for (int i = 0; i < 2; i++) {
#pragma unroll
                for (int j = 0; j < 2; j++) {
                    int m = m0 + wm * 64 + mt * 16 + g + i * 8;
                    int n = n0 + wn * 32 + nt * 8 + c2 + j;
                    float v = acc[mt][nt][i * 2 + j];
                    if (MODE == 1) {
                        v += bias[n];
                        int head = n / (3 * HDIM);
                        int r3   = n % (3 * HDIM);
                        int part = r3 / HDIM;
                        int d    = r3 % HDIM;
                        int off  = (((m & 1) * NHEADS + head) * SEQ + (m >> 1)) * HDIM + d;
                        if      (part == 0) q_out[off] = v;
                        else if (part == 1) k_out[off] = v;
                        else                v_out[off] = v;
                    } else {
                        C[(size_t)m * N + n] = v;
                    }
                }
            }
        }
    }
}

// ---------------- fp16 split-2 conversion (vectorized) -----------------------
// PAT 0 (A): [hi|lo]    PAT 1 (B): [hi|hi]
template<int PAT>
__global__ void conv_split(const float* __restrict__ src,
                           __half* __restrict__ dst, int R, int K)
{
    int idx = blockIdx.x * blockDim.x + threadIdx.x;     // float4 index
    int kq = K >> 2;
    if (idx >= R * kq) return;
    int row = idx / kq, c4 = idx - row * kq;
    float4 x = ((const float4*)src)[idx];
    __half hi[4];
    hi[0] = __float2half(x.x); hi[1] = __float2half(x.y);
    hi[2] = __float2half(x.z); hi[3] = __float2half(x.w);
    size_t base = (size_t)row * (2*K) + c4 * 4;
    *(uint2*)(dst + base) = *(uint2*)hi;
    if (PAT == 0) {
        __half lo[4];
        lo[0] = __float2half(x.x - __half2float(hi[0]));
        lo[1] = __float2half(x.y - __half2float(hi[1]));
        lo[2] = __float2half(x.z - __half2float(hi[2]));
        lo[3] = __float2half(x.w - __half2float(hi[3]));
        *(uint2*)(dst + base + K) = *(uint2*)lo;
    } else {
        *(uint2*)(dst + base + K) = *(uint2*)hi;
    }
}

// ---------------- RoPE tables + apply ----------------------------------------
__global__ void rope_table_kernel() {
    __shared__ float invf[64];
    if (threadIdx.x < 64)
        invf[threadIdx.x] = (float)pow(10000.0, -((double)threadIdx.x) / 64.0);
    __syncthreads();
    int idx = blockIdx.x * blockDim.x + threadIdx.x;
    if (idx >= SEQ * 64) return;
    int s = idx >> 6;
    int i = idx & 63;
    float theta = (float)s * invf[i];
    g_cos[idx] = cosf(theta);
    g_sin[idx] = sinf(theta);
}

__device__ __forceinline__ void split_store_h(__half* hi, __half* lo,
                                              int off, float x) {
    __half h = __float2half(x);
    hi[off] = h;
    lo[off] = __float2half(x - __half2float(h));
}

__global__ void rope_apply_kernel() {
    int idx = blockIdx.x * blockDim.x + threadIdx.x;
    int total = NBH*SEQ*64;
    if (idx >= total) return;
    int i = idx & 63;
    int rowid = idx >> 6;
    int s = rowid & (SEQ - 1);
    float c  = g_cos[s*64 + i];
    float sn = g_sin[s*64 + i];
    int base = rowid * HDIM;
    float q1 = g_q[base + i], q2 = g_q[base + 64 + i];
    float k1 = g_k[base + i], k2 = g_k[base + 64 + i];
    split_store_h(gq_hi, gq_lo, base + i,      q1*c - q2*sn);
    split_store_h(gq_hi, gq_lo, base + 64 + i, q2*c + q1*sn);
    gk_hi[base + i]      = __float2half(k1*c - k2*sn);    // K hi-only
    gk_hi[base + 64 + i] = __float2half(k2*c + k1*sn);
}

// ---------------- V transpose: g_v[bh][s][d] -> gvt_hi[bh][d][s] -------------
__global__ void v_transpose_split() {
    __shared__ float t[32][33];
    int bh = blockIdx.z;
    int s0 = blockIdx.x * 32, d0 = blockIdx.y * 32;
    int tx = threadIdx.x, ty = threadIdx.y;   // 32 x 8
#pragma unroll
    for (int i = 0; i < 32; i += 8)
        t[ty + i][tx] = g_v[((size_t)bh*SEQ + s0 + ty + i) * HDIM + d0 + tx];
    __syncthreads();
#pragma unroll
    for (int i = 0; i < 32; i += 8) {
        float x = t[tx][ty + i];
        size_t off = ((size_t)bh*HDIM + d0 + ty + i) * SEQ + s0 + tx;
        gvt_hi[off] = __float2half(x);                    // V hi-only
    }
}

// ============================================================================
// FA2-style HMMA causal flash attention, fp16 split-2 (2-term MMAs).
// 8 warps x 16 rows each; softmax entirely in registers via quad shuffles;
// P converted in-register from C-fragment to A-fragment layout (no smem P).
// smem = Q hi/lo + K hi + V hi only (105.5 KB) -> occupancy 2.
// ============================================================================
#define BQ 128
#define BT 64
#define QSTR 136
#define KSTR 136
#define VSTR 72

#define OFF_QHI 0
#define SZ_Q    (BQ*QSTR*2)
#define OFF_QLO (OFF_QHI + SZ_Q)
#define OFF_KHI (OFF_QLO + SZ_Q)
#define SZ_K    (BT*KSTR*2)
#define OFF_VHI (OFF_KHI + SZ_K)
#define SZ_V    (HDIM*VSTR*2)
#define ATTN_SMEM (OFF_VHI + SZ_V)     // 105472

__global__ void __launch_bounds__(256, 2) attn_hmma(__half* __restrict__ Aout) {
    extern __shared__ char smem[];
    const uint32_t sb = smem_u32(smem);

    const int tid  = threadIdx.x;
    const int lane = tid & 31;
    const int w    = tid >> 5;               // warp owns rows [w*16, w*16+16)
    const int qt = gridDim.x - 1 - blockIdx.x;   // heavy tiles first
    const int bh = blockIdx.y;
    const int q0 = qt * BQ;

    const int l16 = lane & 15;
    const int g   = lane >> 2;
    const int c2  = (lane & 3) * 2;

    __half* s_qhi = (__half*)(smem + OFF_QHI);
    __half* s_qlo = (__half*)(smem + OFF_QLO);

    const __half* Kh = gk_hi + (size_t)bh*SEQ*HDIM;
    const __half* Vh = gvt_hi + (size_t)bh*HDIM*SEQ;

    auto prefetch_k = [&](int k0) {
#pragma unroll
        for (int it = 0; it < 4; it++) {
            int t = tid + it*256;
            int row = t >> 4, cc = t & 15;
            cpasync16(sb + OFF_KHI + (row*KSTR + cc*8)*2,
                      Kh + (size_t)(k0 + row)*HDIM + cc*8);
        }
    };
    auto prefetch_v = [&](int k0) {
#pragma unroll
        for (int it = 0; it < 4; it++) {
            int t = tid + it*256;
            int d = t >> 3, cc = t & 7;
            cpasync16(sb + OFF_VHI + (d*VSTR + cc*8)*2,
                      Vh + (size_t)d*SEQ + k0 + cc*8);
        }
    };

    prefetch_k(0); CP_COMMIT();
    prefetch_v(0); CP_COMMIT();

    // Q tile (hi & lo), once
    {
        const __half* qh = gq_hi + ((size_t)bh*SEQ + q0) * HDIM;
        const __half* ql = gq_lo + ((size_t)bh*SEQ + q0) * HDIM;
#pragma unroll
        for (int it = 0; it < 8; it++) {
            int t = tid + it*256;
            int row = t >> 4, cc = t & 15;
            *(uint4*)(s_qhi + row*QSTR + cc*8) = *(const uint4*)(qh + row*HDIM + cc*8);
        }
#pragma unroll
        for (int it = 0; it < 8; it++) {
            int t = tid + it*256;
            int row = t >> 4, cc = t & 15;
            *(uint4*)(s_qlo + row*QSTR + cc*8) = *(const uint4*)(ql + row*HDIM + cc*8);
        }
    }

    float m0 = -1e30f, m1 = -1e30f, l0 = 0.0f, l1 = 0.0f;
    float acc[16][4];
#pragma unroll
    for (int nt = 0; nt < 16; nt++)
#pragma unroll
        for (int e = 0; e < 4; e++) acc[nt][e] = 0.0f;

    const float rnorm = 0.088388347648318447f;

    const uint32_t qhi_b = sb + OFF_QHI + (((w*16 + l16)*QSTR) + (lane>>4)*8)*2;
    const uint32_t qlo_b = sb + OFF_QLO + (((w*16 + l16)*QSTR) + (lane>>4)*8)*2;
    const uint32_t khi_b = sb + OFF_KHI + (((l16&7)*KSTR) + (l16>>3)*8)*2;
    const uint32_t vhi_b = sb + OFF_VHI + (((l16&7)*VSTR) + (l16>>3)*8)*2;

    const int rbase = q0 + w*16 + g;

    const int ntiles = 2*qt + 2;
    for (int kt = 0; kt < ntiles; kt++) {
        const int k0 = kt * BT;

        CP_WAIT(1);          // K(kt) resident
        __syncthreads();     // K (and Q on iter 0) visible

        // ---- S = q_hi*k_hi + q_lo*k_hi (per warp: 16 rows x 64 cols) ----
        float sacc[8][4];
#pragma unroll
        for (int nt = 0; nt < 8; nt++)
#pragma unroll
            for (int e = 0; e < 4; e++) sacc[nt][e] = 0.0f;

#pragma unroll
        for (int k16 = 0; k16 < HDIM; k16 += 16) {
            uint32_t bhi[8][2];
#pragma unroll
            for (int nt = 0; nt < 8; nt++)
                ldsm2(bhi[nt], khi_b + (nt*8*KSTR + k16)*2);
            uint32_t ahi[4], alo[4];
            ldsm4(ahi, qhi_b + k16*2);
            ldsm4(alo, qlo_b + k16*2);
#pragma unroll
            for (int nt = 0; nt < 8; nt++) {
                mma16816h(sacc[nt], ahi, bhi[nt]);
                mma16816h(sacc[nt], alo, bhi[nt]);
            }
        }
        __syncthreads();     // K(kt) reads retired

        if (kt + 1 < ntiles) prefetch_k(k0 + BT);
        CP_COMMIT();

        // ---- mask + scale + register softmax ----
#pragma unroll
        for (int nt = 0; nt < 8; nt++) {
#pragma unroll
            for (int e = 0; e < 4; e++) {
                int r = rbase + (e >> 1)*8;
                int c = k0 + nt*8 + c2 + (e & 1);
                float v = sacc[nt][e] * rnorm;
                if (c > r) v = -10000.0f;
                sacc[nt][e] = v;
            }
        }
        float mx0 = -1e30f, mx1 = -1e30f;
#pragma unroll
        for (int nt = 0; nt < 8; nt++) {
            mx0 = fmaxf(mx0, fmaxf(sacc[nt][0], sacc[nt][1]));
            mx1 = fmaxf(mx1, fmaxf(sacc[nt][2], sacc[nt][3]));
        }
        mx0 = fmaxf(mx0, __shfl_xor_sync(0xFFFFFFFFu, mx0, 1));
        mx0 = fmaxf(mx0, __shfl_xor_sync(0xFFFFFFFFu, mx0, 2));
        mx1 = fmaxf(mx1, __shfl_xor_sync(0xFFFFFFFFu, mx1, 1));
        mx1 = fmaxf(mx1, __shfl_xor_sync(0xFFFFFFFFu, mx1, 2));
        float mn0 = fmaxf(m0, mx0), mn1 = fmaxf(m1, mx1);
        float scl0 = __expf(m0 - mn0), scl1 = __expf(m1 - mn1);
        m0 = mn0; m1 = mn1;
        float sum0 = 0.0f, sum1 = 0.0f;
#pragma unroll
        for (int nt = 0; nt < 8; nt++) {
            float p0 = __expf(sacc[nt][0] - m0);
            float p1 = __expf(sacc[nt][1] - m0);
            float p2 = __expf(sacc[nt][2] - m1);
            float p3 = __expf(sacc[nt][3] - m1);
            sacc[nt][0] = p0; sacc[nt][1] = p1;
            sacc[nt][2] = p2; sacc[nt][3] = p3;
            sum0 += p0 + p1; sum1 += p2 + p3;
        }
        l0 = l0 * scl0 + sum0;          // per-thread partial; quad-reduced at end
        l1 = l1 * scl1 + sum1;
#pragma unroll
        for (int nt = 0; nt < 16; nt++) {
            acc[nt][0] *= scl0; acc[nt][1] *= scl0;
            acc[nt][2] *= scl1; acc[nt][3] *= scl1;
        }

        CP_WAIT(1);          // V(kt) resident
        __syncthreads();     // V visible

        // ---- O += p_hi*v_hi + p_lo*v_hi (P from registers) ----
#pragma unroll
        for (int s = 0; s < 4; s++) {
            uint32_t aph[4], apl[4];
            split_pack(sacc[2*s][0],   sacc[2*s][1],   aph[0], apl[0]);
            split_pack(sacc[2*s][2],   sacc[2*s][3],   aph[1], apl[1]);
            split_pack(sacc[2*s+1][0], sacc[2*s+1][1], aph[2], apl[2]);
            split_pack(sacc[2*s+1][2], sacc[2*s+1][3], aph[3], apl[3]);
#pragma unroll
            for (int nt = 0; nt < 16; nt++) {
                uint32_t bv[2];
                ldsm2(bv, vhi_b + (nt*8*VSTR + s*16)*2);
                mma16816h(acc[nt], aph, bv);
                mma16816h(acc[nt], apl, bv);
            }
        }
        __syncthreads();     // V(kt) reads retired

        if (kt + 1 < ntiles) prefetch_v(k0 + BT);
        CP_COMMIT();
    }

    // ---- finalize: quad-reduce l, divide, write fp16 split-2 dense A' ----
    l0 += __shfl_xor_sync(0xFFFFFFFFu, l0, 1);
    l0 += __shfl_xor_sync(0xFFFFFFFFu, l0, 2);
    l1 += __shfl_xor_sync(0xFFFFFFFFu, l1, 1);
    l1 += __shfl_xor_sync(0xFFFFFFFFu, l1, 2);
    const float linv0 = 1.0f / l0, linv1 = 1.0f / l1;
    const int b_idx = bh / NHEADS;
    const int h_idx = bh % NHEADS;
#pragma unroll
    for (int i = 0; i < 2; i++) {
        int r = rbase + i*8;
        float linv = i ? linv1 : linv0;
        size_t tok = (size_t)(r*BATCH + b_idx);
        __half* dst = Aout + tok*K2 + h_idx*HDIM;
#pragma unroll
        for (int nt = 0; nt < 16; nt++) {
#pragma unroll
            for (int j = 0; j < 2; j++) {
                float v = acc[nt][i*2 + j] * linv;
                __half h = __float2half(v);
                __half l = __float2half(v - __half2float(h));
                int cc = nt*8 + c2 + j;
                dst[cc]       = h;
                dst[HID + cc] = l;
            }
        }
    }
}

// ---------------- tail bias ---------------------------------------------------
__global__ void tail_copy(const float* __restrict__ src, float* __restrict__ dst, int n) {
    int i = blockIdx.x * blockDim.x + threadIdx.x;
    if (i < n) dst[i] = src[i];
}

// ---------------- launch -------------------------------------------------------
extern "C" void kernel_launch(void* const* d_in, const int* in_sizes, int n_in,
                              void* d_out, int out_size)
{
    const float* hidden  = (const float*)d_in[0];
    const float* w_qkv   = (const float*)d_in[2];
    const float* b_qkv   = (const float*)d_in[3];
    const float* w_dense = (const float*)d_in[4];
    const float* b_dense = (const float*)d_in[5];
    float* out = (float*)d_out;

    void *pA, *pBq, *pBd, *pQ, *pK, *pV;
    cudaGetSymbolAddress(&pA,   g_Abuf);
    cudaGetSymbolAddress(&pBq,  g_Bq);
    cudaGetSymbolAddress(&pBd,  g_Bd);
    cudaGetSymbolAddress(&pQ,   g_q);
    cudaGetSymbolAddress(&pK,   g_k);
    cudaGetSymbolAddress(&pV,   g_v);

    cudaFuncSetAttribute(hmma_gemm<1>, cudaFuncAttributeMaxDynamicSharedMemorySize, GEMM_SMEM);
    cudaFuncSetAttribute(hmma_gemm<2>, cudaFuncAttributeMaxDynamicSharedMemorySize, GEMM_SMEM);
    cudaFuncSetAttribute(attn_hmma, cudaFuncAttributeMaxDynamicSharedMemorySize, ATTN_SMEM);

    // 1) split-convert A (hidden) and B (w_qkv) to fp16 split-2
    conv_split<0><<<(TOK*HID/4 + 255)/256, 256>>>(hidden, (__half*)pA, TOK, HID);
    conv_split<1><<<(QKV_N*HID/4 + 255)/256, 256>>>(w_qkv, (__half*)pBq, QKV_N, HID);

    // 2) QKV projection (fp16 HMMA, bias + scatter epilogue)
    hmma_gemm<1><<<dim3(QKV_N/128, TOK/128), 256, GEMM_SMEM>>>(
        (const __half*)pA, (const __half*)pBq, b_qkv, nullptr,
        (float*)pQ, (float*)pK, (float*)pV, QKV_N);

    // 3) RoPE (Q hi/lo, K hi) + V transpose (hi)
    rope_table_kernel<<<(SEQ*64 + 255)/256, 256>>>();
    rope_apply_kernel<<<(NBH*SEQ*64 + 255)/256, 256>>>();
    v_transpose_split<<<dim3(SEQ/32, HDIM/32, NBH), dim3(32, 8)>>>();

    // 4) causal attention (FA2 register softmax, fp16 split-2)
    attn_hmma<<<dim3(SEQ/BQ, NBH), 256, ATTN_SMEM>>>((__half*)pA);

    // 5) w_dense split + dense GEMM (fp16 HMMA)
    conv_split<1><<<(HID*HID/4 + 255)/256, 256>>>(w_dense, (__half*)pBd, HID, HID);
    hmma_gemm<2><<<dim3(HID/128, TOK/128), 256, GEMM_SMEM>>>(
        (const __half*)pA, (const __half*)pBd, nullptr, out,
        nullptr, nullptr, nullptr, HID);

    // 6) bias tail if harness flattens the (output, bias) tuple
    int extra = out_size - TOK*HID;
    if (extra > 0)
        tail_copy<<<(extra + 255)/256, 256>>>(b_dense, out + (size_t)TOK*HID, extra);
    (void)in_sizes; (void)n_in;
}

// round 12
// speedup vs baseline: 4.1744x; 1.0084x over previous
#include <cuda_runtime.h>
#include <cuda_bf16.h>
#include <cuda_fp16.h>
#include <math.h>
#include <stdint.h>

#define SEQ     2048
#define BATCH   2
#define HID     2048
#define NHEADS  16
#define HDIM    128
#define TOK     (SEQ*BATCH)     // 4096
#define QKV_N   (3*HID)         // 6144
#define K2      (2*HID)         // A' split-2 width (hi|lo)
#define NBH     (BATCH*NHEADS)  // 32

// ---------------- scratch (device globals; no runtime allocs allowed) -------
__device__ float g_q[NBH*SEQ*HDIM];
__device__ float g_k[NBH*SEQ*HDIM];
__device__ float g_v[NBH*SEQ*HDIM];
__device__ float g_cos[SEQ*64];
__device__ float g_sin[SEQ*64];
// GEMM operands: A' = [hi|lo] (stride K2); B = hi only (stride HID)
__device__ __align__(1024) __half g_Abuf[TOK*K2];
__device__ __align__(1024) __half g_Bq[QKV_N*HID];
__device__ __align__(1024) __half g_Bd[HID*HID];
// attention operands: Q split-2 (hi+lo), K/V hi-only
__device__ __align__(16) __half gq_hi[NBH*SEQ*HDIM];
__device__ __align__(16) __half gq_lo[NBH*SEQ*HDIM];
__device__ __align__(16) __half gk_hi[NBH*SEQ*HDIM];
__device__ __align__(16) __half gvt_hi[NBH*HDIM*SEQ];   // [bh][d][s]

// ============================================================================
// PTX helpers (base-target-safe)
// ============================================================================
__device__ __forceinline__ uint32_t smem_u32(const void* p) {
    uint32_t a;
    asm("{ .reg .u64 t; cvta.to.shared.u64 t, %1; cvt.u32.u64 %0, t; }"
        : "=r"(a) : "l"(p));
    return a;
}
__device__ __forceinline__ void cpasync16(uint32_t s, const void* g) {
    asm volatile("cp.async.cg.shared.global [%0], [%1], 16;" :: "r"(s), "l"(g));
}
#define CP_COMMIT() asm volatile("cp.async.commit_group;" ::: "memory")
#define CP_WAIT(n)  asm volatile("cp.async.wait_group %0;" :: "n"(n) : "memory")

__device__ __forceinline__ void ldsm4(uint32_t* r, uint32_t a) {
    asm volatile("ldmatrix.sync.aligned.m8n8.x4.shared.b16 {%0,%1,%2,%3}, [%4];"
        : "=r"(r[0]), "=r"(r[1]), "=r"(r[2]), "=r"(r[3]) : "r"(a));
}
__device__ __forceinline__ void ldsm2(uint32_t* r, uint32_t a) {
    asm volatile("ldmatrix.sync.aligned.m8n8.x2.shared.b16 {%0,%1}, [%2];"
        : "=r"(r[0]), "=r"(r[1]) : "r"(a));
}
__device__ __forceinline__ void mma16816h(float* c, const uint32_t* a, const uint32_t* b) {
    asm volatile("mma.sync.aligned.m16n8k16.row.col.f32.f16.f16.f32 "
        "{%0,%1,%2,%3}, {%4,%5,%6,%7}, {%8,%9}, {%0,%1,%2,%3};"
        : "+f"(c[0]), "+f"(c[1]), "+f"(c[2]), "+f"(c[3])
        : "r"(a[0]), "r"(a[1]), "r"(a[2]), "r"(a[3]), "r"(b[0]), "r"(b[1]));
}
// pack two floats into fp16x2 hi + residual lo fragments
__device__ __forceinline__ void split_pack(float a, float b, uint32_t& hi, uint32_t& lo) {
    __half ha = __float2half(a), hb = __float2half(b);
    __half la = __float2half(a - __half2float(ha));
    __half lb = __float2half(b - __half2float(hb));
    hi = (uint32_t)__half_as_ushort(ha) | ((uint32_t)__half_as_ushort(hb) << 16);
    lo = (uint32_t)__half_as_ushort(la) | ((uint32_t)__half_as_ushort(hb) << 16) ;
    lo = (uint32_t)__half_as_ushort(la) | ((uint32_t)__half_as_ushort(lb) << 16);
}

// ============================================================================
// HMMA fp16 split-2 GEMM, B-dedup: C = A_hi*B + A_lo*B over K=2048.
// CTA tile 128x128x32, 256 thr, warps 4(m) x 2(n), warp tile 32x64.
// 3-stage ring of [Ahi|Alo|B] tiles, one barrier per K-step.
// MODE 1: QKV — add bias + scatter to q/k/v.   MODE 2: plain C store.
// ============================================================================
#define BK 32
#define ASTR 40
#define TILE_B16 (128*ASTR)            // 5120 halfs per tile
#define STAGE_B16 (3*TILE_B16)         // Ahi + Alo + B
#define STAGE_BYTES (STAGE_B16*2)      // 30720
#define GSTAGES 3
#define GEMM_SMEM (GSTAGES*STAGE_BYTES)  // 92160

template<int MODE>
__global__ void __launch_bounds__(256, 2)
hmma_gemm(const __half* __restrict__ Ag, const __half* __restrict__ Bg,
          const float* __restrict__ bias, float* __restrict__ C,
          float* __restrict__ q_out, float* __restrict__ k_out, float* __restrict__ v_out,
          int N)
{
    extern __shared__ __align__(16) __half smbuf[];

    const int tid  = threadIdx.x;
    const int lane = tid & 31;
    const int warp = tid >> 5;
    const int wm = warp >> 1;          // 0..3 (32-row slabs)
    const int wn = warp & 1;           // 0..1 (64-col slabs)
    const int m0 = blockIdx.y * 128;
    const int n0 = blockIdx.x * 128;

    const uint32_t smb = smem_u32(smbuf);
    const int cr  = tid >> 2;          // row 0..63 (+64 second half)
    const int ccn = tid & 3;           // 16B chunk within 64B row
    const int KT  = HID / BK;          // 64

    auto prefetch = [&](int kt, int slot) {
        uint32_t base = smb + slot * STAGE_BYTES;
#pragma unroll
        for (int h = 0; h < 2; h++) {
            int r = cr + h * 64;
            uint32_t so = (r * ASTR + ccn * 8) * 2;
            cpasync16(base + so,
                      Ag + (size_t)(m0 + r) * K2 + kt * BK + ccn * 8);
            cpasync16(base + TILE_B16*2 + so,
                      Ag + (size_t)(m0 + r) * K2 + HID + kt * BK + ccn * 8);
            cpasync16(base + 2*TILE_B16*2 + so,
                      Bg + (size_t)(n0 + r) * HID + kt * BK + ccn * 8);
        }
    };

    float acc[2][8][4];
#pragma unroll
    for (int i = 0; i < 2; i++)
#pragma unroll
        for (int j = 0; j < 8; j++)
#pragma unroll
            for (int e = 0; e < 4; e++) acc[i][j][e] = 0.0f;

    const int l16 = lane & 15;
    const uint32_t a_off = (((wm * 32 + l16) * ASTR) + ((lane >> 4) * 8)) * 2;
    const uint32_t b_off = (((wn * 64 + (l16 & 7)) * ASTR) + ((l16 >> 3) * 8)) * 2;

    prefetch(0, 0); CP_COMMIT();
    prefetch(1, 1); CP_COMMIT();

    int slot = 0, pslot = 2;
    for (int kt = 0; kt < KT; kt++) {
        CP_WAIT(1);
        __syncthreads();
        int pf = kt + 2;
        if (pf < KT) prefetch(pf, pslot);
        CP_COMMIT();

        uint32_t ahib = smb + slot * STAGE_BYTES + a_off;
        uint32_t alob = ahib + TILE_B16*2;
        uint32_t bb   = smb + slot * STAGE_BYTES + 2*TILE_B16*2 + b_off;

#pragma unroll
        for (int k16 = 0; k16 < BK; k16 += 16) {
            uint32_t bfr[8][2];
#pragma unroll
            for (int nt = 0; nt < 8; nt++)
                ldsm2(bfr[nt], bb + (nt * 8 * ASTR + k16) * 2);
#pragma unroll
            for (int mt = 0; mt < 2; mt++) {
                uint32_t ahi[4], alo[4];
                ldsm4(ahi, ahib + (mt * 16 * ASTR + k16) * 2);
                ldsm4(alo, alob + (mt * 16 * ASTR + k16) * 2);
#pragma unroll
                for (int nt = 0; nt < 8; nt++) {
                    mma16816h(acc[mt][nt], ahi, bfr[nt]);
                    mma16816h(acc[mt][nt], alo, bfr[nt]);
                }
            }
        }
        if (++slot == 3) slot = 0;
        if (++pslot == 3) pslot = 0;
    }

    const int g  = lane >> 2;
    const int c2 = (lane & 3) * 2;
#pragma unroll
    for (int mt = 0; mt < 2; mt++) {
#pragma unroll
        for (int nt = 0; nt < 8; nt++) {
#pragma unroll
            for (int i = 0; i < 2; i++) {
#pragma unroll
                for (int j = 0; j < 2; j++) {
                    int m = m0 + wm * 32 + mt * 16 + g + i * 8;
                    int n = n0 + wn * 64 + nt * 8 + c2 + j;
                    float v = acc[mt][nt][i * 2 + j];
                    if (MODE == 1) {
                        v += bias[n];
                        int head = n / (3 * HDIM);
                        int r3   = n % (3 * HDIM);
                        int part = r3 / HDIM;
                        int d    = r3 % HDIM;
                        int off  = (((m & 1) * NHEADS + head) * SEQ + (m >> 1)) * HDIM + d;
                        if      (part == 0) q_out[off] = v;
                        else if (part == 1) k_out[off] = v;
                        else                v_out[off] = v;
                    } else {
                        C[(size_t)m * N + n] = v;
                    }
                }
            }
        }
    }
}

// ---------------- conversions -------------------------------------------------
// A (hidden): fp32 -> [hi|lo] rows of width K2
__global__ void conv_split_a(const float* __restrict__ src,
                             __half* __restrict__ dst, int R, int K)
{
    int idx = blockIdx.x * blockDim.x + threadIdx.x;     // float4 index
    int kq = K >> 2;
    if (idx >= R * kq) return;
    int row = idx / kq, c4 = idx - row * kq;
    float4 x = ((const float4*)src)[idx];
    __half hi[4];
    hi[0] = __float2half(x.x); hi[1] = __float2half(x.y);
    hi[2] = __float2half(x.z); hi[3] = __float2half(x.w);
    size_t base = (size_t)row * (2*K) + c4 * 4;
    *(uint2*)(dst + base) = *(uint2*)hi;
    __half lo[4];
    lo[0] = __float2half(x.x - __half2float(hi[0]));
    lo[1] = __float2half(x.y - __half2float(hi[1]));
    lo[2] = __float2half(x.z - __half2float(hi[2]));
    lo[3] = __float2half(x.w - __half2float(hi[3]));
    *(uint2*)(dst + base + K) = *(uint2*)lo;
}
// B (weights): flat fp32 -> fp16 hi
__global__ void conv_hi(const float* __restrict__ src,
                        __half* __restrict__ dst, int n4)
{
    int idx = blockIdx.x * blockDim.x + threadIdx.x;
    if (idx >= n4) return;
    float4 x = ((const float4*)src)[idx];
    __half h[4];
    h[0] = __float2half(x.x); h[1] = __float2half(x.y);
    h[2] = __float2half(x.z); h[3] = __float2half(x.w);
    *(uint2*)(dst + (size_t)idx * 4) = *(uint2*)h;
}

// ---------------- RoPE tables + apply ----------------------------------------
__global__ void rope_table_kernel() {
    __shared__ float invf[64];
    if (threadIdx.x < 64)
        invf[threadIdx.x] = (float)pow(10000.0, -((double)threadIdx.x) / 64.0);
    __syncthreads();
    int idx = blockIdx.x * blockDim.x + threadIdx.x;
    if (idx >= SEQ * 64) return;
    int s = idx >> 6;
    int i = idx & 63;
    float theta = (float)s * invf[i];
    g_cos[idx] = cosf(theta);
    g_sin[idx] = sinf(theta);
}

__device__ __forceinline__ void split_store_h(__half* hi, __half* lo,
                                              int off, float x) {
    __half h = __float2half(x);
    hi[off] = h;
    lo[off] = __float2half(x - __half2float(h));
}

__global__ void rope_apply_kernel() {
    int idx = blockIdx.x * blockDim.x + threadIdx.x;
    int total = NBH*SEQ*64;
    if (idx >= total) return;
    int i = idx & 63;
    int rowid = idx >> 6;
    int s = rowid & (SEQ - 1);
    float c  = g_cos[s*64 + i];
    float sn = g_sin[s*64 + i];
    int base = rowid * HDIM;
    float q1 = g_q[base + i], q2 = g_q[base + 64 + i];
    float k1 = g_k[base + i], k2 = g_k[base + 64 + i];
    split_store_h(gq_hi, gq_lo, base + i,      q1*c - q2*sn);
    split_store_h(gq_hi, gq_lo, base + 64 + i, q2*c + q1*sn);
    gk_hi[base + i]      = __float2half(k1*c - k2*sn);    // K hi-only
    gk_hi[base + 64 + i] = __float2half(k2*c + k1*sn);
}

// ---------------- V transpose: g_v[bh][s][d] -> gvt_hi[bh][d][s] -------------
__global__ void v_transpose_split() {
    __shared__ float t[32][33];
    int bh = blockIdx.z;
    int s0 = blockIdx.x * 32, d0 = blockIdx.y * 32;
    int tx = threadIdx.x, ty = threadIdx.y;   // 32 x 8
#pragma unroll
    for (int i = 0; i < 32; i += 8)
        t[ty + i][tx] = g_v[((size_t)bh*SEQ + s0 + ty + i) * HDIM + d0 + tx];
    __syncthreads();
#pragma unroll
    for (int i = 0; i < 32; i += 8) {
        float x = t[tx][ty + i];
        size_t off = ((size_t)bh*HDIM + d0 + ty + i) * SEQ + s0 + tx;
        gvt_hi[off] = __float2half(x);                    // V hi-only
    }
}

// ============================================================================
// FA2-style HMMA causal flash attention, fp16 split-2 (unchanged from R11).
// ============================================================================
#define BQ 128
#define BT 64
#define QSTR 136
#define KSTR 136
#define VSTR 72

#define OFF_QHI 0
#define SZ_Q    (BQ*QSTR*2)
#define OFF_QLO (OFF_QHI + SZ_Q)
#define OFF_KHI (OFF_QLO + SZ_Q)
#define SZ_K    (BT*KSTR*2)
#define OFF_VHI (OFF_KHI + SZ_K)
#define SZ_V    (HDIM*VSTR*2)
#define ATTN_SMEM (OFF_VHI + SZ_V)     // 105472

__global__ void __launch_bounds__(256, 2) attn_hmma(__half* __restrict__ Aout) {
    extern __shared__ char smem[];
    const uint32_t sb = smem_u32(smem);

    const int tid  = threadIdx.x;
    const int lane = tid & 31;
    const int w    = tid >> 5;               // warp owns rows [w*16, w*16+16)
    const int qt = gridDim.x - 1 - blockIdx.x;   // heavy tiles first
    const int bh = blockIdx.y;
    const int q0 = qt * BQ;

    const int l16 = lane & 15;
    const int g   = lane >> 2;
    const int c2  = (lane & 3) * 2;

    __half* s_qhi = (__half*)(smem + OFF_QHI);
    __half* s_qlo = (__half*)(smem + OFF_QLO);

    const __half* Kh = gk_hi + (size_t)bh*SEQ*HDIM;
    const __half* Vh = gvt_hi + (size_t)bh*HDIM*SEQ;

    auto prefetch_k = [&](int k0) {
#pragma unroll
        for (int it = 0; it < 4; it++) {
            int t = tid + it*256;
            int row = t >> 4, cc = t & 15;
            cpasync16(sb + OFF_KHI + (row*KSTR + cc*8)*2,
                      Kh + (size_t)(k0 + row)*HDIM + cc*8);
        }
    };
    auto prefetch_v = [&](int k0) {
#pragma unroll
        for (int it = 0; it < 4; it++) {
            int t = tid + it*256;
            int d = t >> 3, cc = t & 7;
            cpasync16(sb + OFF_VHI + (d*VSTR + cc*8)*2,
                      Vh + (size_t)d*SEQ + k0 + cc*8);
        }
    };

    prefetch_k(0); CP_COMMIT();
    prefetch_v(0); CP_COMMIT();

    // Q tile (hi & lo), once
    {
        const __half* qh = gq_hi + ((size_t)bh*SEQ + q0) * HDIM;
        const __half* ql = gq_lo + ((size_t)bh*SEQ + q0) * HDIM;
#pragma unroll
        for (int it = 0; it < 8; it++) {
            int t = tid + it*256;
            int row = t >> 4, cc = t & 15;
            *(uint4*)(s_qhi + row*QSTR + cc*8) = *(const uint4*)(qh + row*HDIM + cc*8);
        }
#pragma unroll
        for (int it = 0; it < 8; it++) {
            int t = tid + it*256;
            int row = t >> 4, cc = t & 15;
            *(uint4*)(s_qlo + row*QSTR + cc*8) = *(const uint4*)(ql + row*HDIM + cc*8);
        }
    }

    float m0 = -1e30f, m1 = -1e30f, l0 = 0.0f, l1 = 0.0f;
    float acc[16][4];
#pragma unroll
    for (int nt = 0; nt < 16; nt++)
#pragma unroll
        for (int e = 0; e < 4; e++) acc[nt][e] = 0.0f;

    const float rnorm = 0.088388347648318447f;

    const uint32_t qhi_b = sb + OFF_QHI + (((w*16 + l16)*QSTR) + (lane>>4)*8)*2;
    const uint32_t qlo_b = sb + OFF_QLO + (((w*16 + l16)*QSTR) + (lane>>4)*8)*2;
    const uint32_t khi_b = sb + OFF_KHI + (((l16&7)*KSTR) + (l16>>3)*8)*2;
    const uint32_t vhi_b = sb + OFF_VHI + (((l16&7)*VSTR) + (l16>>3)*8)*2;

    const int rbase = q0 + w*16 + g;

    const int ntiles = 2*qt + 2;
    for (int kt = 0; kt < ntiles; kt++) {
        const int k0 = kt * BT;

        CP_WAIT(1);          // K(kt) resident
        __syncthreads();     // K (and Q on iter 0) visible

        // ---- S = q_hi*k_hi + q_lo*k_hi ----
        float sacc[8][4];
#pragma unroll
        for (int nt = 0; nt < 8; nt++)
#pragma unroll
            for (int e = 0; e < 4; e++) sacc[nt][e] = 0.0f;

#pragma unroll
        for (int k16 = 0; k16 < HDIM; k16 += 16) {
            uint32_t bhi[8][2];
#pragma unroll
            for (int nt = 0; nt < 8; nt++)
                ldsm2(bhi[nt], khi_b + (nt*8*KSTR + k16)*2);
            uint32_t ahi[4], alo[4];
            ldsm4(ahi, qhi_b + k16*2);
            ldsm4(alo, qlo_b + k16*2);
#pragma unroll
            for (int nt = 0; nt < 8; nt++) {
                mma16816h(sacc[nt], ahi, bhi[nt]);
                mma16816h(sacc[nt], alo, bhi[nt]);
            }
        }
        __syncthreads();     // K(kt) reads retired

        if (kt + 1 < ntiles) prefetch_k(k0 + BT);
        CP_COMMIT();

        // ---- mask + scale + register softmax ----
#pragma unroll
        for (int nt = 0; nt < 8; nt++) {
#pragma unroll
            for (int e = 0; e < 4; e++) {
                int r = rbase + (e >> 1)*8;
                int c = k0 + nt*8 + c2 + (e & 1);
                float v = sacc[nt][e] * rnorm;
                if (c > r) v = -10000.0f;
                sacc[nt][e] = v;
            }
        }
        float mx0 = -1e30f, mx1 = -1e30f;
#pragma unroll
        for (int nt = 0; nt < 8; nt++) {
            mx0 = fmaxf(mx0, fmaxf(sacc[nt][0], sacc[nt][1]));
            mx1 = fmaxf(mx1, fmaxf(sacc[nt][2], sacc[nt][3]));
        }
        mx0 = fmaxf(mx0, __shfl_xor_sync(0xFFFFFFFFu, mx0, 1));
        mx0 = fmaxf(mx0, __shfl_xor_sync(0xFFFFFFFFu, mx0, 2));
        mx1 = fmaxf(mx1, __shfl_xor_sync(0xFFFFFFFFu, mx1, 1));
        mx1 = fmaxf(mx1, __shfl_xor_sync(0xFFFFFFFFu, mx1, 2));
        float mn0 = fmaxf(m0, mx0), mn1 = fmaxf(m1, mx1);
        float scl0 = __expf(m0 - mn0), scl1 = __expf(m1 - mn1);
        m0 = mn0; m1 = mn1;
        float sum0 = 0.0f, sum1 = 0.0f;
#pragma unroll
        for (int nt = 0; nt < 8; nt++) {
            float p0 = __expf(sacc[nt][0] - m0);
            float p1 = __expf(sacc[nt][1] - m0);
            float p2 = __expf(sacc[nt][2] - m1);
            float p3 = __expf(sacc[nt][3] - m1);
            sacc[nt][0] = p0; sacc[nt][1] = p1;
            sacc[nt][2] = p2; sacc[nt][3] = p3;
            sum0 += p0 + p1; sum1 += p2 + p3;
        }
        l0 = l0 * scl0 + sum0;
        l1 = l1 * scl1 + sum1;
#pragma unroll
        for (int nt = 0; nt < 16; nt++) {
            acc[nt][0] *= scl0; acc[nt][1] *= scl0;
            acc[nt][2] *= scl1; acc[nt][3] *= scl1;
        }

        CP_WAIT(1);          // V(kt) resident
        __syncthreads();     // V visible

        // ---- O += p_hi*v_hi + p_lo*v_hi (P from registers) ----
#pragma unroll
        for (int s = 0; s < 4; s++) {
            uint32_t aph[4], apl[4];
            split_pack(sacc[2*s][0],   sacc[2*s][1],   aph[0], apl[0]);
            split_pack(sacc[2*s][2],   sacc[2*s][3],   aph[1], apl[1]);
            split_pack(sacc[2*s+1][0], sacc[2*s+1][1], aph[2], apl[2]);
            split_pack(sacc[2*s+1][2], sacc[2*s+1][3], aph[3], apl[3]);
#pragma unroll
            for (int nt = 0; nt < 16; nt++) {
                uint32_t bv[2];
                ldsm2(bv, vhi_b + (nt*8*VSTR + s*16)*2);
                mma16816h(acc[nt], aph, bv);
                mma16816h(acc[nt], apl, bv);
            }
        }
        __syncthreads();     // V(kt) reads retired

        if (kt + 1 < ntiles) prefetch_v(k0 + BT);
        CP_COMMIT();
    }

    // ---- finalize: quad-reduce l, divide, write fp16 split-2 dense A' ----
    l0 += __shfl_xor_sync(0xFFFFFFFFu, l0, 1);
    l0 += __shfl_xor_sync(0xFFFFFFFFu, l0, 2);
    l1 += __shfl_xor_sync(0xFFFFFFFFu, l1, 1);
    l1 += __shfl_xor_sync(0xFFFFFFFFu, l1, 2);
    const float linv0 = 1.0f / l0, linv1 = 1.0f / l1;
    const int b_idx = bh / NHEADS;
    const int h_idx = bh % NHEADS;
#pragma unroll
    for (int i = 0; i < 2; i++) {
        int r = rbase + i*8;
        float linv = i ? linv1 : linv0;
        size_t tok = (size_t)(r*BATCH + b_idx);
        __half* dst = Aout + tok*K2 + h_idx*HDIM;
#pragma unroll
        for (int nt = 0; nt < 16; nt++) {
#pragma unroll
            for (int j = 0; j < 2; j++) {
                float v = acc[nt][i*2 + j] * linv;
                __half h = __float2half(v);
                __half l = __float2half(v - __half2float(h));
                int cc = nt*8 + c2 + j;
                dst[cc]       = h;
                dst[HID + cc] = l;
            }
        }
    }
}

// ---------------- tail bias ---------------------------------------------------
__global__ void tail_copy(const float* __restrict__ src, float* __restrict__ dst, int n) {
    int i = blockIdx.x * blockDim.x + threadIdx.x;
    if (i < n) dst[i] = src[i];
}

// ---------------- launch -------------------------------------------------------
extern "C" void kernel_launch(void* const* d_in, const int* in_sizes, int n_in,
                              void* d_out, int out_size)
{
    const float* hidden  = (const float*)d_in[0];
    const float* w_qkv   = (const float*)d_in[2];
    const float* b_qkv   = (const float*)d_in[3];
    const float* w_dense = (const float*)d_in[4];
    const float* b_dense = (const float*)d_in[5];
    float* out = (float*)d_out;

    void *pA, *pBq, *pBd, *pQ, *pK, *pV;
    cudaGetSymbolAddress(&pA,   g_Abuf);
    cudaGetSymbolAddress(&pBq,  g_Bq);
    cudaGetSymbolAddress(&pBd,  g_Bd);
    cudaGetSymbolAddress(&pQ,   g_q);
    cudaGetSymbolAddress(&pK,   g_k);
    cudaGetSymbolAddress(&pV,   g_v);

    cudaFuncSetAttribute(hmma_gemm<1>, cudaFuncAttributeMaxDynamicSharedMemorySize, GEMM_SMEM);
    cudaFuncSetAttribute(hmma_gemm<2>, cudaFuncAttributeMaxDynamicSharedMemorySize, GEMM_SMEM);
    cudaFuncSetAttribute(attn_hmma, cudaFuncAttributeMaxDynamicSharedMemorySize, ATTN_SMEM);

    // 1) convert A (hidden -> [hi|lo]) and B (w_qkv -> hi)
    conv_split_a<<<(TOK*HID/4 + 255)/256, 256>>>(hidden, (__half*)pA, TOK, HID);
    conv_hi<<<(QKV_N*HID/4 + 255)/256, 256>>>(w_qkv, (__half*)pBq, QKV_N*HID/4);

    // 2) QKV projection (fp16 HMMA B-dedup, bias + scatter epilogue)
    hmma_gemm<1><<<dim3(QKV_N/128, TOK/128), 256, GEMM_SMEM>>>(
        (const __half*)pA, (const __half*)pBq, b_qkv, nullptr,
        (float*)pQ, (float*)pK, (float*)pV, QKV_N);

    // 3) RoPE (Q hi/lo, K hi) + V transpose (hi)
    rope_table_kernel<<<(SEQ*64 + 255)/256, 256>>>();
    rope_apply_kernel<<<(NBH*SEQ*64 + 255)/256, 256>>>();
    v_transpose_split<<<dim3(SEQ/32, HDIM/32, NBH), dim3(32, 8)>>>();

    // 4) causal attention (FA2 register softmax, fp16 split-2)
    attn_hmma<<<dim3(SEQ/BQ, NBH), 256, ATTN_SMEM>>>((__half*)pA);

    // 5) w_dense -> hi, dense GEMM (fp16 HMMA B-dedup)
    conv_hi<<<(HID*HID/4 + 255)/256, 256>>>(w_dense, (__half*)pBd, HID*HID/4);
    hmma_gemm<2><<<dim3(HID/128, TOK/128), 256, GEMM_SMEM>>>(
        (const __half*)pA, (const __half*)pBd, nullptr, out,
        nullptr, nullptr, nullptr, HID);

    // 6) bias tail if harness flattens the (output, bias) tuple
    int extra = out_size - TOK*HID;
    if (extra > 0)
        tail_copy<<<(extra + 255)/256, 256>>>(b_dense, out + (size_t)TOK*HID, extra);
    (void)in_sizes; (void)n_in;
}

// round 13
// speedup vs baseline: 4.4972x; 1.0773x over previous
#include <cuda_runtime.h>
#include <cuda_bf16.h>
#include <cuda_fp16.h>
#include <math.h>
#include <stdint.h>

#define SEQ     2048
#define BATCH   2
#define HID     2048
#define NHEADS  16
#define HDIM    128
#define TOK     (SEQ*BATCH)     // 4096
#define QKV_N   (3*HID)         // 6144
#define K2      (2*HID)         // A' split-2 width (hi|lo)
#define NBH     (BATCH*NHEADS)  // 32

// ---------------- scratch (device globals; no runtime allocs allowed) -------
__device__ float g_q[NBH*SEQ*HDIM];
__device__ float g_k[NBH*SEQ*HDIM];
__device__ float g_v[NBH*SEQ*HDIM];
__device__ float g_cos[SEQ*64];
__device__ float g_sin[SEQ*64];
// GEMM operands: A' = [hi|lo] (stride K2); B = hi only (stride HID)
__device__ __align__(1024) __half g_Abuf[TOK*K2];
__device__ __align__(1024) __half g_Bq[QKV_N*HID];
__device__ __align__(1024) __half g_Bd[HID*HID];
// attention operands: Q split-2 (hi+lo), K/V hi-only
__device__ __align__(16) __half gq_hi[NBH*SEQ*HDIM];
__device__ __align__(16) __half gq_lo[NBH*SEQ*HDIM];
__device__ __align__(16) __half gk_hi[NBH*SEQ*HDIM];
__device__ __align__(16) __half gvt_hi[NBH*HDIM*SEQ];   // [bh][d][s]

// ============================================================================
// PTX helpers (base-target-safe)
// ============================================================================
__device__ __forceinline__ uint32_t smem_u32(const void* p) {
    uint32_t a;
    asm("{ .reg .u64 t; cvta.to.shared.u64 t, %1; cvt.u32.u64 %0, t; }"
        : "=r"(a) : "l"(p));
    return a;
}
__device__ __forceinline__ void cpasync16(uint32_t s, const void* g) {
    asm volatile("cp.async.cg.shared.global [%0], [%1], 16;" :: "r"(s), "l"(g));
}
#define CP_COMMIT() asm volatile("cp.async.commit_group;" ::: "memory")
#define CP_WAIT(n)  asm volatile("cp.async.wait_group %0;" :: "n"(n) : "memory")

__device__ __forceinline__ void ldsm4(uint32_t* r, uint32_t a) {
    asm volatile("ldmatrix.sync.aligned.m8n8.x4.shared.b16 {%0,%1,%2,%3}, [%4];"
        : "=r"(r[0]), "=r"(r[1]), "=r"(r[2]), "=r"(r[3]) : "r"(a));
}
__device__ __forceinline__ void mma16816h(float* c, const uint32_t* a, const uint32_t* b) {
    asm volatile("mma.sync.aligned.m16n8k16.row.col.f32.f16.f16.f32 "
        "{%0,%1,%2,%3}, {%4,%5,%6,%7}, {%8,%9}, {%0,%1,%2,%3};"
        : "+f"(c[0]), "+f"(c[1]), "+f"(c[2]), "+f"(c[3])
        : "r"(a[0]), "r"(a[1]), "r"(a[2]), "r"(a[3]), "r"(b[0]), "r"(b[1]));
}
// pack two floats into fp16x2 hi + residual lo fragments
__device__ __forceinline__ void split_pack(float a, float b, uint32_t& hi, uint32_t& lo) {
    __half ha = __float2half(a), hb = __float2half(b);
    __half la = __float2half(a - __half2float(ha));
    __half lb = __float2half(b - __half2float(hb));
    hi = (uint32_t)__half_as_ushort(ha) | ((uint32_t)__half_as_ushort(hb) << 16);
    lo = (uint32_t)__half_as_ushort(la) | ((uint32_t)__half_as_ushort(lb) << 16);
}
// per-lane address shaping for paired-B ldsm4: two n-groups x one k16
// lane -> row (lane&7) + ((lane>>4)<<3), k-offset ((lane>>3)&1)*8
__device__ __forceinline__ uint32_t bpair_off(int lane, int stride_h) {
    int row = (lane & 7) + ((lane >> 4) << 3);
    int kof = ((lane >> 3) & 1) * 8;
    return (uint32_t)((row * stride_h + kof) * 2);
}

// ============================================================================
// HMMA fp16 split-2 GEMM, B-dedup: C = A_hi*B + A_lo*B over K=2048.
// CTA tile 128x128x32, 256 thr, warps 4(m) x 2(n), warp tile 32x64.
// 3-stage ring of [Ahi|Alo|B] tiles, one barrier per K-step.
// B fragments loaded pairwise via ldsm4 (2 nt per instruction).
// ============================================================================
#define BK 32
#define ASTR 40
#define TILE_B16 (128*ASTR)            // 5120 halfs per tile
#define STAGE_B16 (3*TILE_B16)         // Ahi + Alo + B
#define STAGE_BYTES (STAGE_B16*2)      // 30720
#define GSTAGES 3
#define GEMM_SMEM (GSTAGES*STAGE_BYTES)  // 92160

template<int MODE>
__global__ void __launch_bounds__(256, 2)
hmma_gemm(const __half* __restrict__ Ag, const __half* __restrict__ Bg,
          const float* __restrict__ bias, float* __restrict__ C,
          float* __restrict__ q_out, float* __restrict__ k_out, float* __restrict__ v_out,
          int N)
{
    extern __shared__ __align__(16) __half smbuf[];

    const int tid  = threadIdx.x;
    const int lane = tid & 31;
    const int warp = tid >> 5;
    const int wm = warp >> 1;          // 0..3 (32-row slabs)
    const int wn = warp & 1;           // 0..1 (64-col slabs)
    const int m0 = blockIdx.y * 128;
    const int n0 = blockIdx.x * 128;

    const uint32_t smb = smem_u32(smbuf);
    const int cr  = tid >> 2;          // row 0..63 (+64 second half)
    const int ccn = tid & 3;           // 16B chunk within 64B row
    const int KT  = HID / BK;          // 64

    auto prefetch = [&](int kt, int slot) {
        uint32_t base = smb + slot * STAGE_BYTES;
#pragma unroll
        for (int h = 0; h < 2; h++) {
            int r = cr + h * 64;
            uint32_t so = (r * ASTR + ccn * 8) * 2;
            cpasync16(base + so,
                      Ag + (size_t)(m0 + r) * K2 + kt * BK + ccn * 8);
            cpasync16(base + TILE_B16*2 + so,
                      Ag + (size_t)(m0 + r) * K2 + HID + kt * BK + ccn * 8);
            cpasync16(base + 2*TILE_B16*2 + so,
                      Bg + (size_t)(n0 + r) * HID + kt * BK + ccn * 8);
        }
    };

    float acc[2][8][4];
#pragma unroll
    for (int i = 0; i < 2; i++)
#pragma unroll
        for (int j = 0; j < 8; j++)
#pragma unroll
            for (int e = 0; e < 4; e++) acc[i][j][e] = 0.0f;

    const int l16 = lane & 15;
    const uint32_t a_off = (((wm * 32 + l16) * ASTR) + ((lane >> 4) * 8)) * 2;
    const uint32_t b_off = (uint32_t)(wn * 64 * ASTR * 2) + bpair_off(lane, ASTR);

    prefetch(0, 0); CP_COMMIT();
    prefetch(1, 1); CP_COMMIT();

    int slot = 0, pslot = 2;
    for (int kt = 0; kt < KT; kt++) {
        CP_WAIT(1);
        __syncthreads();
        int pf = kt + 2;
        if (pf < KT) prefetch(pf, pslot);
        CP_COMMIT();

        uint32_t ahib = smb + slot * STAGE_BYTES + a_off;
        uint32_t alob = ahib + TILE_B16*2;
        uint32_t bb   = smb + slot * STAGE_BYTES + 2*TILE_B16*2 + b_off;

#pragma unroll
        for (int k16 = 0; k16 < BK; k16 += 16) {
            uint32_t bfr[8][2];
#pragma unroll
            for (int p = 0; p < 4; p++) {
                uint32_t r4[4];
                ldsm4(r4, bb + (p * 16 * ASTR + k16) * 2);
                bfr[2*p + 0][0] = r4[0]; bfr[2*p + 0][1] = r4[1];
                bfr[2*p + 1][0] = r4[2]; bfr[2*p + 1][1] = r4[3];
            }
#pragma unroll
            for (int mt = 0; mt < 2; mt++) {
                uint32_t ahi[4], alo[4];
                ldsm4(ahi, ahib + (mt * 16 * ASTR + k16) * 2);
                ldsm4(alo, alob + (mt * 16 * ASTR + k16) * 2);
#pragma unroll
                for (int nt = 0; nt < 8; nt++) {
                    mma16816h(acc[mt][nt], ahi, bfr[nt]);
                    mma16816h(acc[mt][nt], alo, bfr[nt]);
                }
            }
        }
        if (++slot == 3) slot = 0;
        if (++pslot == 3) pslot = 0;
    }

    const int g  = lane >> 2;
    const int c2 = (lane & 3) * 2;
#pragma unroll
    for (int mt = 0; mt < 2; mt++) {
#pragma unroll
        for (int nt = 0; nt < 8; nt++) {
#pragma unroll
            for (int i = 0; i < 2; i++) {
#pragma unroll
                for (int j = 0; j < 2; j++) {
                    int m = m0 + wm * 32 + mt * 16 + g + i * 8;
                    int n = n0 + wn * 64 + nt * 8 + c2 + j;
                    float v = acc[mt][nt][i * 2 + j];
                    if (MODE == 1) {
                        v += bias[n];
                        int head = n / (3 * HDIM);
                        int r3   = n % (3 * HDIM);
                        int part = r3 / HDIM;
                        int d    = r3 % HDIM;
                        int off  = (((m & 1) * NHEADS + head) * SEQ + (m >> 1)) * HDIM + d;
                        if      (part == 0) q_out[off] = v;
                        else if (part == 1) k_out[off] = v;
                        else                v_out[off] = v;
                    } else {
                        C[(size_t)m * N + n] = v;
                    }
                }
            }
        }
    }
}

// ---------------- conversions -------------------------------------------------
__global__ void conv_split_a(const float* __restrict__ src,
                             __half* __restrict__ dst, int R, int K)
{
    int idx = blockIdx.x * blockDim.x + threadIdx.x;     // float4 index
    int kq = K >> 2;
    if (idx >= R * kq) return;
    int row = idx / kq, c4 = idx - row * kq;
    float4 x = ((const float4*)src)[idx];
    __half hi[4];
    hi[0] = __float2half(x.x); hi[1] = __float2half(x.y);
    hi[2] = __float2half(x.z); hi[3] = __float2half(x.w);
    size_t base = (size_t)row * (2*K) + c4 * 4;
    *(uint2*)(dst + base) = *(uint2*)hi;
    __half lo[4];
    lo[0] = __float2half(x.x - __half2float(hi[0]));
    lo[1] = __float2half(x.y - __half2float(hi[1]));
    lo[2] = __float2half(x.z - __half2float(hi[2]));
    lo[3] = __float2half(x.w - __half2float(hi[3]));
    *(uint2*)(dst + base + K) = *(uint2*)lo;
}
__global__ void conv_hi(const float* __restrict__ src,
                        __half* __restrict__ dst, int n4)
{
    int idx = blockIdx.x * blockDim.x + threadIdx.x;
    if (idx >= n4) return;
    float4 x = ((const float4*)src)[idx];
    __half h[4];
    h[0] = __float2half(x.x); h[1] = __float2half(x.y);
    h[2] = __float2half(x.z); h[3] = __float2half(x.w);
    *(uint2*)(dst + (size_t)idx * 4) = *(uint2*)h;
}

// ---------------- RoPE tables + apply ----------------------------------------
__global__ void rope_table_kernel() {
    __shared__ float invf[64];
    if (threadIdx.x < 64)
        invf[threadIdx.x] = (float)pow(10000.0, -((double)threadIdx.x) / 64.0);
    __syncthreads();
    int idx = blockIdx.x * blockDim.x + threadIdx.x;
    if (idx >= SEQ * 64) return;
    int s = idx >> 6;
    int i = idx & 63;
    float theta = (float)s * invf[i];
    g_cos[idx] = cosf(theta);
    g_sin[idx] = sinf(theta);
}

__device__ __forceinline__ void split_store_h(__half* hi, __half* lo,
                                              int off, float x) {
    __half h = __float2half(x);
    hi[off] = h;
    lo[off] = __float2half(x - __half2float(h));
}

__global__ void rope_apply_kernel() {
    int idx = blockIdx.x * blockDim.x + threadIdx.x;
    int total = NBH*SEQ*64;
    if (idx >= total) return;
    int i = idx & 63;
    int rowid = idx >> 6;
    int s = rowid & (SEQ - 1);
    float c  = g_cos[s*64 + i];
    float sn = g_sin[s*64 + i];
    int base = rowid * HDIM;
    float q1 = g_q[base + i], q2 = g_q[base + 64 + i];
    float k1 = g_k[base + i], k2 = g_k[base + 64 + i];
    split_store_h(gq_hi, gq_lo, base + i,      q1*c - q2*sn);
    split_store_h(gq_hi, gq_lo, base + 64 + i, q2*c + q1*sn);
    gk_hi[base + i]      = __float2half(k1*c - k2*sn);    // K hi-only
    gk_hi[base + 64 + i] = __float2half(k2*c + k1*sn);
}

// ---------------- V transpose: g_v[bh][s][d] -> gvt_hi[bh][d][s] -------------
__global__ void v_transpose_split() {
    __shared__ float t[32][33];
    int bh = blockIdx.z;
    int s0 = blockIdx.x * 32, d0 = blockIdx.y * 32;
    int tx = threadIdx.x, ty = threadIdx.y;   // 32 x 8
#pragma unroll
    for (int i = 0; i < 32; i += 8)
        t[ty + i][tx] = g_v[((size_t)bh*SEQ + s0 + ty + i) * HDIM + d0 + tx];
    __syncthreads();
#pragma unroll
    for (int i = 0; i < 32; i += 8) {
        float x = t[tx][ty + i];
        size_t off = ((size_t)bh*HDIM + d0 + ty + i) * SEQ + s0 + tx;
        gvt_hi[off] = __float2half(x);                    // V hi-only
    }
}

// ============================================================================
// FA2-style HMMA causal flash attention, fp16 split-2; K/V fragments loaded
// pairwise via ldsm4 (2 n-groups per instruction).
// ============================================================================
#define BQ 128
#define BT 64
#define QSTR 136
#define KSTR 136
#define VSTR 72

#define OFF_QHI 0
#define SZ_Q    (BQ*QSTR*2)
#define OFF_QLO (OFF_QHI + SZ_Q)
#define OFF_KHI (OFF_QLO + SZ_Q)
#define SZ_K    (BT*KSTR*2)
#define OFF_VHI (OFF_KHI + SZ_K)
#define SZ_V    (HDIM*VSTR*2)
#define ATTN_SMEM (OFF_VHI + SZ_V)     // 105472

__global__ void __launch_bounds__(256, 2) attn_hmma(__half* __restrict__ Aout) {
    extern __shared__ char smem[];
    const uint32_t sb = smem_u32(smem);

    const int tid  = threadIdx.x;
    const int lane = tid & 31;
    const int w    = tid >> 5;               // warp owns rows [w*16, w*16+16)
    const int qt = gridDim.x - 1 - blockIdx.x;   // heavy tiles first
    const int bh = blockIdx.y;
    const int q0 = qt * BQ;

    const int l16 = lane & 15;
    const int g   = lane >> 2;
    const int c2  = (lane & 3) * 2;

    __half* s_qhi = (__half*)(smem + OFF_QHI);
    __half* s_qlo = (__half*)(smem + OFF_QLO);

    const __half* Kh = gk_hi + (size_t)bh*SEQ*HDIM;
    const __half* Vh = gvt_hi + (size_t)bh*HDIM*SEQ;

    auto prefetch_k = [&](int k0) {
#pragma unroll
        for (int it = 0; it < 4; it++) {
            int t = tid + it*256;
            int row = t >> 4, cc = t & 15;
            cpasync16(sb + OFF_KHI + (row*KSTR + cc*8)*2,
                      Kh + (size_t)(k0 + row)*HDIM + cc*8);
        }
    };
    auto prefetch_v = [&](int k0) {
#pragma unroll
        for (int it = 0; it < 4; it++) {
            int t = tid + it*256;
            int d = t >> 3, cc = t & 7;
            cpasync16(sb + OFF_VHI + (d*VSTR + cc*8)*2,
                      Vh + (size_t)d*SEQ + k0 + cc*8);
        }
    };

    prefetch_k(0); CP_COMMIT();
    prefetch_v(0); CP_COMMIT();

    // Q tile (hi & lo), once
    {
        const __half* qh = gq_hi + ((size_t)bh*SEQ + q0) * HDIM;
        const __half* ql = gq_lo + ((size_t)bh*SEQ + q0) * HDIM;
#pragma unroll
        for (int it = 0; it < 8; it++) {
            int t = tid + it*256;
            int row = t >> 4, cc = t & 15;
            *(uint4*)(s_qhi + row*QSTR + cc*8) = *(const uint4*)(qh + row*HDIM + cc*8);
        }
#pragma unroll
        for (int it = 0; it < 8; it++) {
            int t = tid + it*256;
            int row = t >> 4, cc = t & 15;
            *(uint4*)(s_qlo + row*QSTR + cc*8) = *(const uint4*)(ql + row*HDIM + cc*8);
        }
    }

    float m0 = -1e30f, m1 = -1e30f, l0 = 0.0f, l1 = 0.0f;
    float acc[16][4];
#pragma unroll
    for (int nt = 0; nt < 16; nt++)
#pragma unroll
        for (int e = 0; e < 4; e++) acc[nt][e] = 0.0f;

    const float rnorm = 0.088388347648318447f;

    const uint32_t qhi_b = sb + OFF_QHI + (((w*16 + l16)*QSTR) + (lane>>4)*8)*2;
    const uint32_t qlo_b = sb + OFF_QLO + (((w*16 + l16)*QSTR) + (lane>>4)*8)*2;
    const uint32_t khi4  = sb + OFF_KHI + bpair_off(lane, KSTR);
    const uint32_t vhi4  = sb + OFF_VHI + bpair_off(lane, VSTR);

    const int rbase = q0 + w*16 + g;

    const int ntiles = 2*qt + 2;
    for (int kt = 0; kt < ntiles; kt++) {
        const int k0 = kt * BT;

        CP_WAIT(1);          // K(kt) resident
        __syncthreads();     // K (and Q on iter 0) visible

        // ---- S = q_hi*k_hi + q_lo*k_hi (paired-K ldsm4) ----
        float sacc[8][4];
#pragma unroll
        for (int nt = 0; nt < 8; nt++)
#pragma unroll
            for (int e = 0; e < 4; e++) sacc[nt][e] = 0.0f;

#pragma unroll
        for (int k16 = 0; k16 < HDIM; k16 += 16) {
            uint32_t bhi[8][2];
#pragma unroll
            for (int p = 0; p < 4; p++) {
                uint32_t r4[4];
                ldsm4(r4, khi4 + (p*16*KSTR + k16)*2);
                bhi[2*p + 0][0] = r4[0]; bhi[2*p + 0][1] = r4[1];
                bhi[2*p + 1][0] = r4[2]; bhi[2*p + 1][1] = r4[3];
            }
            uint32_t ahi[4], alo[4];
            ldsm4(ahi, qhi_b + k16*2);
            ldsm4(alo, qlo_b + k16*2);
#pragma unroll
            for (int nt = 0; nt < 8; nt++) {
                mma16816h(sacc[nt], ahi, bhi[nt]);
                mma16816h(sacc[nt], alo, bhi[nt]);
            }
        }
        __syncthreads();     // K(kt) reads retired

        if (kt + 1 < ntiles) prefetch_k(k0 + BT);
        CP_COMMIT();

        // ---- mask + scale + register softmax ----
#pragma unroll
        for (int nt = 0; nt < 8; nt++) {
#pragma unroll
            for (int e = 0; e < 4; e++) {
                int r = rbase + (e >> 1)*8;
                int c = k0 + nt*8 + c2 + (e & 1);
                float v = sacc[nt][e] * rnorm;
                if (c > r) v = -10000.0f;
                sacc[nt][e] = v;
            }
        }
        float mx0 = -1e30f, mx1 = -1e30f;
#pragma unroll
        for (int nt = 0; nt < 8; nt++) {
            mx0 = fmaxf(mx0, fmaxf(sacc[nt][0], sacc[nt][1]));
            mx1 = fmaxf(mx1, fmaxf(sacc[nt][2], sacc[nt][3]));
        }
        mx0 = fmaxf(mx0, __shfl_xor_sync(0xFFFFFFFFu, mx0, 1));
        mx0 = fmaxf(mx0, __shfl_xor_sync(0xFFFFFFFFu, mx0, 2));
        mx1 = fmaxf(mx1, __shfl_xor_sync(0xFFFFFFFFu, mx1, 1));
        mx1 = fmaxf(mx1, __shfl_xor_sync(0xFFFFFFFFu, mx1, 2));
        float mn0 = fmaxf(m0, mx0), mn1 = fmaxf(m1, mx1);
        float scl0 = __expf(m0 - mn0), scl1 = __expf(m1 - mn1);
        m0 = mn0; m1 = mn1;
        float sum0 = 0.0f, sum1 = 0.0f;
#pragma unroll
        for (int nt = 0; nt < 8; nt++) {
            float p0 = __expf(sacc[nt][0] - m0);
            float p1 = __expf(sacc[nt][1] - m0);
            float p2 = __expf(sacc[nt][2] - m1);
            float p3 = __expf(sacc[nt][3] - m1);
            sacc[nt][0] = p0; sacc[nt][1] = p1;
            sacc[nt][2] = p2; sacc[nt][3] = p3;
            sum0 += p0 + p1; sum1 += p2 + p3;
        }
        l0 = l0 * scl0 + sum0;
        l1 = l1 * scl1 + sum1;
#pragma unroll
        for (int nt = 0; nt < 16; nt++) {
            acc[nt][0] *= scl0; acc[nt][1] *= scl0;
            acc[nt][2] *= scl1; acc[nt][3] *= scl1;
        }

        CP_WAIT(1);          // V(kt) resident
        __syncthreads();     // V visible

        // ---- O += p_hi*v_hi + p_lo*v_hi (paired-V ldsm4) ----
#pragma unroll
        for (int s = 0; s < 4; s++) {
            uint32_t aph[4], apl[4];
            split_pack(sacc[2*s][0],   sacc[2*s][1],   aph[0], apl[0]);
            split_pack(sacc[2*s][2],   sacc[2*s][3],   aph[1], apl[1]);
            split_pack(sacc[2*s+1][0], sacc[2*s+1][1], aph[2], apl[2]);
            split_pack(sacc[2*s+1][2], sacc[2*s+1][3], aph[3], apl[3]);
#pragma unroll
            for (int p = 0; p < 8; p++) {
                uint32_t r4[4];
                ldsm4(r4, vhi4 + (p*16*VSTR + s*16)*2);
                uint32_t bv0[2] = {r4[0], r4[1]};
                uint32_t bv1[2] = {r4[2], r4[3]};
                mma16816h(acc[2*p + 0], aph, bv0);
                mma16816h(acc[2*p + 0], apl, bv0);
                mma16816h(acc[2*p + 1], aph, bv1);
                mma16816h(acc[2*p + 1], apl, bv1);
            }
        }
        __syncthreads();     // V(kt) reads retired

        if (kt + 1 < ntiles) prefetch_v(k0 + BT);
        CP_COMMIT();
    }

    // ---- finalize: quad-reduce l, divide, write fp16 split-2 dense A' ----
    l0 += __shfl_xor_sync(0xFFFFFFFFu, l0, 1);
    l0 += __shfl_xor_sync(0xFFFFFFFFu, l0, 2);
    l1 += __shfl_xor_sync(0xFFFFFFFFu, l1, 1);
    l1 += __shfl_xor_sync(0xFFFFFFFFu, l1, 2);
    const float linv0 = 1.0f / l0, linv1 = 1.0f / l1;
    const int b_idx = bh / NHEADS;
    const int h_idx = bh % NHEADS;
#pragma unroll
    for (int i = 0; i < 2; i++) {
        int r = rbase + i*8;
        float linv = i ? linv1 : linv0;
        size_t tok = (size_t)(r*BATCH + b_idx);
        __half* dst = Aout + tok*K2 + h_idx*HDIM;
#pragma unroll
        for (int nt = 0; nt < 16; nt++) {
#pragma unroll
            for (int j = 0; j < 2; j++) {
                float v = acc[nt][i*2 + j] * linv;
                __half h = __float2half(v);
                __half l = __float2half(v - __half2float(h));
                int cc = nt*8 + c2 + j;
                dst[cc]       = h;
                dst[HID + cc] = l;
            }
        }
    }
}

// ---------------- tail bias ---------------------------------------------------
__global__ void tail_copy(const float* __restrict__ src, float* __restrict__ dst, int n) {
    int i = blockIdx.x * blockDim.x + threadIdx.x;
    if (i < n) dst[i] = src[i];
}

// ---------------- launch -------------------------------------------------------
extern "C" void kernel_launch(void* const* d_in, const int* in_sizes, int n_in,
                              void* d_out, int out_size)
{
    const float* hidden  = (const float*)d_in[0];
    const float* w_qkv   = (const float*)d_in[2];
    const float* b_qkv   = (const float*)d_in[3];
    const float* w_dense = (const float*)d_in[4];
    const float* b_dense = (const float*)d_in[5];
    float* out = (float*)d_out;

    void *pA, *pBq, *pBd, *pQ, *pK, *pV;
    cudaGetSymbolAddress(&pA,   g_Abuf);
    cudaGetSymbolAddress(&pBq,  g_Bq);
    cudaGetSymbolAddress(&pBd,  g_Bd);
    cudaGetSymbolAddress(&pQ,   g_q);
    cudaGetSymbolAddress(&pK,   g_k);
    cudaGetSymbolAddress(&pV,   g_v);

    cudaFuncSetAttribute(hmma_gemm<1>, cudaFuncAttributeMaxDynamicSharedMemorySize, GEMM_SMEM);
    cudaFuncSetAttribute(hmma_gemm<2>, cudaFuncAttributeMaxDynamicSharedMemorySize, GEMM_SMEM);
    cudaFuncSetAttribute(attn_hmma, cudaFuncAttributeMaxDynamicSharedMemorySize, ATTN_SMEM);

    // 1) convert A (hidden -> [hi|lo]) and B (w_qkv -> hi)
    conv_split_a<<<(TOK*HID/4 + 255)/256, 256>>>(hidden, (__half*)pA, TOK, HID);
    conv_hi<<<(QKV_N*HID/4 + 255)/256, 256>>>(w_qkv, (__half*)pBq, QKV_N*HID/4);

    // 2) QKV projection (fp16 HMMA B-dedup, bias + scatter epilogue)
    hmma_gemm<1><<<dim3(QKV_N/128, TOK/128), 256, GEMM_SMEM>>>(
        (const __half*)pA, (const __half*)pBq, b_qkv, nullptr,
        (float*)pQ, (float*)pK, (float*)pV, QKV_N);

    // 3) RoPE (Q hi/lo, K hi) + V transpose (hi)
    rope_table_kernel<<<(SEQ*64 + 255)/256, 256>>>();
    rope_apply_kernel<<<(NBH*SEQ*64 + 255)/256, 256>>>();
    v_transpose_split<<<dim3(SEQ/32, HDIM/32, NBH), dim3(32, 8)>>>();

    // 4) causal attention (FA2 register softmax, fp16 split-2, paired ldsm4)
    attn_hmma<<<dim3(SEQ/BQ, NBH), 256, ATTN_SMEM>>>((__half*)pA);

    // 5) w_dense -> hi, dense GEMM (fp16 HMMA B-dedup)
    conv_hi<<<(HID*HID/4 + 255)/256, 256>>>(w_dense, (__half*)pBd, HID*HID/4);
    hmma_gemm<2><<<dim3(HID/128, TOK/128), 256, GEMM_SMEM>>>(
        (const __half*)pA, (const __half*)pBd, nullptr, out,
        nullptr, nullptr, nullptr, HID);

    // 6) bias tail if harness flattens the (output, bias) tuple
    int extra = out_size - TOK*HID;
    if (extra > 0)
        tail_copy<<<(extra + 255)/256, 256>>>(b_dense, out + (size_t)TOK*HID, extra);
    (void)in_sizes; (void)n_in;
}

// round 14
// speedup vs baseline: 4.7487x; 1.0559x over previous
#include <cuda_runtime.h>
#include <cuda_bf16.h>
#include <cuda_fp16.h>
#include <math.h>
#include <stdint.h>

#define SEQ     2048
#define BATCH   2
#define HID     2048
#define NHEADS  16
#define HDIM    128
#define TOK     (SEQ*BATCH)     // 4096
#define QKV_N   (3*HID)         // 6144
#define K2      (2*HID)         // A' split-2 width (hi|lo)
#define NBH     (BATCH*NHEADS)  // 32

// ---------------- scratch (device globals; no runtime allocs allowed) -------
__device__ float g_q[NBH*SEQ*HDIM];
__device__ float g_k[NBH*SEQ*HDIM];
__device__ float g_v[NBH*SEQ*HDIM];
__device__ float g_cos[SEQ*64];
__device__ float g_sin[SEQ*64];
// GEMM operands: A' = [hi|lo] (stride K2); B = hi only (stride HID)
__device__ __align__(1024) __half g_Abuf[TOK*K2];
__device__ __align__(1024) __half g_Bq[QKV_N*HID];
__device__ __align__(1024) __half g_Bd[HID*HID];
// attention operands: Q split-2 (hi+lo), K/V hi-only
__device__ __align__(16) __half gq_hi[NBH*SEQ*HDIM];
__device__ __align__(16) __half gq_lo[NBH*SEQ*HDIM];
__device__ __align__(16) __half gk_hi[NBH*SEQ*HDIM];
__device__ __align__(16) __half gvt_hi[NBH*HDIM*SEQ];   // [bh][d][s]

// ============================================================================
// PTX helpers (base-target-safe)
// ============================================================================
__device__ __forceinline__ uint32_t smem_u32(const void* p) {
    uint32_t a;
    asm("{ .reg .u64 t; cvta.to.shared.u64 t, %1; cvt.u32.u64 %0, t; }"
        : "=r"(a) : "l"(p));
    return a;
}
__device__ __forceinline__ void cpasync16(uint32_t s, const void* g) {
    asm volatile("cp.async.cg.shared.global [%0], [%1], 16;" :: "r"(s), "l"(g));
}
#define CP_COMMIT() asm volatile("cp.async.commit_group;" ::: "memory")
#define CP_WAIT(n)  asm volatile("cp.async.wait_group %0;" :: "n"(n) : "memory")

__device__ __forceinline__ void ldsm4(uint32_t* r, uint32_t a) {
    asm volatile("ldmatrix.sync.aligned.m8n8.x4.shared.b16 {%0,%1,%2,%3}, [%4];"
        : "=r"(r[0]), "=r"(r[1]), "=r"(r[2]), "=r"(r[3]) : "r"(a));
}
__device__ __forceinline__ void mma16816h(float* c, const uint32_t* a, const uint32_t* b) {
    asm volatile("mma.sync.aligned.m16n8k16.row.col.f32.f16.f16.f32 "
        "{%0,%1,%2,%3}, {%4,%5,%6,%7}, {%8,%9}, {%0,%1,%2,%3};"
        : "+f"(c[0]), "+f"(c[1]), "+f"(c[2]), "+f"(c[3])
        : "r"(a[0]), "r"(a[1]), "r"(a[2]), "r"(a[3]), "r"(b[0]), "r"(b[1]));
}
// pack two floats into fp16x2 hi + residual lo fragments
__device__ __forceinline__ void split_pack(float a, float b, uint32_t& hi, uint32_t& lo) {
    __half ha = __float2half(a), hb = __float2half(b);
    __half la = __float2half(a - __half2float(ha));
    __half lb = __float2half(b - __half2float(hb));
    hi = (uint32_t)__half_as_ushort(ha) | ((uint32_t)__half_as_ushort(hb) << 16);
    lo = (uint32_t)__half_as_ushort(la) | ((uint32_t)__half_as_ushort(lb) << 16);
}
// per-lane address shaping for paired-B ldsm4: two n-groups x one k16
__device__ __forceinline__ uint32_t bpair_off(int lane, int stride_h) {
    int row = (lane & 7) + ((lane >> 4) << 3);
    int kof = ((lane >> 3) & 1) * 8;
    return (uint32_t)((row * stride_h + kof) * 2);
}

// ============================================================================
// HMMA fp16 split-2 GEMM, B-dedup (unchanged from R13).
// ============================================================================
#define BK 32
#define ASTR 40
#define TILE_B16 (128*ASTR)
#define STAGE_B16 (3*TILE_B16)
#define STAGE_BYTES (STAGE_B16*2)
#define GSTAGES 3
#define GEMM_SMEM (GSTAGES*STAGE_BYTES)

template<int MODE>
__global__ void __launch_bounds__(256, 2)
hmma_gemm(const __half* __restrict__ Ag, const __half* __restrict__ Bg,
          const float* __restrict__ bias, float* __restrict__ C,
          float* __restrict__ q_out, float* __restrict__ k_out, float* __restrict__ v_out,
          int N)
{
    extern __shared__ __align__(16) __half smbuf[];

    const int tid  = threadIdx.x;
    const int lane = tid & 31;
    const int warp = tid >> 5;
    const int wm = warp >> 1;
    const int wn = warp & 1;
    const int m0 = blockIdx.y * 128;
    const int n0 = blockIdx.x * 128;

    const uint32_t smb = smem_u32(smbuf);
    const int cr  = tid >> 2;
    const int ccn = tid & 3;
    const int KT  = HID / BK;          // 64

    auto prefetch = [&](int kt, int slot) {
        uint32_t base = smb + slot * STAGE_BYTES;
#pragma unroll
        for (int h = 0; h < 2; h++) {
            int r = cr + h * 64;
            uint32_t so = (r * ASTR + ccn * 8) * 2;
            cpasync16(base + so,
                      Ag + (size_t)(m0 + r) * K2 + kt * BK + ccn * 8);
            cpasync16(base + TILE_B16*2 + so,
                      Ag + (size_t)(m0 + r) * K2 + HID + kt * BK + ccn * 8);
            cpasync16(base + 2*TILE_B16*2 + so,
                      Bg + (size_t)(n0 + r) * HID + kt * BK + ccn * 8);
        }
    };

    float acc[2][8][4];
#pragma unroll
    for (int i = 0; i < 2; i++)
#pragma unroll
        for (int j = 0; j < 8; j++)
#pragma unroll
            for (int e = 0; e < 4; e++) acc[i][j][e] = 0.0f;

    const int l16 = lane & 15;
    const uint32_t a_off = (((wm * 32 + l16) * ASTR) + ((lane >> 4) * 8)) * 2;
    const uint32_t b_off = (uint32_t)(wn * 64 * ASTR * 2) + bpair_off(lane, ASTR);

    prefetch(0, 0); CP_COMMIT();
    prefetch(1, 1); CP_COMMIT();

    int slot = 0, pslot = 2;
    for (int kt = 0; kt < KT; kt++) {
        CP_WAIT(1);
        __syncthreads();
        int pf = kt + 2;
        if (pf < KT) prefetch(pf, pslot);
        CP_COMMIT();

        uint32_t ahib = smb + slot * STAGE_BYTES + a_off;
        uint32_t alob = ahib + TILE_B16*2;
        uint32_t bb   = smb + slot * STAGE_BYTES + 2*TILE_B16*2 + b_off;

#pragma unroll
        for (int k16 = 0; k16 < BK; k16 += 16) {
            uint32_t bfr[8][2];
#pragma unroll
            for (int p = 0; p < 4; p++) {
                uint32_t r4[4];
                ldsm4(r4, bb + (p * 16 * ASTR + k16) * 2);
                bfr[2*p + 0][0] = r4[0]; bfr[2*p + 0][1] = r4[1];
                bfr[2*p + 1][0] = r4[2]; bfr[2*p + 1][1] = r4[3];
            }
#pragma unroll
            for (int mt = 0; mt < 2; mt++) {
                uint32_t ahi[4], alo[4];
                ldsm4(ahi, ahib + (mt * 16 * ASTR + k16) * 2);
                ldsm4(alo, alob + (mt * 16 * ASTR + k16) * 2);
#pragma unroll
                for (int nt = 0; nt < 8; nt++) {
                    mma16816h(acc[mt][nt], ahi, bfr[nt]);
                    mma16816h(acc[mt][nt], alo, bfr[nt]);
                }
            }
        }
        if (++slot == 3) slot = 0;
        if (++pslot == 3) pslot = 0;
    }

    const int g  = lane >> 2;
    const int c2 = (lane & 3) * 2;
#pragma unroll
    for (int mt = 0; mt < 2; mt++) {
#pragma unroll
        for (int nt = 0; nt < 8; nt++) {
#pragma unroll
            for (int i = 0; i < 2; i++) {
#pragma unroll
                for (int j = 0; j < 2; j++) {
                    int m = m0 + wm * 32 + mt * 16 + g + i * 8;
                    int n = n0 + wn * 64 + nt * 8 + c2 + j;
                    float v = acc[mt][nt][i * 2 + j];
                    if (MODE == 1) {
                        v += bias[n];
                        int head = n / (3 * HDIM);
                        int r3   = n % (3 * HDIM);
                        int part = r3 / HDIM;
                        int d    = r3 % HDIM;
                        int off  = (((m & 1) * NHEADS + head) * SEQ + (m >> 1)) * HDIM + d;
                        if      (part == 0) q_out[off] = v;
                        else if (part == 1) k_out[off] = v;
                        else                v_out[off] = v;
                    } else {
                        C[(size_t)m * N + n] = v;
                    }
                }
            }
        }
    }
}

// ---------------- conversions -------------------------------------------------
__global__ void conv_split_a(const float* __restrict__ src,
                             __half* __restrict__ dst, int R, int K)
{
    int idx = blockIdx.x * blockDim.x + threadIdx.x;
    int kq = K >> 2;
    if (idx >= R * kq) return;
    int row = idx / kq, c4 = idx - row * kq;
    float4 x = ((const float4*)src)[idx];
    __half hi[4];
    hi[0] = __float2half(x.x); hi[1] = __float2half(x.y);
    hi[2] = __float2half(x.z); hi[3] = __float2half(x.w);
    size_t base = (size_t)row * (2*K) + c4 * 4;
    *(uint2*)(dst + base) = *(uint2*)hi;
    __half lo[4];
    lo[0] = __float2half(x.x - __half2float(hi[0]));
    lo[1] = __float2half(x.y - __half2float(hi[1]));
    lo[2] = __float2half(x.z - __half2float(hi[2]));
    lo[3] = __float2half(x.w - __half2float(hi[3]));
    *(uint2*)(dst + base + K) = *(uint2*)lo;
}
__global__ void conv_hi(const float* __restrict__ src,
                        __half* __restrict__ dst, int n4)
{
    int idx = blockIdx.x * blockDim.x + threadIdx.x;
    if (idx >= n4) return;
    float4 x = ((const float4*)src)[idx];
    __half h[4];
    h[0] = __float2half(x.x); h[1] = __float2half(x.y);
    h[2] = __float2half(x.z); h[3] = __float2half(x.w);
    *(uint2*)(dst + (size_t)idx * 4) = *(uint2*)h;
}

// ---------------- RoPE tables + apply ----------------------------------------
__global__ void rope_table_kernel() {
    __shared__ float invf[64];
    if (threadIdx.x < 64)
        invf[threadIdx.x] = (float)pow(10000.0, -((double)threadIdx.x) / 64.0);
    __syncthreads();
    int idx = blockIdx.x * blockDim.x + threadIdx.x;
    if (idx >= SEQ * 64) return;
    int s = idx >> 6;
    int i = idx & 63;
    float theta = (float)s * invf[i];
    g_cos[idx] = cosf(theta);
    g_sin[idx] = sinf(theta);
}

__device__ __forceinline__ void split_store_h(__half* hi, __half* lo,
                                              int off, float x) {
    __half h = __float2half(x);
    hi[off] = h;
    lo[off] = __float2half(x - __half2float(h));
}

__global__ void rope_apply_kernel() {
    int idx = blockIdx.x * blockDim.x + threadIdx.x;
    int total = NBH*SEQ*64;
    if (idx >= total) return;
    int i = idx & 63;
    int rowid = idx >> 6;
    int s = rowid & (SEQ - 1);
    float c  = g_cos[s*64 + i];
    float sn = g_sin[s*64 + i];
    int base = rowid * HDIM;
    float q1 = g_q[base + i], q2 = g_q[base + 64 + i];
    float k1 = g_k[base + i], k2 = g_k[base + 64 + i];
    split_store_h(gq_hi, gq_lo, base + i,      q1*c - q2*sn);
    split_store_h(gq_hi, gq_lo, base + 64 + i, q2*c + q1*sn);
    gk_hi[base + i]      = __float2half(k1*c - k2*sn);
    gk_hi[base + 64 + i] = __float2half(k2*c + k1*sn);
}

// ---------------- V transpose: g_v[bh][s][d] -> gvt_hi[bh][d][s] -------------
__global__ void v_transpose_split() {
    __shared__ float t[32][33];
    int bh = blockIdx.z;
    int s0 = blockIdx.x * 32, d0 = blockIdx.y * 32;
    int tx = threadIdx.x, ty = threadIdx.y;
#pragma unroll
    for (int i = 0; i < 32; i += 8)
        t[ty + i][tx] = g_v[((size_t)bh*SEQ + s0 + ty + i) * HDIM + d0 + tx];
    __syncthreads();
#pragma unroll
    for (int i = 0; i < 32; i += 8) {
        float x = t[tx][ty + i];
        size_t off = ((size_t)bh*HDIM + d0 + ty + i) * SEQ + s0 + tx;
        gvt_hi[off] = __float2half(x);
    }
}

// ============================================================================
// FA2-style HMMA causal flash attention, fp16 split-2, paired ldsm4.
// WORK PAIRING: each CTA processes TWO q-tiles (heavy qt=15-bx, then light
// qt=bx) so every CTA does exactly 36 key-tiles; 256 CTAs = one balanced wave.
// ============================================================================
#define BQ 128
#define BT 64
#define NQT (SEQ/BQ)          // 16
#define QSTR 136
#define KSTR 136
#define VSTR 72

#define OFF_QHI 0
#define SZ_Q    (BQ*QSTR*2)
#define OFF_QLO (OFF_QHI + SZ_Q)
#define OFF_KHI (OFF_QLO + SZ_Q)
#define SZ_K    (BT*KSTR*2)
#define OFF_VHI (OFF_KHI + SZ_K)
#define SZ_V    (HDIM*VSTR*2)
#define ATTN_SMEM (OFF_VHI + SZ_V)     // 105472

__global__ void __launch_bounds__(256, 2) attn_hmma(__half* __restrict__ Aout) {
    extern __shared__ char smem[];
    const uint32_t sb = smem_u32(smem);

    const int tid  = threadIdx.x;
    const int lane = tid & 31;
    const int w    = tid >> 5;
    const int bh = blockIdx.y;

    const int l16 = lane & 15;
    const int g   = lane >> 2;
    const int c2  = (lane & 3) * 2;

    __half* s_qhi = (__half*)(smem + OFF_QHI);
    __half* s_qlo = (__half*)(smem + OFF_QLO);

    const __half* Kh = gk_hi + (size_t)bh*SEQ*HDIM;
    const __half* Vh = gvt_hi + (size_t)bh*HDIM*SEQ;

    auto prefetch_k = [&](int k0) {
#pragma unroll
        for (int it = 0; it < 4; it++) {
            int t = tid + it*256;
            int row = t >> 4, cc = t & 15;
            cpasync16(sb + OFF_KHI + (row*KSTR + cc*8)*2,
                      Kh + (size_t)(k0 + row)*HDIM + cc*8);
        }
    };
    auto prefetch_v = [&](int k0) {
#pragma unroll
        for (int it = 0; it < 4; it++) {
            int t = tid + it*256;
            int d = t >> 3, cc = t & 7;
            cpasync16(sb + OFF_VHI + (d*VSTR + cc*8)*2,
                      Vh + (size_t)d*SEQ + k0 + cc*8);
        }
    };

    const uint32_t qhi_b = sb + OFF_QHI + (((w*16 + l16)*QSTR) + (lane>>4)*8)*2;
    const uint32_t qlo_b = sb + OFF_QLO + (((w*16 + l16)*QSTR) + (lane>>4)*8)*2;
    const uint32_t khi4  = sb + OFF_KHI + bpair_off(lane, KSTR);
    const uint32_t vhi4  = sb + OFF_VHI + bpair_off(lane, VSTR);

    const float rnorm = 0.088388347648318447f;
    const int b_idx = bh / NHEADS;
    const int h_idx = bh % NHEADS;

#pragma unroll 1
    for (int pass = 0; pass < 2; pass++) {
        const int qt = pass == 0 ? (NQT - 1 - blockIdx.x) : blockIdx.x;
        const int q0 = qt * BQ;
        const int rbase = q0 + w*16 + g;

        __syncthreads();     // prior pass's Q/K/V reads fully retired

        prefetch_k(0); CP_COMMIT();
        prefetch_v(0); CP_COMMIT();

        // Q tile (hi & lo)
        {
            const __half* qh = gq_hi + ((size_t)bh*SEQ + q0) * HDIM;
            const __half* ql = gq_lo + ((size_t)bh*SEQ + q0) * HDIM;
#pragma unroll
            for (int it = 0; it < 8; it++) {
                int t = tid + it*256;
                int row = t >> 4, cc = t & 15;
                *(uint4*)(s_qhi + row*QSTR + cc*8) = *(const uint4*)(qh + row*HDIM + cc*8);
            }
#pragma unroll
            for (int it = 0; it < 8; it++) {
                int t = tid + it*256;
                int row = t >> 4, cc = t & 15;
                *(uint4*)(s_qlo + row*QSTR + cc*8) = *(const uint4*)(ql + row*HDIM + cc*8);
            }
        }

        float m0 = -1e30f, m1 = -1e30f, l0 = 0.0f, l1 = 0.0f;
        float acc[16][4];
#pragma unroll
        for (int nt = 0; nt < 16; nt++)
#pragma unroll
            for (int e = 0; e < 4; e++) acc[nt][e] = 0.0f;

        const int ntiles = 2*qt + 2;
        for (int kt = 0; kt < ntiles; kt++) {
            const int k0 = kt * BT;

            CP_WAIT(1);          // K(kt) resident
            __syncthreads();     // K (and Q) visible

            // ---- S = q_hi*k_hi + q_lo*k_hi (paired-K ldsm4) ----
            float sacc[8][4];
#pragma unroll
            for (int nt = 0; nt < 8; nt++)
#pragma unroll
                for (int e = 0; e < 4; e++) sacc[nt][e] = 0.0f;

#pragma unroll
            for (int k16 = 0; k16 < HDIM; k16 += 16) {
                uint32_t bhi[8][2];
#pragma unroll
                for (int p = 0; p < 4; p++) {
                    uint32_t r4[4];
                    ldsm4(r4, khi4 + (p*16*KSTR + k16)*2);
                    bhi[2*p + 0][0] = r4[0]; bhi[2*p + 0][1] = r4[1];
                    bhi[2*p + 1][0] = r4[2]; bhi[2*p + 1][1] = r4[3];
                }
                uint32_t ahi[4], alo[4];
                ldsm4(ahi, qhi_b + k16*2);
                ldsm4(alo, qlo_b + k16*2);
#pragma unroll
                for (int nt = 0; nt < 8; nt++) {
                    mma16816h(sacc[nt], ahi, bhi[nt]);
                    mma16816h(sacc[nt], alo, bhi[nt]);
                }
            }
            __syncthreads();     // K(kt) reads retired

            if (kt + 1 < ntiles) prefetch_k(k0 + BT);
            CP_COMMIT();

            // ---- mask + scale + register softmax ----
#pragma unroll
            for (int nt = 0; nt < 8; nt++) {
#pragma unroll
                for (int e = 0; e < 4; e++) {
                    int r = rbase + (e >> 1)*8;
                    int c = k0 + nt*8 + c2 + (e & 1);
                    float v = sacc[nt][e] * rnorm;
                    if (c > r) v = -10000.0f;
                    sacc[nt][e] = v;
                }
            }
            float mx0 = -1e30f, mx1 = -1e30f;
#pragma unroll
            for (int nt = 0; nt < 8; nt++) {
                mx0 = fmaxf(mx0, fmaxf(sacc[nt][0], sacc[nt][1]));
                mx1 = fmaxf(mx1, fmaxf(sacc[nt][2], sacc[nt][3]));
            }
            mx0 = fmaxf(mx0, __shfl_xor_sync(0xFFFFFFFFu, mx0, 1));
            mx0 = fmaxf(mx0, __shfl_xor_sync(0xFFFFFFFFu, mx0, 2));
            mx1 = fmaxf(mx1, __shfl_xor_sync(0xFFFFFFFFu, mx1, 1));
            mx1 = fmaxf(mx1, __shfl_xor_sync(0xFFFFFFFFu, mx1, 2));
            float mn0 = fmaxf(m0, mx0), mn1 = fmaxf(m1, mx1);
            float scl0 = __expf(m0 - mn0), scl1 = __expf(m1 - mn1);
            m0 = mn0; m1 = mn1;
            float sum0 = 0.0f, sum1 = 0.0f;
#pragma unroll
            for (int nt = 0; nt < 8; nt++) {
                float p0 = __expf(sacc[nt][0] - m0);
                float p1 = __expf(sacc[nt][1] - m0);
                float p2 = __expf(sacc[nt][2] - m1);
                float p3 = __expf(sacc[nt][3] - m1);
                sacc[nt][0] = p0; sacc[nt][1] = p1;
                sacc[nt][2] = p2; sacc[nt][3] = p3;
                sum0 += p0 + p1; sum1 += p2 + p3;
            }
            l0 = l0 * scl0 + sum0;
            l1 = l1 * scl1 + sum1;
#pragma unroll
            for (int nt = 0; nt < 16; nt++) {
                acc[nt][0] *= scl0; acc[nt][1] *= scl0;
                acc[nt][2] *= scl1; acc[nt][3] *= scl1;
            }

            CP_WAIT(1);          // V(kt) resident
            __syncthreads();     // V visible

            // ---- O += p_hi*v_hi + p_lo*v_hi (paired-V ldsm4) ----
#pragma unroll
            for (int s = 0; s < 4; s++) {
                uint32_t aph[4], apl[4];
                split_pack(sacc[2*s][0],   sacc[2*s][1],   aph[0], apl[0]);
                split_pack(sacc[2*s][2],   sacc[2*s][3],   aph[1], apl[1]);
                split_pack(sacc[2*s+1][0], sacc[2*s+1][1], aph[2], apl[2]);
                split_pack(sacc[2*s+1][2], sacc[2*s+1][3], aph[3], apl[3]);
#pragma unroll
                for (int p = 0; p < 8; p++) {
                    uint32_t r4[4];
                    ldsm4(r4, vhi4 + (p*16*VSTR + s*16)*2);
                    uint32_t bv0[2] = {r4[0], r4[1]};
                    uint32_t bv1[2] = {r4[2], r4[3]};
                    mma16816h(acc[2*p + 0], aph, bv0);
                    mma16816h(acc[2*p + 0], apl, bv0);
                    mma16816h(acc[2*p + 1], aph, bv1);
                    mma16816h(acc[2*p + 1], apl, bv1);
                }
            }
            __syncthreads();     // V(kt) reads retired

            if (kt + 1 < ntiles) prefetch_v(k0 + BT);
            CP_COMMIT();
        }

        // ---- finalize: quad-reduce l, divide, write fp16 split-2 dense A' ----
        l0 += __shfl_xor_sync(0xFFFFFFFFu, l0, 1);
        l0 += __shfl_xor_sync(0xFFFFFFFFu, l0, 2);
        l1 += __shfl_xor_sync(0xFFFFFFFFu, l1, 1);
        l1 += __shfl_xor_sync(0xFFFFFFFFu, l1, 2);
        const float linv0 = 1.0f / l0, linv1 = 1.0f / l1;
#pragma unroll
        for (int i = 0; i < 2; i++) {
            int r = rbase + i*8;
            float linv = i ? linv1 : linv0;
            size_t tok = (size_t)(r*BATCH + b_idx);
            __half* dst = Aout + tok*K2 + h_idx*HDIM;
#pragma unroll
            for (int nt = 0; nt < 16; nt++) {
#pragma unroll
                for (int j = 0; j < 2; j++) {
                    float v = acc[nt][i*2 + j] * linv;
                    __half h = __float2half(v);
                    __half l = __float2half(v - __half2float(h));
                    int cc = nt*8 + c2 + j;
                    dst[cc]       = h;
                    dst[HID + cc] = l;
                }
            }
        }
    }
}

// ---------------- tail bias ---------------------------------------------------
__global__ void tail_copy(const float* __restrict__ src, float* __restrict__ dst, int n) {
    int i = blockIdx.x * blockDim.x + threadIdx.x;
    if (i < n) dst[i] = src[i];
}

// ---------------- launch -------------------------------------------------------
extern "C" void kernel_launch(void* const* d_in, const int* in_sizes, int n_in,
                              void* d_out, int out_size)
{
    const float* hidden  = (const float*)d_in[0];
    const float* w_qkv   = (const float*)d_in[2];
    const float* b_qkv   = (const float*)d_in[3];
    const float* w_dense = (const float*)d_in[4];
    const float* b_dense = (const float*)d_in[5];
    float* out = (float*)d_out;

    void *pA, *pBq, *pBd, *pQ, *pK, *pV;
    cudaGetSymbolAddress(&pA,   g_Abuf);
    cudaGetSymbolAddress(&pBq,  g_Bq);
    cudaGetSymbolAddress(&pBd,  g_Bd);
    cudaGetSymbolAddress(&pQ,   g_q);
    cudaGetSymbolAddress(&pK,   g_k);
    cudaGetSymbolAddress(&pV,   g_v);

    cudaFuncSetAttribute(hmma_gemm<1>, cudaFuncAttributeMaxDynamicSharedMemorySize, GEMM_SMEM);
    cudaFuncSetAttribute(hmma_gemm<2>, cudaFuncAttributeMaxDynamicSharedMemorySize, GEMM_SMEM);
    cudaFuncSetAttribute(attn_hmma, cudaFuncAttributeMaxDynamicSharedMemorySize, ATTN_SMEM);

    // 1) convert A (hidden -> [hi|lo]) and B (w_qkv -> hi)
    conv_split_a<<<(TOK*HID/4 + 255)/256, 256>>>(hidden, (__half*)pA, TOK, HID);
    conv_hi<<<(QKV_N*HID/4 + 255)/256, 256>>>(w_qkv, (__half*)pBq, QKV_N*HID/4);

    // 2) QKV projection (fp16 HMMA B-dedup, bias + scatter epilogue)
    hmma_gemm<1><<<dim3(QKV_N/128, TOK/128), 256, GEMM_SMEM>>>(
        (const __half*)pA, (const __half*)pBq, b_qkv, nullptr,
        (float*)pQ, (float*)pK, (float*)pV, QKV_N);

    // 3) RoPE (Q hi/lo, K hi) + V transpose (hi)
    rope_table_kernel<<<(SEQ*64 + 255)/256, 256>>>();
    rope_apply_kernel<<<(NBH*SEQ*64 + 255)/256, 256>>>();
    v_transpose_split<<<dim3(SEQ/32, HDIM/32, NBH), dim3(32, 8)>>>();

    // 4) causal attention (paired q-tiles: 256 CTAs, one balanced wave)
    attn_hmma<<<dim3(NQT/2, NBH), 256, ATTN_SMEM>>>((__half*)pA);

    // 5) w_dense -> hi, dense GEMM (fp16 HMMA B-dedup)
    conv_hi<<<(HID*HID/4 + 255)/256, 256>>>(w_dense, (__half*)pBd, HID*HID/4);
    hmma_gemm<2><<<dim3(HID/128, TOK/128), 256, GEMM_SMEM>>>(
        (const __half*)pA, (const __half*)pBd, nullptr, out,
        nullptr, nullptr, nullptr, HID);

    // 6) bias tail if harness flattens the (output, bias) tuple
    int extra = out_size - TOK*HID;
    if (extra > 0)
        tail_copy<<<(extra + 255)/256, 256>>>(b_dense, out + (size_t)TOK*HID, extra);
    (void)in_sizes; (void)n_in;
}

// round 15
// speedup vs baseline: 7.4993x; 1.5792x over previous
#include <cuda_runtime.h>
#include <cuda_bf16.h>
#include <cuda_fp16.h>
#include <math.h>
#include <stdint.h>

#define SEQ     2048
#define BATCH   2
#define HID     2048
#define NHEADS  16
#define HDIM    128
#define TOK     (SEQ*BATCH)     // 4096
#define QKV_N   (3*HID)         // 6144
#define NBH     (BATCH*NHEADS)  // 32

// ---------------- scratch (device globals; no runtime allocs allowed) -------
__device__ float g_q[NBH*SEQ*HDIM];
__device__ float g_k[NBH*SEQ*HDIM];
__device__ float g_v[NBH*SEQ*HDIM];
__device__ float g_cos[SEQ*64];
__device__ float g_sin[SEQ*64];
// GEMM operands: pure fp16, stride HID
__device__ __align__(1024) __half g_Abuf[TOK*HID];
__device__ __align__(1024) __half g_Bq[QKV_N*HID];
__device__ __align__(1024) __half g_Bd[HID*HID];
// attention operands: pure fp16
__device__ __align__(16) __half gq_hi[NBH*SEQ*HDIM];
__device__ __align__(16) __half gk_hi[NBH*SEQ*HDIM];
__device__ __align__(16) __half gvt_hi[NBH*HDIM*SEQ];   // [bh][d][s]

// ============================================================================
// PTX helpers (base-target-safe)
// ============================================================================
__device__ __forceinline__ uint32_t smem_u32(const void* p) {
    uint32_t a;
    asm("{ .reg .u64 t; cvta.to.shared.u64 t, %1; cvt.u32.u64 %0, t; }"
        : "=r"(a) : "l"(p));
    return a;
}
__device__ __forceinline__ void cpasync16(uint32_t s, const void* g) {
    asm volatile("cp.async.cg.shared.global [%0], [%1], 16;" :: "r"(s), "l"(g));
}
#define CP_COMMIT() asm volatile("cp.async.commit_group;" ::: "memory")
#define CP_WAIT(n)  asm volatile("cp.async.wait_group %0;" :: "n"(n) : "memory")

__device__ __forceinline__ void ldsm4(uint32_t* r, uint32_t a) {
    asm volatile("ldmatrix.sync.aligned.m8n8.x4.shared.b16 {%0,%1,%2,%3}, [%4];"
        : "=r"(r[0]), "=r"(r[1]), "=r"(r[2]), "=r"(r[3]) : "r"(a));
}
__device__ __forceinline__ void mma16816h(float* c, const uint32_t* a, const uint32_t* b) {
    asm volatile("mma.sync.aligned.m16n8k16.row.col.f32.f16.f16.f32 "
        "{%0,%1,%2,%3}, {%4,%5,%6,%7}, {%8,%9}, {%0,%1,%2,%3};"
        : "+f"(c[0]), "+f"(c[1]), "+f"(c[2]), "+f"(c[3])
        : "r"(a[0]), "r"(a[1]), "r"(a[2]), "r"(a[3]), "r"(b[0]), "r"(b[1]));
}
// pack two floats into one fp16x2 register
__device__ __forceinline__ uint32_t pack2h(float a, float b) {
    __half ha = __float2half(a), hb = __float2half(b);
    return (uint32_t)__half_as_ushort(ha) | ((uint32_t)__half_as_ushort(hb) << 16);
}
// per-lane address shaping for paired-B ldsm4: two n-groups x one k16
__device__ __forceinline__ uint32_t bpair_off(int lane, int stride_h) {
    int row = (lane & 7) + ((lane >> 4) << 3);
    int kof = ((lane >> 3) & 1) * 8;
    return (uint32_t)((row * stride_h + kof) * 2);
}

// ============================================================================
// HMMA fp16 GEMM: C[M,N] = A[M,K] * B[N,K]^T, K=2048, pure fp16, fp32 accum.
// CTA tile 128x128x32, 256 thr, warps 4(m) x 2(n), warp tile 32x64.
// 3-stage ring of [A|B] tiles, one barrier per K-step, paired-B ldsm4.
// MODE 1: QKV — add bias + scatter to q/k/v.   MODE 2: plain C store.
// ============================================================================
#define BK 32
#define ASTR 40
#define TILE_B16 (128*ASTR)            // 5120 halfs per tile
#define STAGE_B16 (2*TILE_B16)         // A + B
#define STAGE_BYTES (STAGE_B16*2)      // 20480
#define GSTAGES 3
#define GEMM_SMEM (GSTAGES*STAGE_BYTES)  // 61440

template<int MODE>
__global__ void __launch_bounds__(256, 2)
hmma_gemm(const __half* __restrict__ Ag, const __half* __restrict__ Bg,
          const float* __restrict__ bias, float* __restrict__ C,
          float* __restrict__ q_out, float* __restrict__ k_out, float* __restrict__ v_out,
          int N)
{
    extern __shared__ __align__(16) __half smbuf[];

    const int tid  = threadIdx.x;
    const int lane = tid & 31;
    const int warp = tid >> 5;
    const int wm = warp >> 1;
    const int wn = warp & 1;
    const int m0 = blockIdx.y * 128;
    const int n0 = blockIdx.x * 128;

    const uint32_t smb = smem_u32(smbuf);
    const int cr  = tid >> 2;
    const int ccn = tid & 3;
    const int KT  = HID / BK;          // 64

    auto prefetch = [&](int kt, int slot) {
        uint32_t base = smb + slot * STAGE_BYTES;
#pragma unroll
        for (int h = 0; h < 2; h++) {
            int r = cr + h * 64;
            uint32_t so = (r * ASTR + ccn * 8) * 2;
            cpasync16(base + so,
                      Ag + (size_t)(m0 + r) * HID + kt * BK + ccn * 8);
            cpasync16(base + TILE_B16*2 + so,
                      Bg + (size_t)(n0 + r) * HID + kt * BK + ccn * 8);
        }
    };

    float acc[2][8][4];
#pragma unroll
    for (int i = 0; i < 2; i++)
#pragma unroll
        for (int j = 0; j < 8; j++)
#pragma unroll
            for (int e = 0; e < 4; e++) acc[i][j][e] = 0.0f;

    const int l16 = lane & 15;
    const uint32_t a_off = (((wm * 32 + l16) * ASTR) + ((lane >> 4) * 8)) * 2;
    const uint32_t b_off = (uint32_t)(wn * 64 * ASTR * 2) + bpair_off(lane, ASTR);

    prefetch(0, 0); CP_COMMIT();
    prefetch(1, 1); CP_COMMIT();

    int slot = 0, pslot = 2;
    for (int kt = 0; kt < KT; kt++) {
        CP_WAIT(1);
        __syncthreads();
        int pf = kt + 2;
        if (pf < KT) prefetch(pf, pslot);
        CP_COMMIT();

        uint32_t ab = smb + slot * STAGE_BYTES + a_off;
        uint32_t bb = smb + slot * STAGE_BYTES + TILE_B16*2 + b_off;

#pragma unroll
        for (int k16 = 0; k16 < BK; k16 += 16) {
            uint32_t bfr[8][2];
#pragma unroll
            for (int p = 0; p < 4; p++) {
                uint32_t r4[4];
                ldsm4(r4, bb + (p * 16 * ASTR + k16) * 2);
                bfr[2*p + 0][0] = r4[0]; bfr[2*p + 0][1] = r4[1];
                bfr[2*p + 1][0] = r4[2]; bfr[2*p + 1][1] = r4[3];
            }
#pragma unroll
            for (int mt = 0; mt < 2; mt++) {
                uint32_t afr[4];
                ldsm4(afr, ab + (mt * 16 * ASTR + k16) * 2);
#pragma unroll
                for (int nt = 0; nt < 8; nt++)
                    mma16816h(acc[mt][nt], afr, bfr[nt]);
            }
        }
        if (++slot == 3) slot = 0;
        if (++pslot == 3) pslot = 0;
    }

    const int g  = lane >> 2;
    const int c2 = (lane & 3) * 2;
#pragma unroll
    for (int mt = 0; mt < 2; mt++) {
#pragma unroll
        for (int nt = 0; nt < 8; nt++) {
#pragma unroll
            for (int i = 0; i < 2; i++) {
#pragma unroll
                for (int j = 0; j < 2; j++) {
                    int m = m0 + wm * 32 + mt * 16 + g + i * 8;
                    int n = n0 + wn * 64 + nt * 8 + c2 + j;
                    float v = acc[mt][nt][i * 2 + j];
                    if (MODE == 1) {
                        v += bias[n];
                        int head = n / (3 * HDIM);
                        int r3   = n % (3 * HDIM);
                        int part = r3 / HDIM;
                        int d    = r3 % HDIM;
                        int off  = (((m & 1) * NHEADS + head) * SEQ + (m >> 1)) * HDIM + d;
                        if      (part == 0) q_out[off] = v;
                        else if (part == 1) k_out[off] = v;
                        else                v_out[off] = v;
                    } else {
                        C[(size_t)m * N + n] = v;
                    }
                }
            }
        }
    }
}

// ---------------- conversion: flat fp32 -> fp16 -------------------------------
__global__ void conv_hi(const float* __restrict__ src,
                        __half* __restrict__ dst, int n4)
{
    int idx = blockIdx.x * blockDim.x + threadIdx.x;
    if (idx >= n4) return;
    float4 x = ((const float4*)src)[idx];
    __half h[4];
    h[0] = __float2half(x.x); h[1] = __float2half(x.y);
    h[2] = __float2half(x.z); h[3] = __float2half(x.w);
    *(uint2*)(dst + (size_t)idx * 4) = *(uint2*)h;
}

// ---------------- RoPE tables + apply ----------------------------------------
__global__ void rope_table_kernel() {
    __shared__ float invf[64];
    if (threadIdx.x < 64)
        invf[threadIdx.x] = (float)pow(10000.0, -((double)threadIdx.x) / 64.0);
    __syncthreads();
    int idx = blockIdx.x * blockDim.x + threadIdx.x;
    if (idx >= SEQ * 64) return;
    int s = idx >> 6;
    int i = idx & 63;
    float theta = (float)s * invf[i];
    g_cos[idx] = cosf(theta);
    g_sin[idx] = sinf(theta);
}

__global__ void rope_apply_kernel() {
    int idx = blockIdx.x * blockDim.x + threadIdx.x;
    int total = NBH*SEQ*64;
    if (idx >= total) return;
    int i = idx & 63;
    int rowid = idx >> 6;
    int s = rowid & (SEQ - 1);
    float c  = g_cos[s*64 + i];
    float sn = g_sin[s*64 + i];
    int base = rowid * HDIM;
    float q1 = g_q[base + i], q2 = g_q[base + 64 + i];
    float k1 = g_k[base + i], k2 = g_k[base + 64 + i];
    gq_hi[base + i]      = __float2half(q1*c - q2*sn);
    gq_hi[base + 64 + i] = __float2half(q2*c + q1*sn);
    gk_hi[base + i]      = __float2half(k1*c - k2*sn);
    gk_hi[base + 64 + i] = __float2half(k2*c + k1*sn);
}

// ---------------- V transpose: g_v[bh][s][d] -> gvt_hi[bh][d][s] -------------
__global__ void v_transpose_split() {
    __shared__ float t[32][33];
    int bh = blockIdx.z;
    int s0 = blockIdx.x * 32, d0 = blockIdx.y * 32;
    int tx = threadIdx.x, ty = threadIdx.y;
#pragma unroll
    for (int i = 0; i < 32; i += 8)
        t[ty + i][tx] = g_v[((size_t)bh*SEQ + s0 + ty + i) * HDIM + d0 + tx];
    __syncthreads();
#pragma unroll
    for (int i = 0; i < 32; i += 8) {
        float x = t[tx][ty + i];
        size_t off = ((size_t)bh*HDIM + d0 + ty + i) * SEQ + s0 + tx;
        gvt_hi[off] = __float2half(x);
    }
}

// ============================================================================
// FA2-style HMMA causal flash attention, pure fp16, paired ldsm4, balanced
// wave pairing (each CTA: heavy qt then light qt; 256 CTAs = one wave).
// ============================================================================
#define BQ 128
#define BT 64
#define NQT (SEQ/BQ)          // 16
#define QSTR 136
#define KSTR 136
#define VSTR 72

#define OFF_QHI 0
#define SZ_Q    (BQ*QSTR*2)
#define OFF_KHI (OFF_QHI + SZ_Q)
#define SZ_K    (BT*KSTR*2)
#define OFF_VHI (OFF_KHI + SZ_K)
#define SZ_V    (HDIM*VSTR*2)
#define ATTN_SMEM (OFF_VHI + SZ_V)     // 70656

__global__ void __launch_bounds__(256, 2) attn_hmma(__half* __restrict__ Aout) {
    extern __shared__ char smem[];
    const uint32_t sb = smem_u32(smem);

    const int tid  = threadIdx.x;
    const int lane = tid & 31;
    const int w    = tid >> 5;
    const int bh = blockIdx.y;

    const int l16 = lane & 15;
    const int g   = lane >> 2;
    const int c2  = (lane & 3) * 2;

    __half* s_qhi = (__half*)(smem + OFF_QHI);

    const __half* Kh = gk_hi + (size_t)bh*SEQ*HDIM;
    const __half* Vh = gvt_hi + (size_t)bh*HDIM*SEQ;

    auto prefetch_k = [&](int k0) {
#pragma unroll
        for (int it = 0; it < 4; it++) {
            int t = tid + it*256;
            int row = t >> 4, cc = t & 15;
            cpasync16(sb + OFF_KHI + (row*KSTR + cc*8)*2,
                      Kh + (size_t)(k0 + row)*HDIM + cc*8);
        }
    };
    auto prefetch_v = [&](int k0) {
#pragma unroll
        for (int it = 0; it < 4; it++) {
            int t = tid + it*256;
            int d = t >> 3, cc = t & 7;
            cpasync16(sb + OFF_VHI + (d*VSTR + cc*8)*2,
                      Vh + (size_t)d*SEQ + k0 + cc*8);
        }
    };

    const uint32_t qhi_b = sb + OFF_QHI + (((w*16 + l16)*QSTR) + (lane>>4)*8)*2;
    const uint32_t khi4  = sb + OFF_KHI + bpair_off(lane, KSTR);
    const uint32_t vhi4  = sb + OFF_VHI + bpair_off(lane, VSTR);

    const float rnorm = 0.088388347648318447f;
    const int b_idx = bh / NHEADS;
    const int h_idx = bh % NHEADS;

#pragma unroll 1
    for (int pass = 0; pass < 2; pass++) {
        const int qt = pass == 0 ? (NQT - 1 - blockIdx.x) : blockIdx.x;
        const int q0 = qt * BQ;
        const int rbase = q0 + w*16 + g;

        __syncthreads();     // prior pass's Q/K/V reads fully retired

        prefetch_k(0); CP_COMMIT();
        prefetch_v(0); CP_COMMIT();

        // Q tile
        {
            const __half* qh = gq_hi + ((size_t)bh*SEQ + q0) * HDIM;
#pragma unroll
            for (int it = 0; it < 8; it++) {
                int t = tid + it*256;
                int row = t >> 4, cc = t & 15;
                *(uint4*)(s_qhi + row*QSTR + cc*8) = *(const uint4*)(qh + row*HDIM + cc*8);
            }
        }

        float m0 = -1e30f, m1 = -1e30f, l0 = 0.0f, l1 = 0.0f;
        float acc[16][4];
#pragma unroll
        for (int nt = 0; nt < 16; nt++)
#pragma unroll
            for (int e = 0; e < 4; e++) acc[nt][e] = 0.0f;

        const int ntiles = 2*qt + 2;
        for (int kt = 0; kt < ntiles; kt++) {
            const int k0 = kt * BT;

            CP_WAIT(1);          // K(kt) resident
            __syncthreads();     // K (and Q) visible

            // ---- S = q*k (paired-K ldsm4) ----
            float sacc[8][4];
#pragma unroll
            for (int nt = 0; nt < 8; nt++)
#pragma unroll
                for (int e = 0; e < 4; e++) sacc[nt][e] = 0.0f;

#pragma unroll
            for (int k16 = 0; k16 < HDIM; k16 += 16) {
                uint32_t bhi[8][2];
#pragma unroll
                for (int p = 0; p < 4; p++) {
                    uint32_t r4[4];
                    ldsm4(r4, khi4 + (p*16*KSTR + k16)*2);
                    bhi[2*p + 0][0] = r4[0]; bhi[2*p + 0][1] = r4[1];
                    bhi[2*p + 1][0] = r4[2]; bhi[2*p + 1][1] = r4[3];
                }
                uint32_t ahi[4];
                ldsm4(ahi, qhi_b + k16*2);
#pragma unroll
                for (int nt = 0; nt < 8; nt++)
                    mma16816h(sacc[nt], ahi, bhi[nt]);
            }
            __syncthreads();     // K(kt) reads retired

            if (kt + 1 < ntiles) prefetch_k(k0 + BT);
            CP_COMMIT();

            // ---- mask + scale + register softmax ----
#pragma unroll
            for (int nt = 0; nt < 8; nt++) {
#pragma unroll
                for (int e = 0; e < 4; e++) {
                    int r = rbase + (e >> 1)*8;
                    int c = k0 + nt*8 + c2 + (e & 1);
                    float v = sacc[nt][e] * rnorm;
                    if (c > r) v = -10000.0f;
                    sacc[nt][e] = v;
                }
            }
            float mx0 = -1e30f, mx1 = -1e30f;
#pragma unroll
            for (int nt = 0; nt < 8; nt++) {
                mx0 = fmaxf(mx0, fmaxf(sacc[nt][0], sacc[nt][1]));
                mx1 = fmaxf(mx1, fmaxf(sacc[nt][2], sacc[nt][3]));
            }
            mx0 = fmaxf(mx0, __shfl_xor_sync(0xFFFFFFFFu, mx0, 1));
            mx0 = fmaxf(mx0, __shfl_xor_sync(0xFFFFFFFFu, mx0, 2));
            mx1 = fmaxf(mx1, __shfl_xor_sync(0xFFFFFFFFu, mx1, 1));
            mx1 = fmaxf(mx1, __shfl_xor_sync(0xFFFFFFFFu, mx1, 2));
            float mn0 = fmaxf(m0, mx0), mn1 = fmaxf(m1, mx1);
            float scl0 = __expf(m0 - mn0), scl1 = __expf(m1 - mn1);
            m0 = mn0; m1 = mn1;
            float sum0 = 0.0f, sum1 = 0.0f;
#pragma unroll
            for (int nt = 0; nt < 8; nt++) {
                float p0 = __expf(sacc[nt][0] - m0);
                float p1 = __expf(sacc[nt][1] - m0);
                float p2 = __expf(sacc[nt][2] - m1);
                float p3 = __expf(sacc[nt][3] - m1);
                sacc[nt][0] = p0; sacc[nt][1] = p1;
                sacc[nt][2] = p2; sacc[nt][3] = p3;
                sum0 += p0 + p1; sum1 += p2 + p3;
            }
            l0 = l0 * scl0 + sum0;
            l1 = l1 * scl1 + sum1;
#pragma unroll
            for (int nt = 0; nt < 16; nt++) {
                acc[nt][0] *= scl0; acc[nt][1] *= scl0;
                acc[nt][2] *= scl1; acc[nt][3] *= scl1;
            }

            CP_WAIT(1);          // V(kt) resident
            __syncthreads();     // V visible

            // ---- O += p*v (paired-V ldsm4, P packed from registers) ----
#pragma unroll
            for (int s = 0; s < 4; s++) {
                uint32_t aph[4];
                aph[0] = pack2h(sacc[2*s][0],   sacc[2*s][1]);
                aph[1] = pack2h(sacc[2*s][2],   sacc[2*s][3]);
                aph[2] = pack2h(sacc[2*s+1][0], sacc[2*s+1][1]);
                aph[3] = pack2h(sacc[2*s+1][2], sacc[2*s+1][3]);
#pragma unroll
                for (int p = 0; p < 8; p++) {
                    uint32_t r4[4];
                    ldsm4(r4, vhi4 + (p*16*VSTR + s*16)*2);
                    uint32_t bv0[2] = {r4[0], r4[1]};
                    uint32_t bv1[2] = {r4[2], r4[3]};
                    mma16816h(acc[2*p + 0], aph, bv0);
                    mma16816h(acc[2*p + 1], aph, bv1);
                }
            }
            __syncthreads();     // V(kt) reads retired

            if (kt + 1 < ntiles) prefetch_v(k0 + BT);
            CP_COMMIT();
        }

        // ---- finalize: quad-reduce l, divide, write fp16 dense A ----
        l0 += __shfl_xor_sync(0xFFFFFFFFu, l0, 1);
        l0 += __shfl_xor_sync(0xFFFFFFFFu, l0, 2);
        l1 += __shfl_xor_sync(0xFFFFFFFFu, l1, 1);
        l1 += __shfl_xor_sync(0xFFFFFFFFu, l1, 2);
        const float linv0 = 1.0f / l0, linv1 = 1.0f / l1;
#pragma unroll
        for (int i = 0; i < 2; i++) {
            int r = rbase + i*8;
            float linv = i ? linv1 : linv0;
            size_t tok = (size_t)(r*BATCH + b_idx);
            __half* dst = Aout + tok*HID + h_idx*HDIM;
#pragma unroll
            for (int nt = 0; nt < 16; nt++) {
#pragma unroll
                for (int j = 0; j < 2; j++) {
                    float v = acc[nt][i*2 + j] * linv;
                    dst[nt*8 + c2 + j] = __float2half(v);
                }
            }
        }
    }
}

// ---------------- tail bias ---------------------------------------------------
__global__ void tail_copy(const float* __restrict__ src, float* __restrict__ dst, int n) {
    int i = blockIdx.x * blockDim.x + threadIdx.x;
    if (i < n) dst[i] = src[i];
}

// ---------------- launch -------------------------------------------------------
extern "C" void kernel_launch(void* const* d_in, const int* in_sizes, int n_in,
                              void* d_out, int out_size)
{
    const float* hidden  = (const float*)d_in[0];
    const float* w_qkv   = (const float*)d_in[2];
    const float* b_qkv   = (const float*)d_in[3];
    const float* w_dense = (const float*)d_in[4];
    const float* b_dense = (const float*)d_in[5];
    float* out = (float*)d_out;

    void *pA, *pBq, *pBd, *pQ, *pK, *pV;
    cudaGetSymbolAddress(&pA,   g_Abuf);
    cudaGetSymbolAddress(&pBq,  g_Bq);
    cudaGetSymbolAddress(&pBd,  g_Bd);
    cudaGetSymbolAddress(&pQ,   g_q);
    cudaGetSymbolAddress(&pK,   g_k);
    cudaGetSymbolAddress(&pV,   g_v);

    cudaFuncSetAttribute(hmma_gemm<1>, cudaFuncAttributeMaxDynamicSharedMemorySize, GEMM_SMEM);
    cudaFuncSetAttribute(hmma_gemm<2>, cudaFuncAttributeMaxDynamicSharedMemorySize, GEMM_SMEM);
    cudaFuncSetAttribute(attn_hmma, cudaFuncAttributeMaxDynamicSharedMemorySize, ATTN_SMEM);

    // 1) convert A (hidden) and B (w_qkv) to fp16
    conv_hi<<<(TOK*HID/4 + 255)/256, 256>>>(hidden, (__half*)pA, TOK*HID/4);
    conv_hi<<<(QKV_N*HID/4 + 255)/256, 256>>>(w_qkv, (__half*)pBq, QKV_N*HID/4);

    // 2) QKV projection (pure fp16 HMMA, bias + scatter epilogue)
    hmma_gemm<1><<<dim3(QKV_N/128, TOK/128), 256, GEMM_SMEM>>>(
        (const __half*)pA, (const __half*)pBq, b_qkv, nullptr,
        (float*)pQ, (float*)pK, (float*)pV, QKV_N);

    // 3) RoPE (Q,K fp16) + V transpose (fp16)
    rope_table_kernel<<<(SEQ*64 + 255)/256, 256>>>();
    rope_apply_kernel<<<(NBH*SEQ*64 + 255)/256, 256>>>();
    v_transpose_split<<<dim3(SEQ/32, HDIM/32, NBH), dim3(32, 8)>>>();

    // 4) causal attention (pure fp16, paired q-tiles: one balanced wave)
    attn_hmma<<<dim3(NQT/2, NBH), 256, ATTN_SMEM>>>((__half*)pA);

    // 5) w_dense -> fp16, dense GEMM (pure fp16 HMMA)
    conv_hi<<<(HID*HID/4 + 255)/256, 256>>>(w_dense, (__half*)pBd, HID*HID/4);
    hmma_gemm<2><<<dim3(HID/128, TOK/128), 256, GEMM_SMEM>>>(
        (const __half*)pA, (const __half*)pBd, nullptr, out,
        nullptr, nullptr, nullptr, HID);

    // 6) bias tail if harness flattens the (output, bias) tuple
    int extra = out_size - TOK*HID;
    if (extra > 0)
        tail_copy<<<(extra + 255)/256, 256>>>(b_dense, out + (size_t)TOK*HID, extra);
    (void)in_sizes; (void)n_in;
}